// round 13
// baseline (speedup 1.0000x reference)
#include <cuda_runtime.h>
#include <math.h>
#include <stdint.h>

#define D_  768
#define H_  12
#define HD_ 64
#define FF_ 3072
#define B_  8
#define N_  1024
#define M_  (B_*N_)          // 8192 rows
#define SCALING_ 0.125f      // HD^-0.5
#define EPS_ 1e-5f

#if defined(__CUDA_ARCH_FEAT_SM103_ALL) || defined(__CUDA_ARCH_FEAT_SM100_ALL) || \
    defined(__CUDA_ARCH_SPECIFIC__) || defined(__CUDA_ARCH_FAMILY_SPECIFIC__)
#define TC_OK 1
#else
#define TC_OK 0
#endif

// ---------------- scratch (static device globals; no allocation) -------------
__device__ float g_h  [M_*D_];
__device__ float g_q  [M_*D_];
__device__ float g_k  [M_*D_];
__device__ float g_v  [M_*D_];
__device__ float g_att[M_*D_];
__device__ float g_ff [M_*FF_];
#define CW_DD (D_*D_)
#define CW_FD (FF_*D_)
__device__ float g_cw [4*CW_DD + 2*CW_FD];

// ---------------- common helpers ---------------------------------------------
__device__ __forceinline__ unsigned f2tf32(float f) {
    unsigned r;
    asm("cvt.rna.tf32.f32 %0, %1;" : "=r"(r) : "f"(f));
    return r;
}
__device__ __forceinline__ float tf32r(float f) { return __uint_as_float(f2tf32(f)); }

#if TC_OK
__device__ __forceinline__ uint32_t smem_u32(const void* p) {
    uint32_t a;
    asm("{ .reg .u64 t; cvta.to.shared.u64 t, %1; cvt.u32.u64 %0, t; }" : "=r"(a) : "l"(p));
    return a;
}
__device__ __forceinline__ uint32_t elect_one() {
    uint32_t p;
    asm volatile("{ .reg .pred p; elect.sync _|p, 0xFFFFFFFF; selp.b32 %0, 1, 0, p; }" : "=r"(p));
    return p;
}
__device__ __forceinline__ void cp16(uint32_t smaddr, const void* g) {
    asm volatile("cp.async.cg.shared.global [%0], [%1], 16;" :: "r"(smaddr), "l"(g) : "memory");
}
#define CP_COMMIT() asm volatile("cp.async.commit_group;" ::: "memory")
#define TC_ALLOC(smem_addr, n) \
    asm volatile("tcgen05.alloc.cta_group::1.sync.aligned.shared::cta.b32 [%0], %1;" \
                 :: "r"(smem_addr), "r"((uint32_t)(n)) : "memory")
#define TC_RELINQ() \
    asm volatile("tcgen05.relinquish_alloc_permit.cta_group::1.sync.aligned;")
#define TC_DEALLOC(tmem, n) \
    asm volatile("tcgen05.dealloc.cta_group::1.sync.aligned.b32 %0, %1;" :: "r"(tmem), "r"((uint32_t)(n)))
#define TC_COMMIT(mbar) \
    asm volatile("tcgen05.commit.cta_group::1.mbarrier::arrive::one.shared::cluster.b64 [%0];" \
                 :: "r"(mbar) : "memory")
#define TC_FENCE_AFTER()  asm volatile("tcgen05.fence::after_thread_sync;" ::: "memory")
#define FENCE_ASYNC_SH()  asm volatile("fence.proxy.async.shared::cta;" ::: "memory")
#define MBAR_INIT(mbar, cnt) \
    asm volatile("mbarrier.init.shared.b64 [%0], %1;" :: "r"(mbar), "r"((uint32_t)(cnt)) : "memory")
#define MBAR_WAIT(mbar, ph) do {                                                  \
    asm volatile("{\n\t.reg .pred P1;\n\t"                                        \
        "WL_%=:\n\t"                                                              \
        "mbarrier.try_wait.parity.acquire.cta.shared::cta.b64 P1, [%0], %1, 0x989680;\n\t" \
        "@P1 bra.uni WD_%=;\n\t"                                                  \
        "bra.uni WL_%=;\n\t"                                                      \
        "WD_%=:\n\t}"                                                             \
        :: "r"(mbar), "r"((uint32_t)(ph)) : "memory");                            \
} while (0)
#define TC_LD_X32(r, tmem) \
    asm volatile( \
        "tcgen05.ld.sync.aligned.32x32b.x32.b32 " \
        "{%0, %1, %2, %3, %4, %5, %6, %7, " \
        " %8, %9, %10, %11, %12, %13, %14, %15, " \
        " %16, %17, %18, %19, %20, %21, %22, %23, " \
        " %24, %25, %26, %27, %28, %29, %30, %31}, [%32];" \
        : "=r"((r)[0]),  "=r"((r)[1]),  "=r"((r)[2]),  "=r"((r)[3]), \
          "=r"((r)[4]),  "=r"((r)[5]),  "=r"((r)[6]),  "=r"((r)[7]), \
          "=r"((r)[8]),  "=r"((r)[9]),  "=r"((r)[10]), "=r"((r)[11]), \
          "=r"((r)[12]), "=r"((r)[13]), "=r"((r)[14]), "=r"((r)[15]), \
          "=r"((r)[16]), "=r"((r)[17]), "=r"((r)[18]), "=r"((r)[19]), \
          "=r"((r)[20]), "=r"((r)[21]), "=r"((r)[22]), "=r"((r)[23]), \
          "=r"((r)[24]), "=r"((r)[25]), "=r"((r)[26]), "=r"((r)[27]), \
          "=r"((r)[28]), "=r"((r)[29]), "=r"((r)[30]), "=r"((r)[31]) \
        : "r"(tmem))
#define TC_WAIT_LD() asm volatile("tcgen05.wait::ld.sync.aligned;" ::: "memory")

__device__ __forceinline__ void tc_mma_tf32_ss(uint32_t d, uint64_t ad, uint64_t bd,
                                               uint32_t idesc, bool acc) {
    uint32_t e = acc ? 1u : 0u;
    asm volatile(
        "{\n\t.reg .pred p;\n\tsetp.ne.u32 p, %4, 0;\n\t"
        "tcgen05.mma.cta_group::1.kind::tf32 [%0], %1, %2, %3, {%5,%5,%5,%5}, p;\n\t}"
        :: "r"(d), "l"(ad), "l"(bd), "r"(idesc), "r"(e), "r"(0u) : "memory");
}
__device__ __forceinline__ uint64_t mk_desc(uint32_t addr) {
    const uint64_t base = (uint64_t(2) << 61) | (uint64_t(1) << 46)
                        | (uint64_t(64) << 32) | (uint64_t(1) << 16);
    return base | ((uint64_t)(addr >> 4) & 0x3FFF);
}
#define SWZ128(b) ((b) ^ (((b) >> 3) & 0x70))
#define TC_IDESC ((1u<<4)|(2u<<7)|(2u<<10)|(16u<<17)|(8u<<24))
#endif  // TC_OK

__device__ __forceinline__ void mma_tf32(float& c0, float& c1, float& c2, float& c3,
                                         unsigned a0, unsigned a1, unsigned a2, unsigned a3,
                                         unsigned b0, unsigned b1) {
    asm volatile(
        "mma.sync.aligned.m16n8k8.row.col.f32.tf32.tf32.f32 "
        "{%0,%1,%2,%3}, {%4,%5,%6,%7}, {%8,%9}, {%0,%1,%2,%3};"
        : "+f"(c0), "+f"(c1), "+f"(c2), "+f"(c3)
        : "r"(a0), "r"(a1), "r"(a2), "r"(a3), "r"(b0), "r"(b1));
}

// ---------------- one-shot tf32 rounding of all six weights (fused) ----------
__global__ __launch_bounds__(256)
void cvt_all_kernel(const float4* wq, const float4* wk, const float4* wv,
                    const float4* wo, const float4* w1, const float4* w2,
                    float4* dst) {
    const int DD4 = CW_DD/4, FD4 = CW_FD/4;
    const int total = 4*DD4 + 2*FD4;
    int i = blockIdx.x * blockDim.x + threadIdx.x;
    if (i >= total) return;
    const float4* src;
    int off;
    if (i < 4*DD4) {
        int w = i / DD4; off = i - w*DD4;
        src = (w == 0) ? wq : (w == 1) ? wk : (w == 2) ? wv : wo;
    } else {
        int j = i - 4*DD4;
        if (j < FD4) { src = w1; off = j; }
        else         { src = w2; off = j - FD4; }
    }
    float4 v = src[off];
    uint4 o;
    o.x = f2tf32(v.x); o.y = f2tf32(v.y); o.z = f2tf32(v.z); o.w = f2tf32(v.w);
    ((uint4*)dst)[i] = o;
}

// ---------------- LayerNorm (tf32-rounded output) ----------------------------
__global__ __launch_bounds__(256)
void ln_kernel(const float* __restrict__ x, const float* __restrict__ w,
               const float* __restrict__ b, float* __restrict__ out) {
    const int row = blockIdx.x;
    const int tid = threadIdx.x;
    const float* xr = x + (size_t)row * D_;
    float v[3];
    float s = 0.f;
    #pragma unroll
    for (int i = 0; i < 3; i++) { v[i] = xr[tid + i*256]; s += v[i]; }

    __shared__ float red[8];
    __shared__ float bc[2];
    #pragma unroll
    for (int o = 16; o; o >>= 1) s += __shfl_xor_sync(0xffffffffu, s, o);
    if ((tid & 31) == 0) red[tid >> 5] = s;
    __syncthreads();
    if (tid == 0) {
        float t = 0.f;
        #pragma unroll
        for (int i = 0; i < 8; i++) t += red[i];
        bc[0] = t * (1.0f / D_);
    }
    __syncthreads();
    const float mu = bc[0];

    float s2 = 0.f;
    #pragma unroll
    for (int i = 0; i < 3; i++) { float d = v[i] - mu; s2 += d * d; }
    #pragma unroll
    for (int o = 16; o; o >>= 1) s2 += __shfl_xor_sync(0xffffffffu, s2, o);
    if ((tid & 31) == 0) red[tid >> 5] = s2;
    __syncthreads();
    if (tid == 0) {
        float t = 0.f;
        #pragma unroll
        for (int i = 0; i < 8; i++) t += red[i];
        bc[1] = rsqrtf(t * (1.0f / D_) + EPS_);
    }
    __syncthreads();
    const float rstd = bc[1];

    float* orow = out + (size_t)row * D_;
    #pragma unroll
    for (int i = 0; i < 3; i++) {
        int c = tid + i*256;
        orow[c] = tf32r((v[i] - mu) * rstd * w[c] + b[c]);
    }
}

// ---------------- GEMM cores (shared by gemm_u and gemm_qkv) ------------------
#define NSTAGE 3
#define SLOT_BYTES 32768
#define GEMM_DYN_SMEM (NSTAGE*SLOT_BYTES + 1024)

#if TC_OK
__device__ __forceinline__ void tc_core(const float* __restrict__ A,
                                        const float* __restrict__ W,
                                        int K, int m0, int n0, char* dsm,
                                        uint32_t* dr) {
    __shared__ uint32_t tmem_ptr_s[1];
    __shared__ __align__(8) uint64_t mbar_s[NSTAGE];

    const int tid  = threadIdx.x;
    const int warp = tid >> 5;

    uint32_t rawb = smem_u32(dsm);
    uint32_t ab   = (rawb + 1023u) & ~1023u;
    uint32_t cbar[NSTAGE];
    #pragma unroll
    for (int j = 0; j < NSTAGE; j++) cbar[j] = smem_u32(&mbar_s[j]);

    if (warp == 0) {
        TC_ALLOC(smem_u32(tmem_ptr_s), 128);
        TC_RELINQ();
    }
    if (tid == 0) {
        #pragma unroll
        for (int j = 0; j < NSTAGE; j++) MBAR_INIT(cbar[j], 1);
    }
    __syncthreads();
    uint32_t tmem;
    asm volatile("ld.shared.b32 %0, [%1];" : "=r"(tmem) : "r"(smem_u32(tmem_ptr_s)));

    const int prow = tid >> 3;
    const int psub = tid & 7;

    const float* Ap[4];
    const float* Wp[4];
    uint32_t soff[4];
    #pragma unroll
    for (int p = 0; p < 4; p++) {
        const int r = prow + (p << 5);
        Ap[p] = A + (size_t)(m0 + r) * K + (psub << 2);
        Wp[p] = W + (size_t)(n0 + r) * K + (psub << 2);
        soff[p] = SWZ128((r << 7) | (psub << 4));
    }

    const int nst = K >> 5;

    #define ISSUE_STAGE(s)                                                   \
        do {                                                                 \
            const int _j = (s) % NSTAGE;                                     \
            const uint32_t _ab = ab + _j * SLOT_BYTES;                       \
            const uint32_t _bb = _ab + 16384;                                \
            const int _ko = (s) << 5;                                        \
            _Pragma("unroll")                                                \
            for (int p = 0; p < 4; p++) {                                    \
                cp16(_ab + soff[p], Ap[p] + _ko);                            \
                cp16(_bb + soff[p], Wp[p] + _ko);                            \
            }                                                                \
            CP_COMMIT();                                                     \
        } while (0)

    ISSUE_STAGE(0);
    ISSUE_STAGE(1);

    for (int i = 0; i < nst; i++) {
        const int pf = i + NSTAGE - 1;
        if (pf < nst) {
            if (i >= 1) MBAR_WAIT(cbar[(i - 1) % NSTAGE], ((i - 1) / NSTAGE) & 1);
            ISSUE_STAGE(pf);
            asm volatile("cp.async.wait_group 2;" ::: "memory");
        } else if (pf == nst) {
            asm volatile("cp.async.wait_group 1;" ::: "memory");
        } else {
            asm volatile("cp.async.wait_group 0;" ::: "memory");
        }
        FENCE_ASYNC_SH();
        __syncthreads();

        if (warp == 0 && elect_one()) {
            const int j = i % NSTAGE;
            const uint64_t ad = mk_desc(ab + j * SLOT_BYTES);
            const uint64_t bd = mk_desc(ab + j * SLOT_BYTES + 16384);
            #pragma unroll
            for (int kk = 0; kk < 4; kk++)
                tc_mma_tf32_ss(tmem, ad + kk*2, bd + kk*2, TC_IDESC, (i > 0) || (kk > 0));
            TC_COMMIT(cbar[j]);
        }
    }
    #undef ISSUE_STAGE

    MBAR_WAIT(cbar[(nst - 1) % NSTAGE], ((nst - 1) / NSTAGE) & 1);
    TC_FENCE_AFTER();

    const int cb = (warp >> 2) << 6;
    TC_LD_X32(dr,      tmem + cb);
    TC_LD_X32(dr + 32, tmem + cb + 32);
    TC_WAIT_LD();
    __syncthreads();
    if (warp == 0) TC_DEALLOC(tmem, 128);
}
#else
__device__ __forceinline__ void fb_core(const float* __restrict__ A,
                                        const float* __restrict__ W,
                                        int K, int m0, int n0, char* dsm,
                                        float (*acc)[4][4]) {
    typedef unsigned SmemBuf[128][16];
    SmemBuf* As = reinterpret_cast<SmemBuf*>(dsm);
    SmemBuf* Ws = reinterpret_cast<SmemBuf*>(dsm + 2 * sizeof(SmemBuf));

    const int tid  = threadIdx.x;
    const int lane = tid & 31;
    const int warp = tid >> 5;
    const int wm = (warp >> 2) * 64;
    const int wn = (warp & 3) * 32;
    const int grp = lane >> 2;
    const int qk  = lane & 3;

    const int ldr = tid >> 2;
    const int sub = tid & 3;
    const float* Ap0 = A + (size_t)(m0 + ldr) * K + (sub << 2);
    const float* Ap1 = A + (size_t)(m0 + ldr + 64) * K + (sub << 2);
    const float* Wp0 = W + (size_t)(n0 + ldr) * K + (sub << 2);
    const float* Wp1 = W + (size_t)(n0 + ldr + 64) * K + (sub << 2);
    const int sw0 = ((ldr >> 1) & 3);
    const int sw1 = (((ldr + 64) >> 1) & 3);

    const int ntiles = K >> 4;

    #define STORE_TILE(buf, a0v, a1v, w0v, w1v)                                              \
        do {                                                                                  \
            As[buf][ldr   ][((0^sw0)<<2)+sub]=__float_as_uint(a0v.x); As[buf][ldr   ][((1^sw0)<<2)+sub]=__float_as_uint(a0v.y); \
            As[buf][ldr   ][((2^sw0)<<2)+sub]=__float_as_uint(a0v.z); As[buf][ldr   ][((3^sw0)<<2)+sub]=__float_as_uint(a0v.w); \
            As[buf][ldr+64][((0^sw1)<<2)+sub]=__float_as_uint(a1v.x); As[buf][ldr+64][((1^sw1)<<2)+sub]=__float_as_uint(a1v.y); \
            As[buf][ldr+64][((2^sw1)<<2)+sub]=__float_as_uint(a1v.z); As[buf][ldr+64][((3^sw1)<<2)+sub]=__float_as_uint(a1v.w); \
            Ws[buf][ldr   ][((0^sw0)<<2)+sub]=__float_as_uint(w0v.x); Ws[buf][ldr   ][((1^sw0)<<2)+sub]=__float_as_uint(w0v.y); \
            Ws[buf][ldr   ][((2^sw0)<<2)+sub]=__float_as_uint(w0v.z); Ws[buf][ldr   ][((3^sw0)<<2)+sub]=__float_as_uint(w0v.w); \
            Ws[buf][ldr+64][((0^sw1)<<2)+sub]=__float_as_uint(w1v.x); Ws[buf][ldr+64][((1^sw1)<<2)+sub]=__float_as_uint(w1v.y); \
            Ws[buf][ldr+64][((2^sw1)<<2)+sub]=__float_as_uint(w1v.z); Ws[buf][ldr+64][((3^sw1)<<2)+sub]=__float_as_uint(w1v.w); \
        } while (0)

    {
        float4 a0 = *(const float4*)(Ap0);
        float4 a1 = *(const float4*)(Ap1);
        float4 w0 = *(const float4*)(Wp0);
        float4 w1 = *(const float4*)(Wp1);
        STORE_TILE(0, a0, a1, w0, w1);
    }
    __syncthreads();

    for (int it = 0; it < ntiles; it++) {
        const int cur = it & 1, nxt = cur ^ 1;
        float4 a0, a1, w0, w1;
        const bool have_next = (it + 1) < ntiles;
        if (have_next) {
            const int ko = (it + 1) << 4;
            a0 = *(const float4*)(Ap0 + ko);
            a1 = *(const float4*)(Ap1 + ko);
            w0 = *(const float4*)(Wp0 + ko);
            w1 = *(const float4*)(Wp1 + ko);
        }

        uint4 Bv[4];
        #pragma unroll
        for (int ni = 0; ni < 4; ni++) {
            const int rn = wn + (ni << 3) + grp;
            Bv[ni] = *(const uint4*)&Ws[cur][rn][((qk ^ ((rn >> 1) & 3)) << 2)];
        }
        #pragma unroll
        for (int mi = 0; mi < 4; mi++) {
            const int rl = wm + (mi << 4) + grp;
            const int rh = rl + 8;
            const uint4 Alo = *(const uint4*)&As[cur][rl][((qk ^ ((rl >> 1) & 3)) << 2)];
            const uint4 Ahi = *(const uint4*)&As[cur][rh][((qk ^ ((rh >> 1) & 3)) << 2)];
            #pragma unroll
            for (int ni = 0; ni < 4; ni++) {
                mma_tf32(acc[mi][ni][0], acc[mi][ni][1], acc[mi][ni][2], acc[mi][ni][3],
                         Alo.x, Ahi.x, Alo.y, Ahi.y, Bv[ni].x, Bv[ni].y);
                mma_tf32(acc[mi][ni][0], acc[mi][ni][1], acc[mi][ni][2], acc[mi][ni][3],
                         Alo.z, Ahi.z, Alo.w, Ahi.w, Bv[ni].z, Bv[ni].w);
            }
        }

        if (have_next) {
            STORE_TILE(nxt, a0, a1, w0, w1);
        }
        __syncthreads();
    }
    #undef STORE_TILE
}
#endif

// ---------------- generic GEMM: EP 0 plain / 2 GELU / 3 +res; RND tf32 -------
template<int EP, int RND>
__global__ __launch_bounds__(256, 2)
void gemm_u(const float* __restrict__ A, const float* __restrict__ W,
            const float* __restrict__ bias, const float* __restrict__ res,
            float* __restrict__ C, int M, int N, int K) {
    extern __shared__ char dsm[];
    const int tid  = threadIdx.x;
    const int warp = tid >> 5;
    const int lane = tid & 31;
    const int m0 = blockIdx.y << 7, n0 = blockIdx.x << 7;

#if TC_OK
    uint32_t dr[64];
    tc_core(A, W, K, m0, n0, dsm, dr);

    const int r  = m0 + ((warp & 3) << 5) + lane;
    const int cg = n0 + ((warp >> 2) << 6);
    float* crow = C + (size_t)r * N + cg;
    const float* rrow = (EP == 3) ? (res + (size_t)r * N + cg) : nullptr;
    #pragma unroll
    for (int j4 = 0; j4 < 16; j4++) {
        float4 bv = *(const float4*)(bias + cg + (j4 << 2));
        float4 o;
        o.x = __uint_as_float(dr[j4*4+0]) + bv.x;
        o.y = __uint_as_float(dr[j4*4+1]) + bv.y;
        o.z = __uint_as_float(dr[j4*4+2]) + bv.z;
        o.w = __uint_as_float(dr[j4*4+3]) + bv.w;
        if (EP == 2) {
            o.x = 0.5f * o.x * (1.0f + erff(o.x * 0.70710678118654752f));
            o.y = 0.5f * o.y * (1.0f + erff(o.y * 0.70710678118654752f));
            o.z = 0.5f * o.z * (1.0f + erff(o.z * 0.70710678118654752f));
            o.w = 0.5f * o.w * (1.0f + erff(o.w * 0.70710678118654752f));
        }
        if (EP == 3) {
            float4 rv = *(const float4*)(rrow + (j4 << 2));
            o.x += rv.x; o.y += rv.y; o.z += rv.z; o.w += rv.w;
        }
        if (RND) { o.x = tf32r(o.x); o.y = tf32r(o.y); o.z = tf32r(o.z); o.w = tf32r(o.w); }
        *(float4*)(crow + (j4 << 2)) = o;
    }
#else
    float acc[4][4][4];
    #pragma unroll
    for (int i = 0; i < 4; i++)
        #pragma unroll
        for (int j = 0; j < 4; j++)
            #pragma unroll
            for (int f = 0; f < 4; f++) acc[i][j][f] = 0.f;
    fb_core(A, W, K, m0, n0, dsm, acc);

    const int wm = (warp >> 2) * 64;
    const int wn = (warp & 3) * 32;
    const int grp = lane >> 2;
    const int qk  = lane & 3;
    #pragma unroll
    for (int mi = 0; mi < 4; mi++) {
        #pragma unroll
        for (int ni = 0; ni < 4; ni++) {
            #pragma unroll
            for (int f = 0; f < 4; f++) {
                const int r = m0 + wm + (mi << 4) + grp + ((f >> 1) << 3);
                const int c = n0 + wn + (ni << 3) + (qk << 1) + (f & 1);
                float val = acc[mi][ni][f] + bias[c];
                if (EP == 2) val = 0.5f * val * (1.0f + erff(val * 0.70710678118654752f));
                if (EP == 3) val += res[(size_t)r * N + c];
                if (RND) val = tf32r(val);
                C[(size_t)r * N + c] = val;
            }
        }
    }
#endif
}

// ---------------- fused QKV GEMM + RoPE epilogue ------------------------------
// grid (6, 64, 3): z=0 Q (scale+rope), z=1 K (rope), z=2 V (plain). All tf32-rounded.
__global__ __launch_bounds__(256, 2)
void gemm_qkv(const float* __restrict__ A, const float* __restrict__ cw,
              const float* __restrict__ bq, const float* __restrict__ bk,
              const float* __restrict__ bv, const float* __restrict__ freqs,
              float* __restrict__ q, float* __restrict__ k, float* __restrict__ v) {
    extern __shared__ char dsm[];
    const int tid  = threadIdx.x;
    const int warp = tid >> 5;
    const int lane = tid & 31;
    const int m0 = blockIdx.y << 7, n0 = blockIdx.x << 7;
    const int z  = blockIdx.z;
    const float* W    = cw + (size_t)z * CW_DD;
    const float* bias = (z == 0) ? bq : (z == 1) ? bk : bv;
    float* C          = (z == 0) ? q  : (z == 1) ? k  : v;

#if TC_OK
    uint32_t dr[64];
    tc_core(A, W, D_, m0, n0, dsm, dr);

    const int r  = m0 + ((warp & 3) << 5) + lane;
    const int cg = n0 + ((warp >> 2) << 6);
    const float n_pos = (float)(r & (N_ - 1));
    float* crow = C + (size_t)r * D_ + cg;
    #pragma unroll
    for (int j4 = 0; j4 < 16; j4++) {
        const int c4 = cg + (j4 << 2);
        float4 bvv = *(const float4*)(bias + c4);
        float4 o;
        o.x = __uint_as_float(dr[j4*4+0]) + bvv.x;
        o.y = __uint_as_float(dr[j4*4+1]) + bvv.y;
        o.z = __uint_as_float(dr[j4*4+2]) + bvv.z;
        o.w = __uint_as_float(dr[j4*4+3]) + bvv.w;
        if (z == 0) { o.x *= SCALING_; o.y *= SCALING_; o.z *= SCALING_; o.w *= SCALING_; }
        if (z < 2) {
            const int i0 = (c4 & 63) >> 1;
            float s0, c0, s1, c1;
            __sincosf(n_pos * freqs[i0],     &s0, &c0);
            __sincosf(n_pos * freqs[i0 + 1], &s1, &c1);
            float4 t = o;
            o.x = t.x * c0 - t.y * s0;
            o.y = t.y * c0 + t.x * s0;
            o.z = t.z * c1 - t.w * s1;
            o.w = t.w * c1 + t.z * s1;
        }
        o.x = tf32r(o.x); o.y = tf32r(o.y); o.z = tf32r(o.z); o.w = tf32r(o.w);
        *(float4*)(crow + (j4 << 2)) = o;
    }
#else
    float acc[4][4][4];
    #pragma unroll
    for (int i = 0; i < 4; i++)
        #pragma unroll
        for (int j = 0; j < 4; j++)
            #pragma unroll
            for (int f = 0; f < 4; f++) acc[i][j][f] = 0.f;
    fb_core(A, W, D_, m0, n0, dsm, acc);

    const int wm = (warp >> 2) * 64;
    const int wn = (warp & 3) * 32;
    const int grp = lane >> 2;
    const int qk  = lane & 3;
    #pragma unroll
    for (int mi = 0; mi < 4; mi++) {
        #pragma unroll
        for (int ni = 0; ni < 4; ni++) {
            #pragma unroll
            for (int fp = 0; fp < 2; fp++) {
                const int r = m0 + wm + (mi << 4) + grp + (fp << 3);
                const int c0 = n0 + wn + (ni << 3) + (qk << 1);
                float v0 = acc[mi][ni][fp*2+0] + bias[c0];
                float v1 = acc[mi][ni][fp*2+1] + bias[c0+1];
                if (z == 0) { v0 *= SCALING_; v1 *= SCALING_; }
                if (z < 2) {
                    const int i0 = (c0 & 63) >> 1;
                    float s0, cc0;
                    __sincosf((float)(r & (N_-1)) * freqs[i0], &s0, &cc0);
                    float t0 = v0, t1 = v1;
                    v0 = t0 * cc0 - t1 * s0;
                    v1 = t1 * cc0 + t0 * s0;
                }
                C[(size_t)r * D_ + c0]     = tf32r(v0);
                C[(size_t)r * D_ + c0 + 1] = tf32r(v1);
            }
        }
    }
#endif
}

// ---------------- flash attention, tf32 mma.sync, BQ=128 BK=64 ---------------
// 65.6KB smem, 2 CTAs/SM (131KB < 228KB). q/k/v pre-rounded -> raw-bit moves.
#define ATTN_SMEM (16384 + 16384 + 32768 + 64)
__global__ __launch_bounds__(256, 2)
void attn_tc(const float* __restrict__ q, const float* __restrict__ k,
             const float* __restrict__ v, const unsigned char* __restrict__ pm,
             float* __restrict__ out) {
    extern __shared__ char asmem[];
    unsigned* Ks = (unsigned*)asmem;               // [4][64][16]  keys x d
    unsigned* Vt = (unsigned*)(asmem + 16384);     // [4][64][16]  dims x keys
    unsigned* Ps = (unsigned*)(asmem + 32768);     // [4][128][16] qrows x keys
    unsigned char* Ms = (unsigned char*)(asmem + 65536);

    const int tid = threadIdx.x, warp = tid >> 5, lane = tid & 31;
    const int grp = lane >> 2, qk = lane & 3;
    const int qt = blockIdx.x, bh = blockIdx.y;
    const int b = bh / H_, h = bh - b * H_;
    const int row0 = b * N_ + qt * 128;
    const int colh = h * HD_;
    const int rl0 = (warp << 4) + grp;
    const int rl1 = rl0 + 8;
    const int r0 = row0 + rl0;

    unsigned aq[8][4];
    {
        const float* q0 = q + (size_t)r0 * D_ + colh;
        const float* q1 = q0 + (size_t)8 * D_;
        #pragma unroll
        for (int s = 0; s < 8; s++) {
            aq[s][0] = __float_as_uint(q0[s*8 + qk]);
            aq[s][1] = __float_as_uint(q1[s*8 + qk]);
            aq[s][2] = __float_as_uint(q0[s*8 + qk + 4]);
            aq[s][3] = __float_as_uint(q1[s*8 + qk + 4]);
        }
    }

    float o_[8][4];
    #pragma unroll
    for (int nt = 0; nt < 8; nt++) { o_[nt][0]=0.f; o_[nt][1]=0.f; o_[nt][2]=0.f; o_[nt][3]=0.f; }
    float m0 = -3.0e38f, m1 = -3.0e38f, l0 = 0.f, l1 = 0.f;

    const int lkey = tid >> 2, lq = tid & 3;
    const int swk = (lkey >> 1) & 3;
    const int vpl = lkey >> 4, vkk = lkey & 15;
    const int swp0 = (rl0 >> 1) & 3, swp1 = (rl1 >> 1) & 3;

    for (int kt = 0; kt < N_; kt += 64) {
        __syncthreads();
        {
            const size_t gbase = (size_t)(b * N_ + kt + lkey) * D_ + colh;
            #pragma unroll
            for (int c = 0; c < 4; c++) {
                const uint4 k4 = *(const uint4*)(k + gbase + 16*c + 4*lq);
                const uint4 v4 = *(const uint4*)(v + gbase + 16*c + 4*lq);
                unsigned* kp = Ks + (c << 10) + (lkey << 4);
                kp[((0^swk)<<2)+lq] = k4.x;
                kp[((1^swk)<<2)+lq] = k4.y;
                kp[((2^swk)<<2)+lq] = k4.z;
                kp[((3^swk)<<2)+lq] = k4.w;
                const unsigned vv[4] = {v4.x, v4.y, v4.z, v4.w};
                #pragma unroll
                for (int i = 0; i < 4; i++) {
                    const int d = 16*c + 4*lq + i;
                    const int quad = (vkk & 3) ^ ((d >> 1) & 3);
                    Vt[(vpl << 10) + (d << 4) + (quad << 2) + (vkk >> 2)] = vv[i];
                }
            }
            if (tid < 64) Ms[tid] = pm[b * N_ + kt + tid];
        }
        __syncthreads();

        float s_[8][4];
        #pragma unroll
        for (int nt = 0; nt < 8; nt++) { s_[nt][0]=0.f; s_[nt][1]=0.f; s_[nt][2]=0.f; s_[nt][3]=0.f; }
        #pragma unroll
        for (int c = 0; c < 4; c++) {
            #pragma unroll
            for (int nt = 0; nt < 8; nt++) {
                const int rn = (nt << 3) + grp;
                const uint4 Bv = *(const uint4*)(Ks + (c << 10) + (rn << 4)
                                                 + ((qk ^ ((rn >> 1) & 3)) << 2));
                mma_tf32(s_[nt][0], s_[nt][1], s_[nt][2], s_[nt][3],
                         aq[2*c][0], aq[2*c][1], aq[2*c][2], aq[2*c][3], Bv.x, Bv.y);
                mma_tf32(s_[nt][0], s_[nt][1], s_[nt][2], s_[nt][3],
                         aq[2*c+1][0], aq[2*c+1][1], aq[2*c+1][2], aq[2*c+1][3], Bv.z, Bv.w);
            }
        }

        float mx0 = -3.0e38f, mx1 = -3.0e38f;
        #pragma unroll
        for (int nt = 0; nt < 8; nt++) {
            const int c0 = (nt << 3) + (qk << 1);
            const bool k0m = Ms[c0] != 0, k1m = Ms[c0 + 1] != 0;
            s_[nt][0] = k0m ? -3.0e38f : s_[nt][0] * 0.125f;
            s_[nt][1] = k1m ? -3.0e38f : s_[nt][1] * 0.125f;
            s_[nt][2] = k0m ? -3.0e38f : s_[nt][2] * 0.125f;
            s_[nt][3] = k1m ? -3.0e38f : s_[nt][3] * 0.125f;
            mx0 = fmaxf(mx0, fmaxf(s_[nt][0], s_[nt][1]));
            mx1 = fmaxf(mx1, fmaxf(s_[nt][2], s_[nt][3]));
        }
        mx0 = fmaxf(mx0, __shfl_xor_sync(0xffffffffu, mx0, 1));
        mx0 = fmaxf(mx0, __shfl_xor_sync(0xffffffffu, mx0, 2));
        mx1 = fmaxf(mx1, __shfl_xor_sync(0xffffffffu, mx1, 1));
        mx1 = fmaxf(mx1, __shfl_xor_sync(0xffffffffu, mx1, 2));

        const float mn0 = fmaxf(m0, mx0), mn1 = fmaxf(m1, mx1);
        const float al0 = __expf(m0 - mn0), al1 = __expf(m1 - mn1);
        m0 = mn0; m1 = mn1;
        float rs0 = 0.f, rs1 = 0.f;
        #pragma unroll
        for (int nt = 0; nt < 8; nt++) {
            s_[nt][0] = __expf(s_[nt][0] - mn0);
            s_[nt][1] = __expf(s_[nt][1] - mn0);
            s_[nt][2] = __expf(s_[nt][2] - mn1);
            s_[nt][3] = __expf(s_[nt][3] - mn1);
            rs0 += s_[nt][0] + s_[nt][1];
            rs1 += s_[nt][2] + s_[nt][3];
            o_[nt][0] *= al0; o_[nt][1] *= al0;
            o_[nt][2] *= al1; o_[nt][3] *= al1;
        }
        rs0 += __shfl_xor_sync(0xffffffffu, rs0, 1);
        rs0 += __shfl_xor_sync(0xffffffffu, rs0, 2);
        rs1 += __shfl_xor_sync(0xffffffffu, rs1, 1);
        rs1 += __shfl_xor_sync(0xffffffffu, rs1, 2);
        l0 = l0 * al0 + rs0;
        l1 = l1 * al1 + rs1;

        #pragma unroll
        for (int nt = 0; nt < 8; nt++) {
            #pragma unroll
            for (int i2 = 0; i2 < 2; i2++) {
                const int ck = (nt << 3) + (qk << 1) + i2;
                const int pl = ck >> 4, kk = ck & 15;
                const int w_ = kk >> 2;
                Ps[(pl << 11) + (rl0 << 4) + ((((kk & 3) ^ swp0)) << 2) + w_] = f2tf32(s_[nt][i2]);
                Ps[(pl << 11) + (rl1 << 4) + ((((kk & 3) ^ swp1)) << 2) + w_] = f2tf32(s_[nt][2 + i2]);
            }
        }
        __syncthreads();

        #pragma unroll
        for (int c = 0; c < 4; c++) {
            const uint4 Alo = *(const uint4*)(Ps + (c << 11) + (rl0 << 4) + ((qk ^ swp0) << 2));
            const uint4 Ahi = *(const uint4*)(Ps + (c << 11) + (rl1 << 4) + ((qk ^ swp1) << 2));
            #pragma unroll
            for (int nt = 0; nt < 8; nt++) {
                const int rn = (nt << 3) + grp;
                const uint4 Bv = *(const uint4*)(Vt + (c << 10) + (rn << 4)
                                                 + ((qk ^ ((rn >> 1) & 3)) << 2));
                mma_tf32(o_[nt][0], o_[nt][1], o_[nt][2], o_[nt][3],
                         Alo.x, Ahi.x, Alo.y, Ahi.y, Bv.x, Bv.y);
                mma_tf32(o_[nt][0], o_[nt][1], o_[nt][2], o_[nt][3],
                         Alo.z, Ahi.z, Alo.w, Ahi.w, Bv.z, Bv.w);
            }
        }
    }

    const float inv0 = 1.0f / l0, inv1 = 1.0f / l1;
    float* out0 = out + (size_t)r0 * D_ + colh;
    float* out1 = out0 + (size_t)8 * D_;
    #pragma unroll
    for (int nt = 0; nt < 8; nt++) {
        const int c0 = (nt << 3) + (qk << 1);
        out0[c0]     = tf32r(o_[nt][0] * inv0);
        out0[c0 + 1] = tf32r(o_[nt][1] * inv0);
        out1[c0]     = tf32r(o_[nt][2] * inv1);
        out1[c0 + 1] = tf32r(o_[nt][3] * inv1);
    }
}

// ---------------- launch ------------------------------------------------------
extern "C" void kernel_launch(void* const* d_in, const int* in_sizes, int n_in,
                              void* d_out, int out_size) {
    const float* x     = (const float*)d_in[0];
    const unsigned char* pmask = (const unsigned char*)d_in[1];
    const float* wq = (const float*)d_in[2];
    const float* bq = (const float*)d_in[3];
    const float* wk = (const float*)d_in[4];
    const float* bk = (const float*)d_in[5];
    const float* wv = (const float*)d_in[6];
    const float* bv = (const float*)d_in[7];
    const float* wo = (const float*)d_in[8];
    const float* bo = (const float*)d_in[9];
    const float* w1 = (const float*)d_in[10];
    const float* b1 = (const float*)d_in[11];
    const float* w2 = (const float*)d_in[12];
    const float* b2 = (const float*)d_in[13];
    const float* ln1w = (const float*)d_in[14];
    const float* ln1b = (const float*)d_in[15];
    const float* ln2w = (const float*)d_in[16];
    const float* ln2b = (const float*)d_in[17];
    const float* freqs = (const float*)d_in[18];
    float* out = (float*)d_out;

    float *ph, *pq, *pk, *pv, *patt, *pff, *pcw;
    cudaGetSymbolAddress((void**)&ph,   g_h);
    cudaGetSymbolAddress((void**)&pq,   g_q);
    cudaGetSymbolAddress((void**)&pk,   g_k);
    cudaGetSymbolAddress((void**)&pv,   g_v);
    cudaGetSymbolAddress((void**)&patt, g_att);
    cudaGetSymbolAddress((void**)&pff,  g_ff);
    cudaGetSymbolAddress((void**)&pcw,  g_cw);

    float* cwo = pcw + 3*CW_DD;
    float* cw1 = pcw + 4*CW_DD;
    float* cw2 = pcw + 4*CW_DD + CW_FD;

    cudaFuncSetAttribute(gemm_u<0,0>, cudaFuncAttributeMaxDynamicSharedMemorySize, GEMM_DYN_SMEM);
    cudaFuncSetAttribute(gemm_u<2,1>, cudaFuncAttributeMaxDynamicSharedMemorySize, GEMM_DYN_SMEM);
    cudaFuncSetAttribute(gemm_u<3,0>, cudaFuncAttributeMaxDynamicSharedMemorySize, GEMM_DYN_SMEM);
    cudaFuncSetAttribute(gemm_qkv,    cudaFuncAttributeMaxDynamicSharedMemorySize, GEMM_DYN_SMEM);
    cudaFuncSetAttribute(attn_tc,     cudaFuncAttributeMaxDynamicSharedMemorySize, ATTN_SMEM);

    const dim3 gD(D_ / 128, M_ / 128);        // (6, 64)
    const dim3 gQKV(D_ / 128, M_ / 128, 3);   // (6, 64, 3)
    const dim3 gF(FF_ / 128, M_ / 128);       // (24, 64)
    const int ntotal4 = (4*CW_DD + 2*CW_FD) / 4;

    // tf32-round all six weight matrices in ONE launch
    cvt_all_kernel<<<(ntotal4 + 255)/256, 256>>>(
        (const float4*)wq, (const float4*)wk, (const float4*)wv,
        (const float4*)wo, (const float4*)w1, (const float4*)w2, (float4*)pcw);

    // LN1 (tf32-rounded output)
    ln_kernel<<<M_, 256>>>(x, ln1w, ln1b, ph);
    // fused QKV projections + RoPE (one launch)
    gemm_qkv<<<gQKV, 256, GEMM_DYN_SMEM>>>(ph, pcw, bq, bk, bv, freqs, pq, pk, pv);
    // attention (BK=64, 2 CTAs/SM)
    attn_tc<<<dim3(N_ / 128, B_ * H_), 256, ATTN_SMEM>>>(pq, pk, pv, pmask, patt);
    // O projection + residual (x) -> d_out
    gemm_u<3,0><<<gD, 256, GEMM_DYN_SMEM>>>(patt, cwo, bo, x, out, M_, D_, D_);
    // LN2 (reuse g_h)
    ln_kernel<<<M_, 256>>>(out, ln2w, ln2b, ph);
    // FFN1 with exact GELU (rounded output feeds FFN2)
    gemm_u<2,1><<<gF, 256, GEMM_DYN_SMEM>>>(ph, cw1, b1, nullptr, pff, M_, FF_, D_);
    // FFN2 + residual (d_out) -> d_out
    gemm_u<3,0><<<gD, 256, GEMM_DYN_SMEM>>>(pff, cw2, b2, out, out, M_, D_, FF_);
}

// round 14
// speedup vs baseline: 1.4482x; 1.4482x over previous
#include <cuda_runtime.h>
#include <math.h>
#include <stdint.h>

#define D_  768
#define H_  12
#define HD_ 64
#define FF_ 3072
#define B_  8
#define N_  1024
#define M_  (B_*N_)          // 8192 rows
#define SCALING_ 0.125f      // HD^-0.5
#define EPS_ 1e-5f

#if defined(__CUDA_ARCH_FEAT_SM103_ALL) || defined(__CUDA_ARCH_FEAT_SM100_ALL) || \
    defined(__CUDA_ARCH_SPECIFIC__) || defined(__CUDA_ARCH_FAMILY_SPECIFIC__)
#define TC_OK 1
#else
#define TC_OK 0
#endif

// ---------------- scratch (static device globals; no allocation) -------------
__device__ float g_h  [M_*D_];
__device__ float g_q  [M_*D_];
__device__ float g_k  [M_*D_];
__device__ float g_v  [M_*D_];
__device__ float g_att[M_*D_];
__device__ float g_ff [M_*FF_];
#define CW_DD (D_*D_)
#define CW_FD (FF_*D_)
__device__ float g_cw [4*CW_DD + 2*CW_FD];

// ---------------- common helpers ---------------------------------------------
__device__ __forceinline__ unsigned f2tf32(float f) {
    unsigned r;
    asm("cvt.rna.tf32.f32 %0, %1;" : "=r"(r) : "f"(f));
    return r;
}
__device__ __forceinline__ float tf32r(float f) { return __uint_as_float(f2tf32(f)); }

#if TC_OK
__device__ __forceinline__ uint32_t smem_u32(const void* p) {
    uint32_t a;
    asm("{ .reg .u64 t; cvta.to.shared.u64 t, %1; cvt.u32.u64 %0, t; }" : "=r"(a) : "l"(p));
    return a;
}
__device__ __forceinline__ uint32_t elect_one() {
    uint32_t p;
    asm volatile("{ .reg .pred p; elect.sync _|p, 0xFFFFFFFF; selp.b32 %0, 1, 0, p; }" : "=r"(p));
    return p;
}
__device__ __forceinline__ void cp16(uint32_t smaddr, const void* g) {
    asm volatile("cp.async.cg.shared.global [%0], [%1], 16;" :: "r"(smaddr), "l"(g) : "memory");
}
#define CP_COMMIT() asm volatile("cp.async.commit_group;" ::: "memory")
#define TC_ALLOC(smem_addr, n) \
    asm volatile("tcgen05.alloc.cta_group::1.sync.aligned.shared::cta.b32 [%0], %1;" \
                 :: "r"(smem_addr), "r"((uint32_t)(n)) : "memory")
#define TC_RELINQ() \
    asm volatile("tcgen05.relinquish_alloc_permit.cta_group::1.sync.aligned;")
#define TC_DEALLOC(tmem, n) \
    asm volatile("tcgen05.dealloc.cta_group::1.sync.aligned.b32 %0, %1;" :: "r"(tmem), "r"((uint32_t)(n)))
#define TC_COMMIT(mbar) \
    asm volatile("tcgen05.commit.cta_group::1.mbarrier::arrive::one.shared::cluster.b64 [%0];" \
                 :: "r"(mbar) : "memory")
#define TC_FENCE_AFTER()  asm volatile("tcgen05.fence::after_thread_sync;" ::: "memory")
#define FENCE_ASYNC_SH()  asm volatile("fence.proxy.async.shared::cta;" ::: "memory")
#define MBAR_INIT(mbar, cnt) \
    asm volatile("mbarrier.init.shared.b64 [%0], %1;" :: "r"(mbar), "r"((uint32_t)(cnt)) : "memory")
#define MBAR_WAIT(mbar, ph) do {                                                  \
    asm volatile("{\n\t.reg .pred P1;\n\t"                                        \
        "WL_%=:\n\t"                                                              \
        "mbarrier.try_wait.parity.acquire.cta.shared::cta.b64 P1, [%0], %1, 0x989680;\n\t" \
        "@P1 bra.uni WD_%=;\n\t"                                                  \
        "bra.uni WL_%=;\n\t"                                                      \
        "WD_%=:\n\t}"                                                             \
        :: "r"(mbar), "r"((uint32_t)(ph)) : "memory");                            \
} while (0)
#define TC_LD_X32(r, tmem) \
    asm volatile( \
        "tcgen05.ld.sync.aligned.32x32b.x32.b32 " \
        "{%0, %1, %2, %3, %4, %5, %6, %7, " \
        " %8, %9, %10, %11, %12, %13, %14, %15, " \
        " %16, %17, %18, %19, %20, %21, %22, %23, " \
        " %24, %25, %26, %27, %28, %29, %30, %31}, [%32];" \
        : "=r"((r)[0]),  "=r"((r)[1]),  "=r"((r)[2]),  "=r"((r)[3]), \
          "=r"((r)[4]),  "=r"((r)[5]),  "=r"((r)[6]),  "=r"((r)[7]), \
          "=r"((r)[8]),  "=r"((r)[9]),  "=r"((r)[10]), "=r"((r)[11]), \
          "=r"((r)[12]), "=r"((r)[13]), "=r"((r)[14]), "=r"((r)[15]), \
          "=r"((r)[16]), "=r"((r)[17]), "=r"((r)[18]), "=r"((r)[19]), \
          "=r"((r)[20]), "=r"((r)[21]), "=r"((r)[22]), "=r"((r)[23]), \
          "=r"((r)[24]), "=r"((r)[25]), "=r"((r)[26]), "=r"((r)[27]), \
          "=r"((r)[28]), "=r"((r)[29]), "=r"((r)[30]), "=r"((r)[31]) \
        : "r"(tmem))
#define TC_WAIT_LD() asm volatile("tcgen05.wait::ld.sync.aligned;" ::: "memory")

__device__ __forceinline__ void tc_mma_tf32_ss(uint32_t d, uint64_t ad, uint64_t bd,
                                               uint32_t idesc, bool acc) {
    uint32_t e = acc ? 1u : 0u;
    asm volatile(
        "{\n\t.reg .pred p;\n\tsetp.ne.u32 p, %4, 0;\n\t"
        "tcgen05.mma.cta_group::1.kind::tf32 [%0], %1, %2, %3, {%5,%5,%5,%5}, p;\n\t}"
        :: "r"(d), "l"(ad), "l"(bd), "r"(idesc), "r"(e), "r"(0u) : "memory");
}
__device__ __forceinline__ uint64_t mk_desc(uint32_t addr) {
    const uint64_t base = (uint64_t(2) << 61) | (uint64_t(1) << 46)
                        | (uint64_t(64) << 32) | (uint64_t(1) << 16);
    return base | ((uint64_t)(addr >> 4) & 0x3FFF);
}
#define SWZ128(b) ((b) ^ (((b) >> 3) & 0x70))
#define TC_IDESC ((1u<<4)|(2u<<7)|(2u<<10)|(16u<<17)|(8u<<24))
#endif  // TC_OK

__device__ __forceinline__ void mma_tf32(float& c0, float& c1, float& c2, float& c3,
                                         unsigned a0, unsigned a1, unsigned a2, unsigned a3,
                                         unsigned b0, unsigned b1) {
    asm volatile(
        "mma.sync.aligned.m16n8k8.row.col.f32.tf32.tf32.f32 "
        "{%0,%1,%2,%3}, {%4,%5,%6,%7}, {%8,%9}, {%0,%1,%2,%3};"
        : "+f"(c0), "+f"(c1), "+f"(c2), "+f"(c3)
        : "r"(a0), "r"(a1), "r"(a2), "r"(a3), "r"(b0), "r"(b1));
}

// ---------------- one-shot tf32 rounding of all six weights (fused) ----------
__global__ __launch_bounds__(256)
void cvt_all_kernel(const float4* wq, const float4* wk, const float4* wv,
                    const float4* wo, const float4* w1, const float4* w2,
                    float4* dst) {
    const int DD4 = CW_DD/4, FD4 = CW_FD/4;
    const int total = 4*DD4 + 2*FD4;
    int i = blockIdx.x * blockDim.x + threadIdx.x;
    if (i >= total) return;
    const float4* src;
    int off;
    if (i < 4*DD4) {
        int w = i / DD4; off = i - w*DD4;
        src = (w == 0) ? wq : (w == 1) ? wk : (w == 2) ? wv : wo;
    } else {
        int j = i - 4*DD4;
        if (j < FD4) { src = w1; off = j; }
        else         { src = w2; off = j - FD4; }
    }
    float4 v = src[off];
    uint4 o;
    o.x = f2tf32(v.x); o.y = f2tf32(v.y); o.z = f2tf32(v.z); o.w = f2tf32(v.w);
    ((uint4*)dst)[i] = o;
}

// ---------------- LayerNorm (tf32-rounded output) ----------------------------
__global__ __launch_bounds__(256)
void ln_kernel(const float* __restrict__ x, const float* __restrict__ w,
               const float* __restrict__ b, float* __restrict__ out) {
    const int row = blockIdx.x;
    const int tid = threadIdx.x;
    const float* xr = x + (size_t)row * D_;
    float v[3];
    float s = 0.f;
    #pragma unroll
    for (int i = 0; i < 3; i++) { v[i] = xr[tid + i*256]; s += v[i]; }

    __shared__ float red[8];
    __shared__ float bc[2];
    #pragma unroll
    for (int o = 16; o; o >>= 1) s += __shfl_xor_sync(0xffffffffu, s, o);
    if ((tid & 31) == 0) red[tid >> 5] = s;
    __syncthreads();
    if (tid == 0) {
        float t = 0.f;
        #pragma unroll
        for (int i = 0; i < 8; i++) t += red[i];
        bc[0] = t * (1.0f / D_);
    }
    __syncthreads();
    const float mu = bc[0];

    float s2 = 0.f;
    #pragma unroll
    for (int i = 0; i < 3; i++) { float d = v[i] - mu; s2 += d * d; }
    #pragma unroll
    for (int o = 16; o; o >>= 1) s2 += __shfl_xor_sync(0xffffffffu, s2, o);
    if ((tid & 31) == 0) red[tid >> 5] = s2;
    __syncthreads();
    if (tid == 0) {
        float t = 0.f;
        #pragma unroll
        for (int i = 0; i < 8; i++) t += red[i];
        bc[1] = rsqrtf(t * (1.0f / D_) + EPS_);
    }
    __syncthreads();
    const float rstd = bc[1];

    float* orow = out + (size_t)row * D_;
    #pragma unroll
    for (int i = 0; i < 3; i++) {
        int c = tid + i*256;
        orow[c] = tf32r((v[i] - mu) * rstd * w[c] + b[c]);
    }
}

// ---------------- GEMM cores (shared by gemm_u and gemm_qkv) ------------------
#define NSTAGE 3
#define SLOT_BYTES 32768
#define GEMM_DYN_SMEM (NSTAGE*SLOT_BYTES + 1024)

#if TC_OK
__device__ __forceinline__ void tc_core(const float* __restrict__ A,
                                        const float* __restrict__ W,
                                        int K, int m0, int n0, char* dsm,
                                        uint32_t* dr) {
    __shared__ uint32_t tmem_ptr_s[1];
    __shared__ __align__(8) uint64_t mbar_s[NSTAGE];

    const int tid  = threadIdx.x;
    const int warp = tid >> 5;

    uint32_t rawb = smem_u32(dsm);
    uint32_t ab   = (rawb + 1023u) & ~1023u;
    uint32_t cbar[NSTAGE];
    #pragma unroll
    for (int j = 0; j < NSTAGE; j++) cbar[j] = smem_u32(&mbar_s[j]);

    if (warp == 0) {
        TC_ALLOC(smem_u32(tmem_ptr_s), 128);
        TC_RELINQ();
    }
    if (tid == 0) {
        #pragma unroll
        for (int j = 0; j < NSTAGE; j++) MBAR_INIT(cbar[j], 1);
    }
    __syncthreads();
    uint32_t tmem;
    asm volatile("ld.shared.b32 %0, [%1];" : "=r"(tmem) : "r"(smem_u32(tmem_ptr_s)));

    const int prow = tid >> 3;
    const int psub = tid & 7;

    const float* Ap[4];
    const float* Wp[4];
    uint32_t soff[4];
    #pragma unroll
    for (int p = 0; p < 4; p++) {
        const int r = prow + (p << 5);
        Ap[p] = A + (size_t)(m0 + r) * K + (psub << 2);
        Wp[p] = W + (size_t)(n0 + r) * K + (psub << 2);
        soff[p] = SWZ128((r << 7) | (psub << 4));
    }

    const int nst = K >> 5;

    #define ISSUE_STAGE(s)                                                   \
        do {                                                                 \
            const int _j = (s) % NSTAGE;                                     \
            const uint32_t _ab = ab + _j * SLOT_BYTES;                       \
            const uint32_t _bb = _ab + 16384;                                \
            const int _ko = (s) << 5;                                        \
            _Pragma("unroll")                                                \
            for (int p = 0; p < 4; p++) {                                    \
                cp16(_ab + soff[p], Ap[p] + _ko);                            \
                cp16(_bb + soff[p], Wp[p] + _ko);                            \
            }                                                                \
            CP_COMMIT();                                                     \
        } while (0)

    ISSUE_STAGE(0);
    ISSUE_STAGE(1);

    for (int i = 0; i < nst; i++) {
        const int pf = i + NSTAGE - 1;
        if (pf < nst) {
            if (i >= 1) MBAR_WAIT(cbar[(i - 1) % NSTAGE], ((i - 1) / NSTAGE) & 1);
            ISSUE_STAGE(pf);
            asm volatile("cp.async.wait_group 2;" ::: "memory");
        } else if (pf == nst) {
            asm volatile("cp.async.wait_group 1;" ::: "memory");
        } else {
            asm volatile("cp.async.wait_group 0;" ::: "memory");
        }
        FENCE_ASYNC_SH();
        __syncthreads();

        if (warp == 0 && elect_one()) {
            const int j = i % NSTAGE;
            const uint64_t ad = mk_desc(ab + j * SLOT_BYTES);
            const uint64_t bd = mk_desc(ab + j * SLOT_BYTES + 16384);
            #pragma unroll
            for (int kk = 0; kk < 4; kk++)
                tc_mma_tf32_ss(tmem, ad + kk*2, bd + kk*2, TC_IDESC, (i > 0) || (kk > 0));
            TC_COMMIT(cbar[j]);
        }
    }
    #undef ISSUE_STAGE

    MBAR_WAIT(cbar[(nst - 1) % NSTAGE], ((nst - 1) / NSTAGE) & 1);
    TC_FENCE_AFTER();

    const int cb = (warp >> 2) << 6;
    TC_LD_X32(dr,      tmem + cb);
    TC_LD_X32(dr + 32, tmem + cb + 32);
    TC_WAIT_LD();
    __syncthreads();
    if (warp == 0) TC_DEALLOC(tmem, 128);
}
#else
__device__ __forceinline__ void fb_core(const float* __restrict__ A,
                                        const float* __restrict__ W,
                                        int K, int m0, int n0, char* dsm,
                                        float (*acc)[4][4]) {
    typedef unsigned SmemBuf[128][16];
    SmemBuf* As = reinterpret_cast<SmemBuf*>(dsm);
    SmemBuf* Ws = reinterpret_cast<SmemBuf*>(dsm + 2 * sizeof(SmemBuf));

    const int tid  = threadIdx.x;
    const int lane = tid & 31;
    const int warp = tid >> 5;
    const int wm = (warp >> 2) * 64;
    const int wn = (warp & 3) * 32;
    const int grp = lane >> 2;
    const int qk  = lane & 3;

    const int ldr = tid >> 2;
    const int sub = tid & 3;
    const float* Ap0 = A + (size_t)(m0 + ldr) * K + (sub << 2);
    const float* Ap1 = A + (size_t)(m0 + ldr + 64) * K + (sub << 2);
    const float* Wp0 = W + (size_t)(n0 + ldr) * K + (sub << 2);
    const float* Wp1 = W + (size_t)(n0 + ldr + 64) * K + (sub << 2);
    const int sw0 = ((ldr >> 1) & 3);
    const int sw1 = (((ldr + 64) >> 1) & 3);

    const int ntiles = K >> 4;

    #define STORE_TILE(buf, a0v, a1v, w0v, w1v)                                              \
        do {                                                                                  \
            As[buf][ldr   ][((0^sw0)<<2)+sub]=__float_as_uint(a0v.x); As[buf][ldr   ][((1^sw0)<<2)+sub]=__float_as_uint(a0v.y); \
            As[buf][ldr   ][((2^sw0)<<2)+sub]=__float_as_uint(a0v.z); As[buf][ldr   ][((3^sw0)<<2)+sub]=__float_as_uint(a0v.w); \
            As[buf][ldr+64][((0^sw1)<<2)+sub]=__float_as_uint(a1v.x); As[buf][ldr+64][((1^sw1)<<2)+sub]=__float_as_uint(a1v.y); \
            As[buf][ldr+64][((2^sw1)<<2)+sub]=__float_as_uint(a1v.z); As[buf][ldr+64][((3^sw1)<<2)+sub]=__float_as_uint(a1v.w); \
            Ws[buf][ldr   ][((0^sw0)<<2)+sub]=__float_as_uint(w0v.x); Ws[buf][ldr   ][((1^sw0)<<2)+sub]=__float_as_uint(w0v.y); \
            Ws[buf][ldr   ][((2^sw0)<<2)+sub]=__float_as_uint(w0v.z); Ws[buf][ldr   ][((3^sw0)<<2)+sub]=__float_as_uint(w0v.w); \
            Ws[buf][ldr+64][((0^sw1)<<2)+sub]=__float_as_uint(w1v.x); Ws[buf][ldr+64][((1^sw1)<<2)+sub]=__float_as_uint(w1v.y); \
            Ws[buf][ldr+64][((2^sw1)<<2)+sub]=__float_as_uint(w1v.z); Ws[buf][ldr+64][((3^sw1)<<2)+sub]=__float_as_uint(w1v.w); \
        } while (0)

    {
        float4 a0 = *(const float4*)(Ap0);
        float4 a1 = *(const float4*)(Ap1);
        float4 w0 = *(const float4*)(Wp0);
        float4 w1 = *(const float4*)(Wp1);
        STORE_TILE(0, a0, a1, w0, w1);
    }
    __syncthreads();

    for (int it = 0; it < ntiles; it++) {
        const int cur = it & 1, nxt = cur ^ 1;
        float4 a0, a1, w0, w1;
        const bool have_next = (it + 1) < ntiles;
        if (have_next) {
            const int ko = (it + 1) << 4;
            a0 = *(const float4*)(Ap0 + ko);
            a1 = *(const float4*)(Ap1 + ko);
            w0 = *(const float4*)(Wp0 + ko);
            w1 = *(const float4*)(Wp1 + ko);
        }

        uint4 Bv[4];
        #pragma unroll
        for (int ni = 0; ni < 4; ni++) {
            const int rn = wn + (ni << 3) + grp;
            Bv[ni] = *(const uint4*)&Ws[cur][rn][((qk ^ ((rn >> 1) & 3)) << 2)];
        }
        #pragma unroll
        for (int mi = 0; mi < 4; mi++) {
            const int rl = wm + (mi << 4) + grp;
            const int rh = rl + 8;
            const uint4 Alo = *(const uint4*)&As[cur][rl][((qk ^ ((rl >> 1) & 3)) << 2)];
            const uint4 Ahi = *(const uint4*)&As[cur][rh][((qk ^ ((rh >> 1) & 3)) << 2)];
            #pragma unroll
            for (int ni = 0; ni < 4; ni++) {
                mma_tf32(acc[mi][ni][0], acc[mi][ni][1], acc[mi][ni][2], acc[mi][ni][3],
                         Alo.x, Ahi.x, Alo.y, Ahi.y, Bv[ni].x, Bv[ni].y);
                mma_tf32(acc[mi][ni][0], acc[mi][ni][1], acc[mi][ni][2], acc[mi][ni][3],
                         Alo.z, Ahi.z, Alo.w, Ahi.w, Bv[ni].z, Bv[ni].w);
            }
        }

        if (have_next) {
            STORE_TILE(nxt, a0, a1, w0, w1);
        }
        __syncthreads();
    }
    #undef STORE_TILE
}
#endif

// ---------------- generic GEMM: EP 0 plain / 2 GELU / 3 +res; RND tf32 -------
template<int EP, int RND>
__global__ __launch_bounds__(256, 2)
void gemm_u(const float* __restrict__ A, const float* __restrict__ W,
            const float* __restrict__ bias, const float* __restrict__ res,
            float* __restrict__ C, int M, int N, int K) {
    extern __shared__ char dsm[];
    const int tid  = threadIdx.x;
    const int warp = tid >> 5;
    const int lane = tid & 31;
    const int m0 = blockIdx.y << 7, n0 = blockIdx.x << 7;

#if TC_OK
    uint32_t dr[64];
    tc_core(A, W, K, m0, n0, dsm, dr);

    const int r  = m0 + ((warp & 3) << 5) + lane;
    const int cg = n0 + ((warp >> 2) << 6);
    float* crow = C + (size_t)r * N + cg;
    const float* rrow = (EP == 3) ? (res + (size_t)r * N + cg) : nullptr;
    #pragma unroll
    for (int j4 = 0; j4 < 16; j4++) {
        float4 bv = *(const float4*)(bias + cg + (j4 << 2));
        float4 o;
        o.x = __uint_as_float(dr[j4*4+0]) + bv.x;
        o.y = __uint_as_float(dr[j4*4+1]) + bv.y;
        o.z = __uint_as_float(dr[j4*4+2]) + bv.z;
        o.w = __uint_as_float(dr[j4*4+3]) + bv.w;
        if (EP == 2) {
            o.x = 0.5f * o.x * (1.0f + erff(o.x * 0.70710678118654752f));
            o.y = 0.5f * o.y * (1.0f + erff(o.y * 0.70710678118654752f));
            o.z = 0.5f * o.z * (1.0f + erff(o.z * 0.70710678118654752f));
            o.w = 0.5f * o.w * (1.0f + erff(o.w * 0.70710678118654752f));
        }
        if (EP == 3) {
            float4 rv = *(const float4*)(rrow + (j4 << 2));
            o.x += rv.x; o.y += rv.y; o.z += rv.z; o.w += rv.w;
        }
        if (RND) { o.x = tf32r(o.x); o.y = tf32r(o.y); o.z = tf32r(o.z); o.w = tf32r(o.w); }
        *(float4*)(crow + (j4 << 2)) = o;
    }
#else
    float acc[4][4][4];
    #pragma unroll
    for (int i = 0; i < 4; i++)
        #pragma unroll
        for (int j = 0; j < 4; j++)
            #pragma unroll
            for (int f = 0; f < 4; f++) acc[i][j][f] = 0.f;
    fb_core(A, W, K, m0, n0, dsm, acc);

    const int wm = (warp >> 2) * 64;
    const int wn = (warp & 3) * 32;
    const int grp = lane >> 2;
    const int qk  = lane & 3;
    #pragma unroll
    for (int mi = 0; mi < 4; mi++) {
        #pragma unroll
        for (int ni = 0; ni < 4; ni++) {
            #pragma unroll
            for (int f = 0; f < 4; f++) {
                const int r = m0 + wm + (mi << 4) + grp + ((f >> 1) << 3);
                const int c = n0 + wn + (ni << 3) + (qk << 1) + (f & 1);
                float val = acc[mi][ni][f] + bias[c];
                if (EP == 2) val = 0.5f * val * (1.0f + erff(val * 0.70710678118654752f));
                if (EP == 3) val += res[(size_t)r * N + c];
                if (RND) val = tf32r(val);
                C[(size_t)r * N + c] = val;
            }
        }
    }
#endif
}

// ---------------- fused QKV GEMM + RoPE epilogue ------------------------------
// grid (6, 64, 3): z=0 Q (scale+rope), z=1 K (rope), z=2 V (plain). All tf32-rounded.
__global__ __launch_bounds__(256, 2)
void gemm_qkv(const float* __restrict__ A, const float* __restrict__ cw,
              const float* __restrict__ bq, const float* __restrict__ bk,
              const float* __restrict__ bv, const float* __restrict__ freqs,
              float* __restrict__ q, float* __restrict__ k, float* __restrict__ v) {
    extern __shared__ char dsm[];
    const int tid  = threadIdx.x;
    const int warp = tid >> 5;
    const int lane = tid & 31;
    const int m0 = blockIdx.y << 7, n0 = blockIdx.x << 7;
    const int z  = blockIdx.z;
    const float* W    = cw + (size_t)z * CW_DD;
    const float* bias = (z == 0) ? bq : (z == 1) ? bk : bv;
    float* C          = (z == 0) ? q  : (z == 1) ? k  : v;

#if TC_OK
    uint32_t dr[64];
    tc_core(A, W, D_, m0, n0, dsm, dr);

    const int r  = m0 + ((warp & 3) << 5) + lane;
    const int cg = n0 + ((warp >> 2) << 6);
    const float n_pos = (float)(r & (N_ - 1));
    float* crow = C + (size_t)r * D_ + cg;
    #pragma unroll
    for (int j4 = 0; j4 < 16; j4++) {
        const int c4 = cg + (j4 << 2);
        float4 bvv = *(const float4*)(bias + c4);
        float4 o;
        o.x = __uint_as_float(dr[j4*4+0]) + bvv.x;
        o.y = __uint_as_float(dr[j4*4+1]) + bvv.y;
        o.z = __uint_as_float(dr[j4*4+2]) + bvv.z;
        o.w = __uint_as_float(dr[j4*4+3]) + bvv.w;
        if (z == 0) { o.x *= SCALING_; o.y *= SCALING_; o.z *= SCALING_; o.w *= SCALING_; }
        if (z < 2) {
            const int i0 = (c4 & 63) >> 1;
            float s0, c0, s1, c1;
            __sincosf(n_pos * freqs[i0],     &s0, &c0);
            __sincosf(n_pos * freqs[i0 + 1], &s1, &c1);
            float4 t = o;
            o.x = t.x * c0 - t.y * s0;
            o.y = t.y * c0 + t.x * s0;
            o.z = t.z * c1 - t.w * s1;
            o.w = t.w * c1 + t.z * s1;
        }
        o.x = tf32r(o.x); o.y = tf32r(o.y); o.z = tf32r(o.z); o.w = tf32r(o.w);
        *(float4*)(crow + (j4 << 2)) = o;
    }
#else
    float acc[4][4][4];
    #pragma unroll
    for (int i = 0; i < 4; i++)
        #pragma unroll
        for (int j = 0; j < 4; j++)
            #pragma unroll
            for (int f = 0; f < 4; f++) acc[i][j][f] = 0.f;
    fb_core(A, W, D_, m0, n0, dsm, acc);

    const int wm = (warp >> 2) * 64;
    const int wn = (warp & 3) * 32;
    const int grp = lane >> 2;
    const int qk  = lane & 3;
    #pragma unroll
    for (int mi = 0; mi < 4; mi++) {
        #pragma unroll
        for (int ni = 0; ni < 4; ni++) {
            #pragma unroll
            for (int fp = 0; fp < 2; fp++) {
                const int r = m0 + wm + (mi << 4) + grp + (fp << 3);
                const int c0 = n0 + wn + (ni << 3) + (qk << 1);
                float v0 = acc[mi][ni][fp*2+0] + bias[c0];
                float v1 = acc[mi][ni][fp*2+1] + bias[c0+1];
                if (z == 0) { v0 *= SCALING_; v1 *= SCALING_; }
                if (z < 2) {
                    const int i0 = (c0 & 63) >> 1;
                    float s0, cc0;
                    __sincosf((float)(r & (N_-1)) * freqs[i0], &s0, &cc0);
                    float t0 = v0, t1 = v1;
                    v0 = t0 * cc0 - t1 * s0;
                    v1 = t1 * cc0 + t0 * s0;
                }
                C[(size_t)r * D_ + c0]     = tf32r(v0);
                C[(size_t)r * D_ + c0 + 1] = tf32r(v1);
            }
        }
    }
#endif
}

// ---------------- flash attention, tf32 mma.sync, BQ=128 BK=32 ---------------
// 32.8KB smem, 2 CTAs/SM. K/V/mask prefetched into registers one tile ahead:
// LDG latency overlaps the PV MMAs instead of sitting on the critical path.
#define ATTN_SMEM (8192 + 8192 + 16384 + 64)
__global__ __launch_bounds__(256, 2)
void attn_tc(const float* __restrict__ q, const float* __restrict__ k,
             const float* __restrict__ v, const unsigned char* __restrict__ pm,
             float* __restrict__ out) {
    extern __shared__ char asmem[];
    unsigned* Ks = (unsigned*)asmem;               // [4][32][16]
    unsigned* Vt = (unsigned*)(asmem + 8192);      // [2][64][16]
    unsigned* Ps = (unsigned*)(asmem + 16384);     // [2][128][16]
    unsigned char* Ms = (unsigned char*)(asmem + 32768);

    const int tid = threadIdx.x, warp = tid >> 5, lane = tid & 31;
    const int grp = lane >> 2, qk = lane & 3;
    const int qt = blockIdx.x, bh = blockIdx.y;
    const int b = bh / H_, h = bh - b * H_;
    const int row0 = b * N_ + qt * 128;
    const int colh = h * HD_;
    const int rl0 = (warp << 4) + grp;
    const int rl1 = rl0 + 8;
    const int r0 = row0 + rl0;

    unsigned aq[8][4];
    {
        const float* q0 = q + (size_t)r0 * D_ + colh;
        const float* q1 = q0 + (size_t)8 * D_;
        #pragma unroll
        for (int s = 0; s < 8; s++) {
            aq[s][0] = __float_as_uint(q0[s*8 + qk]);
            aq[s][1] = __float_as_uint(q1[s*8 + qk]);
            aq[s][2] = __float_as_uint(q0[s*8 + qk + 4]);
            aq[s][3] = __float_as_uint(q1[s*8 + qk + 4]);
        }
    }

    float o_[8][4];
    #pragma unroll
    for (int nt = 0; nt < 8; nt++) { o_[nt][0]=0.f; o_[nt][1]=0.f; o_[nt][2]=0.f; o_[nt][3]=0.f; }
    float m0 = -3.0e38f, m1 = -3.0e38f, l0 = 0.f, l1 = 0.f;

    // producer: key = tid>>3 (0..31), lq8 = tid&7 -> dims 2*lq8, 2*lq8+1 per 16-chunk
    const int lkey = tid >> 3, lq8 = tid & 7;
    const int swk = (lkey >> 1) & 3;
    const int vpl = lkey >> 4, vkk = lkey & 15;
    const int swp0 = (rl0 >> 1) & 3, swp1 = (rl1 >> 1) & 3;

    // prefetch tile 0 into registers
    float2 kp[4], vp[4];
    unsigned char mpre = 0;
    {
        const size_t gb0 = (size_t)(b * N_ + lkey) * D_ + colh;
        #pragma unroll
        for (int c = 0; c < 4; c++) {
            kp[c] = *(const float2*)(k + gb0 + 16*c + 2*lq8);
            vp[c] = *(const float2*)(v + gb0 + 16*c + 2*lq8);
        }
        if (tid < 32) mpre = pm[b * N_ + tid];
    }

    for (int kt = 0; kt < N_; kt += 32) {
        __syncthreads();
        // store prefetched tile (pure STS, no LDG on critical path)
        {
            #pragma unroll
            for (int c = 0; c < 4; c++) {
                #pragma unroll
                for (int j = 0; j < 2; j++) {
                    const int d16 = 2*lq8 + j;
                    const unsigned kb = __float_as_uint(j ? kp[c].y : kp[c].x);
                    const unsigned vb = __float_as_uint(j ? vp[c].y : vp[c].x);
                    Ks[(c << 9) + (lkey << 4) + (((d16 & 3) ^ swk) << 2) + (d16 >> 2)] = kb;
                    const int d = 16*c + d16;
                    Vt[(vpl << 10) + (d << 4) + (((vkk & 3) ^ ((d >> 1) & 3)) << 2) + (vkk >> 2)] = vb;
                }
            }
            if (tid < 32) Ms[tid] = mpre;
        }
        __syncthreads();

        // S = Q K^T : per warp 16 rows x 32 keys
        float s_[4][4];
        #pragma unroll
        for (int nt = 0; nt < 4; nt++) { s_[nt][0]=0.f; s_[nt][1]=0.f; s_[nt][2]=0.f; s_[nt][3]=0.f; }
        #pragma unroll
        for (int c = 0; c < 4; c++) {
            #pragma unroll
            for (int nt = 0; nt < 4; nt++) {
                const int rn = (nt << 3) + grp;
                const uint4 Bv = *(const uint4*)(Ks + (c << 9) + (rn << 4)
                                                 + ((qk ^ ((rn >> 1) & 3)) << 2));
                mma_tf32(s_[nt][0], s_[nt][1], s_[nt][2], s_[nt][3],
                         aq[2*c][0], aq[2*c][1], aq[2*c][2], aq[2*c][3], Bv.x, Bv.y);
                mma_tf32(s_[nt][0], s_[nt][1], s_[nt][2], s_[nt][3],
                         aq[2*c+1][0], aq[2*c+1][1], aq[2*c+1][2], aq[2*c+1][3], Bv.z, Bv.w);
            }
        }

        float mx0 = -3.0e38f, mx1 = -3.0e38f;
        #pragma unroll
        for (int nt = 0; nt < 4; nt++) {
            const int c0 = (nt << 3) + (qk << 1);
            const bool k0m = Ms[c0] != 0, k1m = Ms[c0 + 1] != 0;
            s_[nt][0] = k0m ? -3.0e38f : s_[nt][0] * 0.125f;
            s_[nt][1] = k1m ? -3.0e38f : s_[nt][1] * 0.125f;
            s_[nt][2] = k0m ? -3.0e38f : s_[nt][2] * 0.125f;
            s_[nt][3] = k1m ? -3.0e38f : s_[nt][3] * 0.125f;
            mx0 = fmaxf(mx0, fmaxf(s_[nt][0], s_[nt][1]));
            mx1 = fmaxf(mx1, fmaxf(s_[nt][2], s_[nt][3]));
        }
        mx0 = fmaxf(mx0, __shfl_xor_sync(0xffffffffu, mx0, 1));
        mx0 = fmaxf(mx0, __shfl_xor_sync(0xffffffffu, mx0, 2));
        mx1 = fmaxf(mx1, __shfl_xor_sync(0xffffffffu, mx1, 1));
        mx1 = fmaxf(mx1, __shfl_xor_sync(0xffffffffu, mx1, 2));

        const float mn0 = fmaxf(m0, mx0), mn1 = fmaxf(m1, mx1);
        const float al0 = __expf(m0 - mn0), al1 = __expf(m1 - mn1);
        m0 = mn0; m1 = mn1;
        float rs0 = 0.f, rs1 = 0.f;
        #pragma unroll
        for (int nt = 0; nt < 4; nt++) {
            s_[nt][0] = __expf(s_[nt][0] - mn0);
            s_[nt][1] = __expf(s_[nt][1] - mn0);
            s_[nt][2] = __expf(s_[nt][2] - mn1);
            s_[nt][3] = __expf(s_[nt][3] - mn1);
            rs0 += s_[nt][0] + s_[nt][1];
            rs1 += s_[nt][2] + s_[nt][3];
        }
        #pragma unroll
        for (int nt = 0; nt < 8; nt++) {
            o_[nt][0] *= al0; o_[nt][1] *= al0;
            o_[nt][2] *= al1; o_[nt][3] *= al1;
        }
        rs0 += __shfl_xor_sync(0xffffffffu, rs0, 1);
        rs0 += __shfl_xor_sync(0xffffffffu, rs0, 2);
        rs1 += __shfl_xor_sync(0xffffffffu, rs1, 1);
        rs1 += __shfl_xor_sync(0xffffffffu, rs1, 2);
        l0 = l0 * al0 + rs0;
        l1 = l1 * al1 + rs1;

        #pragma unroll
        for (int nt = 0; nt < 4; nt++) {
            #pragma unroll
            for (int i2 = 0; i2 < 2; i2++) {
                const int ck = (nt << 3) + (qk << 1) + i2;
                const int pl = ck >> 4, kk = ck & 15;
                Ps[(pl << 11) + (rl0 << 4) + ((((kk & 3) ^ swp0)) << 2) + (kk >> 2)] = f2tf32(s_[nt][i2]);
                Ps[(pl << 11) + (rl1 << 4) + ((((kk & 3) ^ swp1)) << 2) + (kk >> 2)] = f2tf32(s_[nt][2 + i2]);
            }
        }

        // prefetch next tile's K/V/mask (s_ registers are dead now;
        // LDG latency overlaps the PV MMAs below + the next sync)
        if (kt + 32 < N_) {
            const size_t gbn = (size_t)(b * N_ + kt + 32 + lkey) * D_ + colh;
            #pragma unroll
            for (int c = 0; c < 4; c++) {
                kp[c] = *(const float2*)(k + gbn + 16*c + 2*lq8);
                vp[c] = *(const float2*)(v + gbn + 16*c + 2*lq8);
            }
            if (tid < 32) mpre = pm[b * N_ + kt + 32 + tid];
        }
        __syncthreads();

        // O += P V
        #pragma unroll
        for (int c = 0; c < 2; c++) {
            const uint4 Alo = *(const uint4*)(Ps + (c << 11) + (rl0 << 4) + ((qk ^ swp0) << 2));
            const uint4 Ahi = *(const uint4*)(Ps + (c << 11) + (rl1 << 4) + ((qk ^ swp1) << 2));
            #pragma unroll
            for (int nt = 0; nt < 8; nt++) {
                const int rn = (nt << 3) + grp;
                const uint4 Bv = *(const uint4*)(Vt + (c << 10) + (rn << 4)
                                                 + ((qk ^ ((rn >> 1) & 3)) << 2));
                mma_tf32(o_[nt][0], o_[nt][1], o_[nt][2], o_[nt][3],
                         Alo.x, Ahi.x, Alo.y, Ahi.y, Bv.x, Bv.y);
                mma_tf32(o_[nt][0], o_[nt][1], o_[nt][2], o_[nt][3],
                         Alo.z, Ahi.z, Alo.w, Ahi.w, Bv.z, Bv.w);
            }
        }
    }

    const float inv0 = 1.0f / l0, inv1 = 1.0f / l1;
    float* out0 = out + (size_t)r0 * D_ + colh;
    float* out1 = out0 + (size_t)8 * D_;
    #pragma unroll
    for (int nt = 0; nt < 8; nt++) {
        const int c0 = (nt << 3) + (qk << 1);
        out0[c0]     = tf32r(o_[nt][0] * inv0);
        out0[c0 + 1] = tf32r(o_[nt][1] * inv0);
        out1[c0]     = tf32r(o_[nt][2] * inv1);
        out1[c0 + 1] = tf32r(o_[nt][3] * inv1);
    }
}

// ---------------- launch ------------------------------------------------------
extern "C" void kernel_launch(void* const* d_in, const int* in_sizes, int n_in,
                              void* d_out, int out_size) {
    const float* x     = (const float*)d_in[0];
    const unsigned char* pmask = (const unsigned char*)d_in[1];
    const float* wq = (const float*)d_in[2];
    const float* bq = (const float*)d_in[3];
    const float* wk = (const float*)d_in[4];
    const float* bk = (const float*)d_in[5];
    const float* wv = (const float*)d_in[6];
    const float* bv = (const float*)d_in[7];
    const float* wo = (const float*)d_in[8];
    const float* bo = (const float*)d_in[9];
    const float* w1 = (const float*)d_in[10];
    const float* b1 = (const float*)d_in[11];
    const float* w2 = (const float*)d_in[12];
    const float* b2 = (const float*)d_in[13];
    const float* ln1w = (const float*)d_in[14];
    const float* ln1b = (const float*)d_in[15];
    const float* ln2w = (const float*)d_in[16];
    const float* ln2b = (const float*)d_in[17];
    const float* freqs = (const float*)d_in[18];
    float* out = (float*)d_out;

    float *ph, *pq, *pk, *pv, *patt, *pff, *pcw;
    cudaGetSymbolAddress((void**)&ph,   g_h);
    cudaGetSymbolAddress((void**)&pq,   g_q);
    cudaGetSymbolAddress((void**)&pk,   g_k);
    cudaGetSymbolAddress((void**)&pv,   g_v);
    cudaGetSymbolAddress((void**)&patt, g_att);
    cudaGetSymbolAddress((void**)&pff,  g_ff);
    cudaGetSymbolAddress((void**)&pcw,  g_cw);

    float* cwo = pcw + 3*CW_DD;
    float* cw1 = pcw + 4*CW_DD;
    float* cw2 = pcw + 4*CW_DD + CW_FD;

    cudaFuncSetAttribute(gemm_u<0,0>, cudaFuncAttributeMaxDynamicSharedMemorySize, GEMM_DYN_SMEM);
    cudaFuncSetAttribute(gemm_u<2,1>, cudaFuncAttributeMaxDynamicSharedMemorySize, GEMM_DYN_SMEM);
    cudaFuncSetAttribute(gemm_u<3,0>, cudaFuncAttributeMaxDynamicSharedMemorySize, GEMM_DYN_SMEM);
    cudaFuncSetAttribute(gemm_qkv,    cudaFuncAttributeMaxDynamicSharedMemorySize, GEMM_DYN_SMEM);
    cudaFuncSetAttribute(attn_tc,     cudaFuncAttributeMaxDynamicSharedMemorySize, ATTN_SMEM);

    const dim3 gD(D_ / 128, M_ / 128);        // (6, 64)
    const dim3 gQKV(D_ / 128, M_ / 128, 3);   // (6, 64, 3)
    const dim3 gF(FF_ / 128, M_ / 128);       // (24, 64)
    const int ntotal4 = (4*CW_DD + 2*CW_FD) / 4;

    // tf32-round all six weight matrices in ONE launch
    cvt_all_kernel<<<(ntotal4 + 255)/256, 256>>>(
        (const float4*)wq, (const float4*)wk, (const float4*)wv,
        (const float4*)wo, (const float4*)w1, (const float4*)w2, (float4*)pcw);

    // LN1 (tf32-rounded output)
    ln_kernel<<<M_, 256>>>(x, ln1w, ln1b, ph);
    // fused QKV projections + RoPE (one launch)
    gemm_qkv<<<gQKV, 256, GEMM_DYN_SMEM>>>(ph, pcw, bq, bk, bv, freqs, pq, pk, pv);
    // attention (BK=32, 2 CTAs/SM, register-prefetched K/V)
    attn_tc<<<dim3(N_ / 128, B_ * H_), 256, ATTN_SMEM>>>(pq, pk, pv, pmask, patt);
    // O projection + residual (x) -> d_out
    gemm_u<3,0><<<gD, 256, GEMM_DYN_SMEM>>>(patt, cwo, bo, x, out, M_, D_, D_);
    // LN2 (reuse g_h)
    ln_kernel<<<M_, 256>>>(out, ln2w, ln2b, ph);
    // FFN1 with exact GELU (rounded output feeds FFN2)
    gemm_u<2,1><<<gF, 256, GEMM_DYN_SMEM>>>(ph, cw1, b1, nullptr, pff, M_, FF_, D_);
    // FFN2 + residual (d_out) -> d_out
    gemm_u<3,0><<<gD, 256, GEMM_DYN_SMEM>>>(pff, cw2, b2, out, out, M_, D_, FF_);
}

// round 15
// speedup vs baseline: 1.5190x; 1.0489x over previous
#include <cuda_runtime.h>
#include <math.h>
#include <stdint.h>

#define D_  768
#define H_  12
#define HD_ 64
#define FF_ 3072
#define B_  8
#define N_  1024
#define M_  (B_*N_)          // 8192 rows
#define SCALING_ 0.125f      // HD^-0.5
#define EPS_ 1e-5f

#if defined(__CUDA_ARCH_FEAT_SM103_ALL) || defined(__CUDA_ARCH_FEAT_SM100_ALL) || \
    defined(__CUDA_ARCH_SPECIFIC__) || defined(__CUDA_ARCH_FAMILY_SPECIFIC__)
#define TC_OK 1
#else
#define TC_OK 0
#endif

// ---------------- scratch (static device globals; no allocation) -------------
__device__ float g_h  [M_*D_];
__device__ float g_q  [M_*D_];
__device__ float g_k  [M_*D_];
__device__ float g_v  [M_*D_];
__device__ float g_att[M_*D_];
__device__ float g_ff [M_*FF_];
#define CW_DD (D_*D_)
#define CW_FD (FF_*D_)
__device__ float g_cw [4*CW_DD + 2*CW_FD];

// ---------------- common helpers ---------------------------------------------
__device__ __forceinline__ unsigned f2tf32(float f) {
    unsigned r;
    asm("cvt.rna.tf32.f32 %0, %1;" : "=r"(r) : "f"(f));
    return r;
}
__device__ __forceinline__ float tf32r(float f) { return __uint_as_float(f2tf32(f)); }

#if TC_OK
__device__ __forceinline__ uint32_t smem_u32(const void* p) {
    uint32_t a;
    asm("{ .reg .u64 t; cvta.to.shared.u64 t, %1; cvt.u32.u64 %0, t; }" : "=r"(a) : "l"(p));
    return a;
}
__device__ __forceinline__ uint32_t elect_one() {
    uint32_t p;
    asm volatile("{ .reg .pred p; elect.sync _|p, 0xFFFFFFFF; selp.b32 %0, 1, 0, p; }" : "=r"(p));
    return p;
}
__device__ __forceinline__ void cp16(uint32_t smaddr, const void* g) {
    asm volatile("cp.async.cg.shared.global [%0], [%1], 16;" :: "r"(smaddr), "l"(g) : "memory");
}
#define CP_COMMIT() asm volatile("cp.async.commit_group;" ::: "memory")
#define TC_ALLOC(smem_addr, n) \
    asm volatile("tcgen05.alloc.cta_group::1.sync.aligned.shared::cta.b32 [%0], %1;" \
                 :: "r"(smem_addr), "r"((uint32_t)(n)) : "memory")
#define TC_RELINQ() \
    asm volatile("tcgen05.relinquish_alloc_permit.cta_group::1.sync.aligned;")
#define TC_DEALLOC(tmem, n) \
    asm volatile("tcgen05.dealloc.cta_group::1.sync.aligned.b32 %0, %1;" :: "r"(tmem), "r"((uint32_t)(n)))
#define TC_COMMIT(mbar) \
    asm volatile("tcgen05.commit.cta_group::1.mbarrier::arrive::one.shared::cluster.b64 [%0];" \
                 :: "r"(mbar) : "memory")
#define TC_FENCE_AFTER()  asm volatile("tcgen05.fence::after_thread_sync;" ::: "memory")
#define FENCE_ASYNC_SH()  asm volatile("fence.proxy.async.shared::cta;" ::: "memory")
#define MBAR_INIT(mbar, cnt) \
    asm volatile("mbarrier.init.shared.b64 [%0], %1;" :: "r"(mbar), "r"((uint32_t)(cnt)) : "memory")
#define MBAR_WAIT(mbar, ph) do {                                                  \
    asm volatile("{\n\t.reg .pred P1;\n\t"                                        \
        "WL_%=:\n\t"                                                              \
        "mbarrier.try_wait.parity.acquire.cta.shared::cta.b64 P1, [%0], %1, 0x989680;\n\t" \
        "@P1 bra.uni WD_%=;\n\t"                                                  \
        "bra.uni WL_%=;\n\t"                                                      \
        "WD_%=:\n\t}"                                                             \
        :: "r"(mbar), "r"((uint32_t)(ph)) : "memory");                            \
} while (0)
#define TC_LD_X32(r, tmem) \
    asm volatile( \
        "tcgen05.ld.sync.aligned.32x32b.x32.b32 " \
        "{%0, %1, %2, %3, %4, %5, %6, %7, " \
        " %8, %9, %10, %11, %12, %13, %14, %15, " \
        " %16, %17, %18, %19, %20, %21, %22, %23, " \
        " %24, %25, %26, %27, %28, %29, %30, %31}, [%32];" \
        : "=r"((r)[0]),  "=r"((r)[1]),  "=r"((r)[2]),  "=r"((r)[3]), \
          "=r"((r)[4]),  "=r"((r)[5]),  "=r"((r)[6]),  "=r"((r)[7]), \
          "=r"((r)[8]),  "=r"((r)[9]),  "=r"((r)[10]), "=r"((r)[11]), \
          "=r"((r)[12]), "=r"((r)[13]), "=r"((r)[14]), "=r"((r)[15]), \
          "=r"((r)[16]), "=r"((r)[17]), "=r"((r)[18]), "=r"((r)[19]), \
          "=r"((r)[20]), "=r"((r)[21]), "=r"((r)[22]), "=r"((r)[23]), \
          "=r"((r)[24]), "=r"((r)[25]), "=r"((r)[26]), "=r"((r)[27]), \
          "=r"((r)[28]), "=r"((r)[29]), "=r"((r)[30]), "=r"((r)[31]) \
        : "r"(tmem))
#define TC_WAIT_LD() asm volatile("tcgen05.wait::ld.sync.aligned;" ::: "memory")

__device__ __forceinline__ void tc_mma_tf32_ss(uint32_t d, uint64_t ad, uint64_t bd,
                                               uint32_t idesc, bool acc) {
    uint32_t e = acc ? 1u : 0u;
    asm volatile(
        "{\n\t.reg .pred p;\n\tsetp.ne.u32 p, %4, 0;\n\t"
        "tcgen05.mma.cta_group::1.kind::tf32 [%0], %1, %2, %3, {%5,%5,%5,%5}, p;\n\t}"
        :: "r"(d), "l"(ad), "l"(bd), "r"(idesc), "r"(e), "r"(0u) : "memory");
}
__device__ __forceinline__ uint64_t mk_desc(uint32_t addr) {
    const uint64_t base = (uint64_t(2) << 61) | (uint64_t(1) << 46)
                        | (uint64_t(64) << 32) | (uint64_t(1) << 16);
    return base | ((uint64_t)(addr >> 4) & 0x3FFF);
}
#define SWZ128(b) ((b) ^ (((b) >> 3) & 0x70))
#define TC_IDESC ((1u<<4)|(2u<<7)|(2u<<10)|(16u<<17)|(8u<<24))
#endif  // TC_OK

__device__ __forceinline__ void mma_tf32(float& c0, float& c1, float& c2, float& c3,
                                         unsigned a0, unsigned a1, unsigned a2, unsigned a3,
                                         unsigned b0, unsigned b1) {
    asm volatile(
        "mma.sync.aligned.m16n8k8.row.col.f32.tf32.tf32.f32 "
        "{%0,%1,%2,%3}, {%4,%5,%6,%7}, {%8,%9}, {%0,%1,%2,%3};"
        : "+f"(c0), "+f"(c1), "+f"(c2), "+f"(c3)
        : "r"(a0), "r"(a1), "r"(a2), "r"(a3), "r"(b0), "r"(b1));
}

// ---------------- one-shot tf32 rounding of all six weights (fused) ----------
__global__ __launch_bounds__(256)
void cvt_all_kernel(const float4* wq, const float4* wk, const float4* wv,
                    const float4* wo, const float4* w1, const float4* w2,
                    float4* dst) {
    const int DD4 = CW_DD/4, FD4 = CW_FD/4;
    const int total = 4*DD4 + 2*FD4;
    int i = blockIdx.x * blockDim.x + threadIdx.x;
    if (i >= total) return;
    const float4* src;
    int off;
    if (i < 4*DD4) {
        int w = i / DD4; off = i - w*DD4;
        src = (w == 0) ? wq : (w == 1) ? wk : (w == 2) ? wv : wo;
    } else {
        int j = i - 4*DD4;
        if (j < FD4) { src = w1; off = j; }
        else         { src = w2; off = j - FD4; }
    }
    float4 v = src[off];
    uint4 o;
    o.x = f2tf32(v.x); o.y = f2tf32(v.y); o.z = f2tf32(v.z); o.w = f2tf32(v.w);
    ((uint4*)dst)[i] = o;
}

// ---------------- LayerNorm (tf32-rounded output) ----------------------------
__global__ __launch_bounds__(256)
void ln_kernel(const float* __restrict__ x, const float* __restrict__ w,
               const float* __restrict__ b, float* __restrict__ out) {
    const int row = blockIdx.x;
    const int tid = threadIdx.x;
    const float* xr = x + (size_t)row * D_;
    float v[3];
    float s = 0.f;
    #pragma unroll
    for (int i = 0; i < 3; i++) { v[i] = xr[tid + i*256]; s += v[i]; }

    __shared__ float red[8];
    __shared__ float bc[2];
    #pragma unroll
    for (int o = 16; o; o >>= 1) s += __shfl_xor_sync(0xffffffffu, s, o);
    if ((tid & 31) == 0) red[tid >> 5] = s;
    __syncthreads();
    if (tid == 0) {
        float t = 0.f;
        #pragma unroll
        for (int i = 0; i < 8; i++) t += red[i];
        bc[0] = t * (1.0f / D_);
    }
    __syncthreads();
    const float mu = bc[0];

    float s2 = 0.f;
    #pragma unroll
    for (int i = 0; i < 3; i++) { float d = v[i] - mu; s2 += d * d; }
    #pragma unroll
    for (int o = 16; o; o >>= 1) s2 += __shfl_xor_sync(0xffffffffu, s2, o);
    if ((tid & 31) == 0) red[tid >> 5] = s2;
    __syncthreads();
    if (tid == 0) {
        float t = 0.f;
        #pragma unroll
        for (int i = 0; i < 8; i++) t += red[i];
        bc[1] = rsqrtf(t * (1.0f / D_) + EPS_);
    }
    __syncthreads();
    const float rstd = bc[1];

    float* orow = out + (size_t)row * D_;
    #pragma unroll
    for (int i = 0; i < 3; i++) {
        int c = tid + i*256;
        orow[c] = tf32r((v[i] - mu) * rstd * w[c] + b[c]);
    }
}

// ---------------- GEMM cores (shared by gemm_u and gemm_qkv) ------------------
#define NSTAGE 3
#define SLOT_BYTES 32768
#define GEMM_DYN_SMEM (NSTAGE*SLOT_BYTES + 1024)

#if TC_OK
__device__ __forceinline__ void tc_core(const float* __restrict__ A,
                                        const float* __restrict__ W,
                                        int K, int m0, int n0, char* dsm,
                                        uint32_t* dr) {
    __shared__ uint32_t tmem_ptr_s[1];
    __shared__ __align__(8) uint64_t mbar_s[NSTAGE];

    const int tid  = threadIdx.x;
    const int warp = tid >> 5;

    uint32_t rawb = smem_u32(dsm);
    uint32_t ab   = (rawb + 1023u) & ~1023u;
    uint32_t cbar[NSTAGE];
    #pragma unroll
    for (int j = 0; j < NSTAGE; j++) cbar[j] = smem_u32(&mbar_s[j]);

    if (warp == 0) {
        TC_ALLOC(smem_u32(tmem_ptr_s), 128);
        TC_RELINQ();
    }
    if (tid == 0) {
        #pragma unroll
        for (int j = 0; j < NSTAGE; j++) MBAR_INIT(cbar[j], 1);
    }
    __syncthreads();
    uint32_t tmem;
    asm volatile("ld.shared.b32 %0, [%1];" : "=r"(tmem) : "r"(smem_u32(tmem_ptr_s)));

    const int prow = tid >> 3;
    const int psub = tid & 7;

    const float* Ap[4];
    const float* Wp[4];
    uint32_t soff[4];
    #pragma unroll
    for (int p = 0; p < 4; p++) {
        const int r = prow + (p << 5);
        Ap[p] = A + (size_t)(m0 + r) * K + (psub << 2);
        Wp[p] = W + (size_t)(n0 + r) * K + (psub << 2);
        soff[p] = SWZ128((r << 7) | (psub << 4));
    }

    const int nst = K >> 5;

    #define ISSUE_STAGE(s)                                                   \
        do {                                                                 \
            const int _j = (s) % NSTAGE;                                     \
            const uint32_t _ab = ab + _j * SLOT_BYTES;                       \
            const uint32_t _bb = _ab + 16384;                                \
            const int _ko = (s) << 5;                                        \
            _Pragma("unroll")                                                \
            for (int p = 0; p < 4; p++) {                                    \
                cp16(_ab + soff[p], Ap[p] + _ko);                            \
                cp16(_bb + soff[p], Wp[p] + _ko);                            \
            }                                                                \
            CP_COMMIT();                                                     \
        } while (0)

    ISSUE_STAGE(0);
    ISSUE_STAGE(1);

    for (int i = 0; i < nst; i++) {
        const int pf = i + NSTAGE - 1;
        if (pf < nst) {
            if (i >= 1) MBAR_WAIT(cbar[(i - 1) % NSTAGE], ((i - 1) / NSTAGE) & 1);
            ISSUE_STAGE(pf);
            asm volatile("cp.async.wait_group 2;" ::: "memory");
        } else if (pf == nst) {
            asm volatile("cp.async.wait_group 1;" ::: "memory");
        } else {
            asm volatile("cp.async.wait_group 0;" ::: "memory");
        }
        FENCE_ASYNC_SH();
        __syncthreads();

        if (warp == 0 && elect_one()) {
            const int j = i % NSTAGE;
            const uint64_t ad = mk_desc(ab + j * SLOT_BYTES);
            const uint64_t bd = mk_desc(ab + j * SLOT_BYTES + 16384);
            #pragma unroll
            for (int kk = 0; kk < 4; kk++)
                tc_mma_tf32_ss(tmem, ad + kk*2, bd + kk*2, TC_IDESC, (i > 0) || (kk > 0));
            TC_COMMIT(cbar[j]);
        }
    }
    #undef ISSUE_STAGE

    MBAR_WAIT(cbar[(nst - 1) % NSTAGE], ((nst - 1) / NSTAGE) & 1);
    TC_FENCE_AFTER();

    const int cb = (warp >> 2) << 6;
    TC_LD_X32(dr,      tmem + cb);
    TC_LD_X32(dr + 32, tmem + cb + 32);
    TC_WAIT_LD();
    __syncthreads();
    if (warp == 0) TC_DEALLOC(tmem, 128);
}
#else
__device__ __forceinline__ void fb_core(const float* __restrict__ A,
                                        const float* __restrict__ W,
                                        int K, int m0, int n0, char* dsm,
                                        float (*acc)[4][4]) {
    typedef unsigned SmemBuf[128][16];
    SmemBuf* As = reinterpret_cast<SmemBuf*>(dsm);
    SmemBuf* Ws = reinterpret_cast<SmemBuf*>(dsm + 2 * sizeof(SmemBuf));

    const int tid  = threadIdx.x;
    const int lane = tid & 31;
    const int warp = tid >> 5;
    const int wm = (warp >> 2) * 64;
    const int wn = (warp & 3) * 32;
    const int grp = lane >> 2;
    const int qk  = lane & 3;

    const int ldr = tid >> 2;
    const int sub = tid & 3;
    const float* Ap0 = A + (size_t)(m0 + ldr) * K + (sub << 2);
    const float* Ap1 = A + (size_t)(m0 + ldr + 64) * K + (sub << 2);
    const float* Wp0 = W + (size_t)(n0 + ldr) * K + (sub << 2);
    const float* Wp1 = W + (size_t)(n0 + ldr + 64) * K + (sub << 2);
    const int sw0 = ((ldr >> 1) & 3);
    const int sw1 = (((ldr + 64) >> 1) & 3);

    const int ntiles = K >> 4;

    #define STORE_TILE(buf, a0v, a1v, w0v, w1v)                                              \
        do {                                                                                  \
            As[buf][ldr   ][((0^sw0)<<2)+sub]=__float_as_uint(a0v.x); As[buf][ldr   ][((1^sw0)<<2)+sub]=__float_as_uint(a0v.y); \
            As[buf][ldr   ][((2^sw0)<<2)+sub]=__float_as_uint(a0v.z); As[buf][ldr   ][((3^sw0)<<2)+sub]=__float_as_uint(a0v.w); \
            As[buf][ldr+64][((0^sw1)<<2)+sub]=__float_as_uint(a1v.x); As[buf][ldr+64][((1^sw1)<<2)+sub]=__float_as_uint(a1v.y); \
            As[buf][ldr+64][((2^sw1)<<2)+sub]=__float_as_uint(a1v.z); As[buf][ldr+64][((3^sw1)<<2)+sub]=__float_as_uint(a1v.w); \
            Ws[buf][ldr   ][((0^sw0)<<2)+sub]=__float_as_uint(w0v.x); Ws[buf][ldr   ][((1^sw0)<<2)+sub]=__float_as_uint(w0v.y); \
            Ws[buf][ldr   ][((2^sw0)<<2)+sub]=__float_as_uint(w0v.z); Ws[buf][ldr   ][((3^sw0)<<2)+sub]=__float_as_uint(w0v.w); \
            Ws[buf][ldr+64][((0^sw1)<<2)+sub]=__float_as_uint(w1v.x); Ws[buf][ldr+64][((1^sw1)<<2)+sub]=__float_as_uint(w1v.y); \
            Ws[buf][ldr+64][((2^sw1)<<2)+sub]=__float_as_uint(w1v.z); Ws[buf][ldr+64][((3^sw1)<<2)+sub]=__float_as_uint(w1v.w); \
        } while (0)

    {
        float4 a0 = *(const float4*)(Ap0);
        float4 a1 = *(const float4*)(Ap1);
        float4 w0 = *(const float4*)(Wp0);
        float4 w1 = *(const float4*)(Wp1);
        STORE_TILE(0, a0, a1, w0, w1);
    }
    __syncthreads();

    for (int it = 0; it < ntiles; it++) {
        const int cur = it & 1, nxt = cur ^ 1;
        float4 a0, a1, w0, w1;
        const bool have_next = (it + 1) < ntiles;
        if (have_next) {
            const int ko = (it + 1) << 4;
            a0 = *(const float4*)(Ap0 + ko);
            a1 = *(const float4*)(Ap1 + ko);
            w0 = *(const float4*)(Wp0 + ko);
            w1 = *(const float4*)(Wp1 + ko);
        }

        uint4 Bv[4];
        #pragma unroll
        for (int ni = 0; ni < 4; ni++) {
            const int rn = wn + (ni << 3) + grp;
            Bv[ni] = *(const uint4*)&Ws[cur][rn][((qk ^ ((rn >> 1) & 3)) << 2)];
        }
        #pragma unroll
        for (int mi = 0; mi < 4; mi++) {
            const int rl = wm + (mi << 4) + grp;
            const int rh = rl + 8;
            const uint4 Alo = *(const uint4*)&As[cur][rl][((qk ^ ((rl >> 1) & 3)) << 2)];
            const uint4 Ahi = *(const uint4*)&As[cur][rh][((qk ^ ((rh >> 1) & 3)) << 2)];
            #pragma unroll
            for (int ni = 0; ni < 4; ni++) {
                mma_tf32(acc[mi][ni][0], acc[mi][ni][1], acc[mi][ni][2], acc[mi][ni][3],
                         Alo.x, Ahi.x, Alo.y, Ahi.y, Bv[ni].x, Bv[ni].y);
                mma_tf32(acc[mi][ni][0], acc[mi][ni][1], acc[mi][ni][2], acc[mi][ni][3],
                         Alo.z, Ahi.z, Alo.w, Ahi.w, Bv[ni].z, Bv[ni].w);
            }
        }

        if (have_next) {
            STORE_TILE(nxt, a0, a1, w0, w1);
        }
        __syncthreads();
    }
    #undef STORE_TILE
}
#endif

// ---------------- generic GEMM: EP 0 plain / 2 GELU / 3 +res; RND tf32 -------
template<int EP, int RND>
__global__ __launch_bounds__(256, 2)
void gemm_u(const float* __restrict__ A, const float* __restrict__ W,
            const float* __restrict__ bias, const float* __restrict__ res,
            float* __restrict__ C, int M, int N, int K) {
    extern __shared__ char dsm[];
    const int tid  = threadIdx.x;
    const int warp = tid >> 5;
    const int lane = tid & 31;
    const int m0 = blockIdx.y << 7, n0 = blockIdx.x << 7;

#if TC_OK
    uint32_t dr[64];
    tc_core(A, W, K, m0, n0, dsm, dr);

    const int r  = m0 + ((warp & 3) << 5) + lane;
    const int cg = n0 + ((warp >> 2) << 6);
    float* crow = C + (size_t)r * N + cg;
    const float* rrow = (EP == 3) ? (res + (size_t)r * N + cg) : nullptr;
    #pragma unroll
    for (int j4 = 0; j4 < 16; j4++) {
        float4 bv = *(const float4*)(bias + cg + (j4 << 2));
        float4 o;
        o.x = __uint_as_float(dr[j4*4+0]) + bv.x;
        o.y = __uint_as_float(dr[j4*4+1]) + bv.y;
        o.z = __uint_as_float(dr[j4*4+2]) + bv.z;
        o.w = __uint_as_float(dr[j4*4+3]) + bv.w;
        if (EP == 2) {
            o.x = 0.5f * o.x * (1.0f + erff(o.x * 0.70710678118654752f));
            o.y = 0.5f * o.y * (1.0f + erff(o.y * 0.70710678118654752f));
            o.z = 0.5f * o.z * (1.0f + erff(o.z * 0.70710678118654752f));
            o.w = 0.5f * o.w * (1.0f + erff(o.w * 0.70710678118654752f));
        }
        if (EP == 3) {
            float4 rv = *(const float4*)(rrow + (j4 << 2));
            o.x += rv.x; o.y += rv.y; o.z += rv.z; o.w += rv.w;
        }
        if (RND) { o.x = tf32r(o.x); o.y = tf32r(o.y); o.z = tf32r(o.z); o.w = tf32r(o.w); }
        *(float4*)(crow + (j4 << 2)) = o;
    }
#else
    float acc[4][4][4];
    #pragma unroll
    for (int i = 0; i < 4; i++)
        #pragma unroll
        for (int j = 0; j < 4; j++)
            #pragma unroll
            for (int f = 0; f < 4; f++) acc[i][j][f] = 0.f;
    fb_core(A, W, K, m0, n0, dsm, acc);

    const int wm = (warp >> 2) * 64;
    const int wn = (warp & 3) * 32;
    const int grp = lane >> 2;
    const int qk  = lane & 3;
    #pragma unroll
    for (int mi = 0; mi < 4; mi++) {
        #pragma unroll
        for (int ni = 0; ni < 4; ni++) {
            #pragma unroll
            for (int f = 0; f < 4; f++) {
                const int r = m0 + wm + (mi << 4) + grp + ((f >> 1) << 3);
                const int c = n0 + wn + (ni << 3) + (qk << 1) + (f & 1);
                float val = acc[mi][ni][f] + bias[c];
                if (EP == 2) val = 0.5f * val * (1.0f + erff(val * 0.70710678118654752f));
                if (EP == 3) val += res[(size_t)r * N + c];
                if (RND) val = tf32r(val);
                C[(size_t)r * N + c] = val;
            }
        }
    }
#endif
}

// ---------------- fused QKV GEMM + RoPE epilogue ------------------------------
// grid (6, 64, 3): z=0 Q (scale+rope), z=1 K (rope), z=2 V (plain). All tf32-rounded.
__global__ __launch_bounds__(256, 2)
void gemm_qkv(const float* __restrict__ A, const float* __restrict__ cw,
              const float* __restrict__ bq, const float* __restrict__ bk,
              const float* __restrict__ bv, const float* __restrict__ freqs,
              float* __restrict__ q, float* __restrict__ k, float* __restrict__ v) {
    extern __shared__ char dsm[];
    const int tid  = threadIdx.x;
    const int warp = tid >> 5;
    const int lane = tid & 31;
    const int m0 = blockIdx.y << 7, n0 = blockIdx.x << 7;
    const int z  = blockIdx.z;
    const float* W    = cw + (size_t)z * CW_DD;
    const float* bias = (z == 0) ? bq : (z == 1) ? bk : bv;
    float* C          = (z == 0) ? q  : (z == 1) ? k  : v;

#if TC_OK
    uint32_t dr[64];
    tc_core(A, W, D_, m0, n0, dsm, dr);

    const int r  = m0 + ((warp & 3) << 5) + lane;
    const int cg = n0 + ((warp >> 2) << 6);
    const float n_pos = (float)(r & (N_ - 1));
    float* crow = C + (size_t)r * D_ + cg;
    #pragma unroll
    for (int j4 = 0; j4 < 16; j4++) {
        const int c4 = cg + (j4 << 2);
        float4 bvv = *(const float4*)(bias + c4);
        float4 o;
        o.x = __uint_as_float(dr[j4*4+0]) + bvv.x;
        o.y = __uint_as_float(dr[j4*4+1]) + bvv.y;
        o.z = __uint_as_float(dr[j4*4+2]) + bvv.z;
        o.w = __uint_as_float(dr[j4*4+3]) + bvv.w;
        if (z == 0) { o.x *= SCALING_; o.y *= SCALING_; o.z *= SCALING_; o.w *= SCALING_; }
        if (z < 2) {
            const int i0 = (c4 & 63) >> 1;
            float s0, c0, s1, c1;
            __sincosf(n_pos * freqs[i0],     &s0, &c0);
            __sincosf(n_pos * freqs[i0 + 1], &s1, &c1);
            float4 t = o;
            o.x = t.x * c0 - t.y * s0;
            o.y = t.y * c0 + t.x * s0;
            o.z = t.z * c1 - t.w * s1;
            o.w = t.w * c1 + t.z * s1;
        }
        o.x = tf32r(o.x); o.y = tf32r(o.y); o.z = tf32r(o.z); o.w = tf32r(o.w);
        *(float4*)(crow + (j4 << 2)) = o;
    }
#else
    float acc[4][4][4];
    #pragma unroll
    for (int i = 0; i < 4; i++)
        #pragma unroll
        for (int j = 0; j < 4; j++)
            #pragma unroll
            for (int f = 0; f < 4; f++) acc[i][j][f] = 0.f;
    fb_core(A, W, D_, m0, n0, dsm, acc);

    const int wm = (warp >> 2) * 64;
    const int wn = (warp & 3) * 32;
    const int grp = lane >> 2;
    const int qk  = lane & 3;
    #pragma unroll
    for (int mi = 0; mi < 4; mi++) {
        #pragma unroll
        for (int ni = 0; ni < 4; ni++) {
            #pragma unroll
            for (int fp = 0; fp < 2; fp++) {
                const int r = m0 + wm + (mi << 4) + grp + (fp << 3);
                const int c0 = n0 + wn + (ni << 3) + (qk << 1);
                float v0 = acc[mi][ni][fp*2+0] + bias[c0];
                float v1 = acc[mi][ni][fp*2+1] + bias[c0+1];
                if (z == 0) { v0 *= SCALING_; v1 *= SCALING_; }
                if (z < 2) {
                    const int i0 = (c0 & 63) >> 1;
                    float s0, cc0;
                    __sincosf((float)(r & (N_-1)) * freqs[i0], &s0, &cc0);
                    float t0 = v0, t1 = v1;
                    v0 = t0 * cc0 - t1 * s0;
                    v1 = t1 * cc0 + t0 * s0;
                }
                C[(size_t)r * D_ + c0]     = tf32r(v0);
                C[(size_t)r * D_ + c0 + 1] = tf32r(v1);
            }
        }
    }
#endif
}

// ---------------- flash attention, tf32 mma.sync, BQ=128 BK=32 ---------------
// P never touches smem: C-layout -> A-layout conversion via warp shuffles
// (P is warp-local). Smem: Ks[4][32][16] + Vt[2][64][16] + mask = 16.4KB.
#define ATTN_SMEM (8192 + 8192 + 64)
__global__ __launch_bounds__(256, 2)
void attn_tc(const float* __restrict__ q, const float* __restrict__ k,
             const float* __restrict__ v, const unsigned char* __restrict__ pm,
             float* __restrict__ out) {
    extern __shared__ char asmem[];
    unsigned* Ks = (unsigned*)asmem;               // [4][32][16]
    unsigned* Vt = (unsigned*)(asmem + 8192);      // [2][64][16]
    unsigned char* Ms = (unsigned char*)(asmem + 16384);

    const int tid = threadIdx.x, warp = tid >> 5, lane = tid & 31;
    const int grp = lane >> 2, qk = lane & 3;
    const int qt = blockIdx.x, bh = blockIdx.y;
    const int b = bh / H_, h = bh - b * H_;
    const int row0 = b * N_ + qt * 128;
    const int colh = h * HD_;
    const int rl0 = (warp << 4) + grp;
    const int r0 = row0 + rl0;

    unsigned aq[8][4];
    {
        const float* q0 = q + (size_t)r0 * D_ + colh;
        const float* q1 = q0 + (size_t)8 * D_;
        #pragma unroll
        for (int s = 0; s < 8; s++) {
            aq[s][0] = __float_as_uint(q0[s*8 + qk]);
            aq[s][1] = __float_as_uint(q1[s*8 + qk]);
            aq[s][2] = __float_as_uint(q0[s*8 + qk + 4]);
            aq[s][3] = __float_as_uint(q1[s*8 + qk + 4]);
        }
    }

    float o_[8][4];
    #pragma unroll
    for (int nt = 0; nt < 8; nt++) { o_[nt][0]=0.f; o_[nt][1]=0.f; o_[nt][2]=0.f; o_[nt][3]=0.f; }
    float m0 = -3.0e38f, m1 = -3.0e38f, l0 = 0.f, l1 = 0.f;

    // producer: key = tid>>3 (0..31), lq8 = tid&7 -> dims 2*lq8, 2*lq8+1 per 16-chunk
    const int lkey = tid >> 3, lq8 = tid & 7;
    const int swk = (lkey >> 1) & 3;
    const int vpl = lkey >> 4, vkk = lkey & 15;

    for (int kt = 0; kt < N_; kt += 32) {
        __syncthreads();
        {
            const size_t gbase = (size_t)(b * N_ + kt + lkey) * D_ + colh;
            #pragma unroll
            for (int c = 0; c < 4; c++) {
                const float2 k2 = *(const float2*)(k + gbase + 16*c + 2*lq8);
                const float2 v2 = *(const float2*)(v + gbase + 16*c + 2*lq8);
                #pragma unroll
                for (int j = 0; j < 2; j++) {
                    const int d16 = 2*lq8 + j;
                    const unsigned kb = __float_as_uint(j ? k2.y : k2.x);
                    const unsigned vb = __float_as_uint(j ? v2.y : v2.x);
                    Ks[(c << 9) + (lkey << 4) + (((d16 & 3) ^ swk) << 2) + (d16 >> 2)] = kb;
                    const int d = 16*c + d16;
                    Vt[(vpl << 10) + (d << 4) + (((vkk & 3) ^ ((d >> 1) & 3)) << 2) + (vkk >> 2)] = vb;
                }
            }
            if (tid < 32) Ms[tid] = pm[b * N_ + kt + tid];
        }
        __syncthreads();

        // S = Q K^T : per warp 16 rows x 32 keys
        float s_[4][4];
        #pragma unroll
        for (int nt = 0; nt < 4; nt++) { s_[nt][0]=0.f; s_[nt][1]=0.f; s_[nt][2]=0.f; s_[nt][3]=0.f; }
        #pragma unroll
        for (int c = 0; c < 4; c++) {
            #pragma unroll
            for (int nt = 0; nt < 4; nt++) {
                const int rn = (nt << 3) + grp;
                const uint4 Bv = *(const uint4*)(Ks + (c << 9) + (rn << 4)
                                                 + ((qk ^ ((rn >> 1) & 3)) << 2));
                mma_tf32(s_[nt][0], s_[nt][1], s_[nt][2], s_[nt][3],
                         aq[2*c][0], aq[2*c][1], aq[2*c][2], aq[2*c][3], Bv.x, Bv.y);
                mma_tf32(s_[nt][0], s_[nt][1], s_[nt][2], s_[nt][3],
                         aq[2*c+1][0], aq[2*c+1][1], aq[2*c+1][2], aq[2*c+1][3], Bv.z, Bv.w);
            }
        }

        float mx0 = -3.0e38f, mx1 = -3.0e38f;
        #pragma unroll
        for (int nt = 0; nt < 4; nt++) {
            const int c0 = (nt << 3) + (qk << 1);
            const bool k0m = Ms[c0] != 0, k1m = Ms[c0 + 1] != 0;
            s_[nt][0] = k0m ? -3.0e38f : s_[nt][0] * 0.125f;
            s_[nt][1] = k1m ? -3.0e38f : s_[nt][1] * 0.125f;
            s_[nt][2] = k0m ? -3.0e38f : s_[nt][2] * 0.125f;
            s_[nt][3] = k1m ? -3.0e38f : s_[nt][3] * 0.125f;
            mx0 = fmaxf(mx0, fmaxf(s_[nt][0], s_[nt][1]));
            mx1 = fmaxf(mx1, fmaxf(s_[nt][2], s_[nt][3]));
        }
        mx0 = fmaxf(mx0, __shfl_xor_sync(0xffffffffu, mx0, 1));
        mx0 = fmaxf(mx0, __shfl_xor_sync(0xffffffffu, mx0, 2));
        mx1 = fmaxf(mx1, __shfl_xor_sync(0xffffffffu, mx1, 1));
        mx1 = fmaxf(mx1, __shfl_xor_sync(0xffffffffu, mx1, 2));

        const float mn0 = fmaxf(m0, mx0), mn1 = fmaxf(m1, mx1);
        const float al0 = __expf(m0 - mn0), al1 = __expf(m1 - mn1);
        m0 = mn0; m1 = mn1;
        float rs0 = 0.f, rs1 = 0.f;
        #pragma unroll
        for (int nt = 0; nt < 4; nt++) {
            s_[nt][0] = __expf(s_[nt][0] - mn0);
            s_[nt][1] = __expf(s_[nt][1] - mn0);
            s_[nt][2] = __expf(s_[nt][2] - mn1);
            s_[nt][3] = __expf(s_[nt][3] - mn1);
            rs0 += s_[nt][0] + s_[nt][1];
            rs1 += s_[nt][2] + s_[nt][3];
        }
        #pragma unroll
        for (int nt = 0; nt < 8; nt++) {
            o_[nt][0] *= al0; o_[nt][1] *= al0;
            o_[nt][2] *= al1; o_[nt][3] *= al1;
        }
        rs0 += __shfl_xor_sync(0xffffffffu, rs0, 1);
        rs0 += __shfl_xor_sync(0xffffffffu, rs0, 2);
        rs1 += __shfl_xor_sync(0xffffffffu, rs1, 1);
        rs1 += __shfl_xor_sync(0xffffffffu, rs1, 2);
        l0 = l0 * al0 + rs0;
        l1 = l1 * al1 + rs1;

        // C-layout -> A-layout via warp shuffles (P is warp-local; no smem).
        // Chunk s (keys 8s..8s+7): a0=(rl0, 8s+qk) a1=(rl1, 8s+qk)
        //                          a2=(rl0, 8s+qk+4) a3=(rl1, 8s+qk+4)
        // owner of col j in chunk s: lane grp*4 + (j>>1), register (j&1)/(2+(j&1))
        unsigned Af[4][4];
        {
            const int lsrc0 = (grp << 2) + (qk >> 1);      // for cols qk
            const int lsrc1 = lsrc0 + 2;                   // for cols qk+4
            const bool odd = (qk & 1) != 0;
            #pragma unroll
            for (int s = 0; s < 4; s++) {
                const float w00 = __shfl_sync(0xffffffffu, s_[s][0], lsrc0);
                const float w01 = __shfl_sync(0xffffffffu, s_[s][1], lsrc0);
                const float w02 = __shfl_sync(0xffffffffu, s_[s][2], lsrc0);
                const float w03 = __shfl_sync(0xffffffffu, s_[s][3], lsrc0);
                const float w10 = __shfl_sync(0xffffffffu, s_[s][0], lsrc1);
                const float w11 = __shfl_sync(0xffffffffu, s_[s][1], lsrc1);
                const float w12 = __shfl_sync(0xffffffffu, s_[s][2], lsrc1);
                const float w13 = __shfl_sync(0xffffffffu, s_[s][3], lsrc1);
                Af[s][0] = f2tf32(odd ? w01 : w00);   // (rl0, 8s+qk)
                Af[s][1] = f2tf32(odd ? w03 : w02);   // (rl1, 8s+qk)
                Af[s][2] = f2tf32(odd ? w11 : w10);   // (rl0, 8s+qk+4)
                Af[s][3] = f2tf32(odd ? w13 : w12);   // (rl1, 8s+qk+4)
            }
        }

        // O += P V  (Vt plane c covers keys 16c..16c+15 = chunks 2c, 2c+1)
        #pragma unroll
        for (int c = 0; c < 2; c++) {
            #pragma unroll
            for (int nt = 0; nt < 8; nt++) {
                const int rn = (nt << 3) + grp;
                const uint4 Bv = *(const uint4*)(Vt + (c << 10) + (rn << 4)
                                                 + ((qk ^ ((rn >> 1) & 3)) << 2));
                mma_tf32(o_[nt][0], o_[nt][1], o_[nt][2], o_[nt][3],
                         Af[2*c][0], Af[2*c][1], Af[2*c][2], Af[2*c][3], Bv.x, Bv.y);
                mma_tf32(o_[nt][0], o_[nt][1], o_[nt][2], o_[nt][3],
                         Af[2*c+1][0], Af[2*c+1][1], Af[2*c+1][2], Af[2*c+1][3], Bv.z, Bv.w);
            }
        }
    }

    const float inv0 = 1.0f / l0, inv1 = 1.0f / l1;
    float* out0 = out + (size_t)r0 * D_ + colh;
    float* out1 = out0 + (size_t)8 * D_;
    #pragma unroll
    for (int nt = 0; nt < 8; nt++) {
        const int c0 = (nt << 3) + (qk << 1);
        out0[c0]     = tf32r(o_[nt][0] * inv0);
        out0[c0 + 1] = tf32r(o_[nt][1] * inv0);
        out1[c0]     = tf32r(o_[nt][2] * inv1);
        out1[c0 + 1] = tf32r(o_[nt][3] * inv1);
    }
}

// ---------------- launch ------------------------------------------------------
extern "C" void kernel_launch(void* const* d_in, const int* in_sizes, int n_in,
                              void* d_out, int out_size) {
    const float* x     = (const float*)d_in[0];
    const unsigned char* pmask = (const unsigned char*)d_in[1];
    const float* wq = (const float*)d_in[2];
    const float* bq = (const float*)d_in[3];
    const float* wk = (const float*)d_in[4];
    const float* bk = (const float*)d_in[5];
    const float* wv = (const float*)d_in[6];
    const float* bv = (const float*)d_in[7];
    const float* wo = (const float*)d_in[8];
    const float* bo = (const float*)d_in[9];
    const float* w1 = (const float*)d_in[10];
    const float* b1 = (const float*)d_in[11];
    const float* w2 = (const float*)d_in[12];
    const float* b2 = (const float*)d_in[13];
    const float* ln1w = (const float*)d_in[14];
    const float* ln1b = (const float*)d_in[15];
    const float* ln2w = (const float*)d_in[16];
    const float* ln2b = (const float*)d_in[17];
    const float* freqs = (const float*)d_in[18];
    float* out = (float*)d_out;

    float *ph, *pq, *pk, *pv, *patt, *pff, *pcw;
    cudaGetSymbolAddress((void**)&ph,   g_h);
    cudaGetSymbolAddress((void**)&pq,   g_q);
    cudaGetSymbolAddress((void**)&pk,   g_k);
    cudaGetSymbolAddress((void**)&pv,   g_v);
    cudaGetSymbolAddress((void**)&patt, g_att);
    cudaGetSymbolAddress((void**)&pff,  g_ff);
    cudaGetSymbolAddress((void**)&pcw,  g_cw);

    float* cwo = pcw + 3*CW_DD;
    float* cw1 = pcw + 4*CW_DD;
    float* cw2 = pcw + 4*CW_DD + CW_FD;

    cudaFuncSetAttribute(gemm_u<0,0>, cudaFuncAttributeMaxDynamicSharedMemorySize, GEMM_DYN_SMEM);
    cudaFuncSetAttribute(gemm_u<2,1>, cudaFuncAttributeMaxDynamicSharedMemorySize, GEMM_DYN_SMEM);
    cudaFuncSetAttribute(gemm_u<3,0>, cudaFuncAttributeMaxDynamicSharedMemorySize, GEMM_DYN_SMEM);
    cudaFuncSetAttribute(gemm_qkv,    cudaFuncAttributeMaxDynamicSharedMemorySize, GEMM_DYN_SMEM);
    cudaFuncSetAttribute(attn_tc,     cudaFuncAttributeMaxDynamicSharedMemorySize, ATTN_SMEM);

    const dim3 gD(D_ / 128, M_ / 128);        // (6, 64)
    const dim3 gQKV(D_ / 128, M_ / 128, 3);   // (6, 64, 3)
    const dim3 gF(FF_ / 128, M_ / 128);       // (24, 64)
    const int ntotal4 = (4*CW_DD + 2*CW_FD) / 4;

    // tf32-round all six weight matrices in ONE launch
    cvt_all_kernel<<<(ntotal4 + 255)/256, 256>>>(
        (const float4*)wq, (const float4*)wk, (const float4*)wv,
        (const float4*)wo, (const float4*)w1, (const float4*)w2, (float4*)pcw);

    // LN1 (tf32-rounded output)
    ln_kernel<<<M_, 256>>>(x, ln1w, ln1b, ph);
    // fused QKV projections + RoPE (one launch)
    gemm_qkv<<<gQKV, 256, GEMM_DYN_SMEM>>>(ph, pcw, bq, bk, bv, freqs, pq, pk, pv);
    // attention (BK=32, shuffle-based P exchange, no Ps smem)
    attn_tc<<<dim3(N_ / 128, B_ * H_), 256, ATTN_SMEM>>>(pq, pk, pv, pmask, patt);
    // O projection + residual (x) -> d_out
    gemm_u<3,0><<<gD, 256, GEMM_DYN_SMEM>>>(patt, cwo, bo, x, out, M_, D_, D_);
    // LN2 (reuse g_h)
    ln_kernel<<<M_, 256>>>(out, ln2w, ln2b, ph);
    // FFN1 with exact GELU (rounded output feeds FFN2)
    gemm_u<2,1><<<gF, 256, GEMM_DYN_SMEM>>>(ph, cw1, b1, nullptr, pff, M_, FF_, D_);
    // FFN2 + residual (d_out) -> d_out
    gemm_u<3,0><<<gD, 256, GEMM_DYN_SMEM>>>(pff, cw2, b2, out, out, M_, D_, FF_);
}

// round 16
// speedup vs baseline: 1.7633x; 1.1608x over previous
#include <cuda_runtime.h>
#include <cuda_fp16.h>
#include <math.h>
#include <stdint.h>

#define D_  768
#define H_  12
#define HD_ 64
#define FF_ 3072
#define B_  8
#define N_  1024
#define M_  (B_*N_)          // 8192 rows
#define SCALING_ 0.125f      // HD^-0.5
#define EPS_ 1e-5f

#if defined(__CUDA_ARCH_FEAT_SM103_ALL) || defined(__CUDA_ARCH_FEAT_SM100_ALL) || \
    defined(__CUDA_ARCH_SPECIFIC__) || defined(__CUDA_ARCH_FAMILY_SPECIFIC__)
#define TC_OK 1
#else
#define TC_OK 0
#endif

// ---------------- scratch (static device globals; no allocation) -------------
__device__ float g_h  [M_*D_];
__device__ float g_q  [M_*D_];
__device__ float g_k  [M_*D_];
__device__ float g_v  [M_*D_];
__device__ float g_att[M_*D_];
__device__ float g_ff [M_*FF_];
#define CW_DD (D_*D_)
#define CW_FD (FF_*D_)
__device__ float g_cw [4*CW_DD + 2*CW_FD];

// ---------------- common helpers ---------------------------------------------
__device__ __forceinline__ unsigned f2tf32(float f) {
    unsigned r;
    asm("cvt.rna.tf32.f32 %0, %1;" : "=r"(r) : "f"(f));
    return r;
}
__device__ __forceinline__ float tf32r(float f) { return __uint_as_float(f2tf32(f)); }
__device__ __forceinline__ unsigned h2pack(float lo, float hi) {
    __half2 h = __floats2half2_rn(lo, hi);
    return *reinterpret_cast<unsigned*>(&h);
}

#if TC_OK
__device__ __forceinline__ uint32_t smem_u32(const void* p) {
    uint32_t a;
    asm("{ .reg .u64 t; cvta.to.shared.u64 t, %1; cvt.u32.u64 %0, t; }" : "=r"(a) : "l"(p));
    return a;
}
__device__ __forceinline__ uint32_t elect_one() {
    uint32_t p;
    asm volatile("{ .reg .pred p; elect.sync _|p, 0xFFFFFFFF; selp.b32 %0, 1, 0, p; }" : "=r"(p));
    return p;
}
__device__ __forceinline__ void cp16(uint32_t smaddr, const void* g) {
    asm volatile("cp.async.cg.shared.global [%0], [%1], 16;" :: "r"(smaddr), "l"(g) : "memory");
}
#define CP_COMMIT() asm volatile("cp.async.commit_group;" ::: "memory")
#define TC_ALLOC(smem_addr, n) \
    asm volatile("tcgen05.alloc.cta_group::1.sync.aligned.shared::cta.b32 [%0], %1;" \
                 :: "r"(smem_addr), "r"((uint32_t)(n)) : "memory")
#define TC_RELINQ() \
    asm volatile("tcgen05.relinquish_alloc_permit.cta_group::1.sync.aligned;")
#define TC_DEALLOC(tmem, n) \
    asm volatile("tcgen05.dealloc.cta_group::1.sync.aligned.b32 %0, %1;" :: "r"(tmem), "r"((uint32_t)(n)))
#define TC_COMMIT(mbar) \
    asm volatile("tcgen05.commit.cta_group::1.mbarrier::arrive::one.shared::cluster.b64 [%0];" \
                 :: "r"(mbar) : "memory")
#define TC_FENCE_AFTER()  asm volatile("tcgen05.fence::after_thread_sync;" ::: "memory")
#define FENCE_ASYNC_SH()  asm volatile("fence.proxy.async.shared::cta;" ::: "memory")
#define MBAR_INIT(mbar, cnt) \
    asm volatile("mbarrier.init.shared.b64 [%0], %1;" :: "r"(mbar), "r"((uint32_t)(cnt)) : "memory")
#define MBAR_WAIT(mbar, ph) do {                                                  \
    asm volatile("{\n\t.reg .pred P1;\n\t"                                        \
        "WL_%=:\n\t"                                                              \
        "mbarrier.try_wait.parity.acquire.cta.shared::cta.b64 P1, [%0], %1, 0x989680;\n\t" \
        "@P1 bra.uni WD_%=;\n\t"                                                  \
        "bra.uni WL_%=;\n\t"                                                      \
        "WD_%=:\n\t}"                                                             \
        :: "r"(mbar), "r"((uint32_t)(ph)) : "memory");                            \
} while (0)
#define TC_LD_X32(r, tmem) \
    asm volatile( \
        "tcgen05.ld.sync.aligned.32x32b.x32.b32 " \
        "{%0, %1, %2, %3, %4, %5, %6, %7, " \
        " %8, %9, %10, %11, %12, %13, %14, %15, " \
        " %16, %17, %18, %19, %20, %21, %22, %23, " \
        " %24, %25, %26, %27, %28, %29, %30, %31}, [%32];" \
        : "=r"((r)[0]),  "=r"((r)[1]),  "=r"((r)[2]),  "=r"((r)[3]), \
          "=r"((r)[4]),  "=r"((r)[5]),  "=r"((r)[6]),  "=r"((r)[7]), \
          "=r"((r)[8]),  "=r"((r)[9]),  "=r"((r)[10]), "=r"((r)[11]), \
          "=r"((r)[12]), "=r"((r)[13]), "=r"((r)[14]), "=r"((r)[15]), \
          "=r"((r)[16]), "=r"((r)[17]), "=r"((r)[18]), "=r"((r)[19]), \
          "=r"((r)[20]), "=r"((r)[21]), "=r"((r)[22]), "=r"((r)[23]), \
          "=r"((r)[24]), "=r"((r)[25]), "=r"((r)[26]), "=r"((r)[27]), \
          "=r"((r)[28]), "=r"((r)[29]), "=r"((r)[30]), "=r"((r)[31]) \
        : "r"(tmem))
#define TC_WAIT_LD() asm volatile("tcgen05.wait::ld.sync.aligned;" ::: "memory")

__device__ __forceinline__ void tc_mma_tf32_ss(uint32_t d, uint64_t ad, uint64_t bd,
                                               uint32_t idesc, bool acc) {
    uint32_t e = acc ? 1u : 0u;
    asm volatile(
        "{\n\t.reg .pred p;\n\tsetp.ne.u32 p, %4, 0;\n\t"
        "tcgen05.mma.cta_group::1.kind::tf32 [%0], %1, %2, %3, {%5,%5,%5,%5}, p;\n\t}"
        :: "r"(d), "l"(ad), "l"(bd), "r"(idesc), "r"(e), "r"(0u) : "memory");
}
__device__ __forceinline__ uint64_t mk_desc(uint32_t addr) {
    const uint64_t base = (uint64_t(2) << 61) | (uint64_t(1) << 46)
                        | (uint64_t(64) << 32) | (uint64_t(1) << 16);
    return base | ((uint64_t)(addr >> 4) & 0x3FFF);
}
#define SWZ128(b) ((b) ^ (((b) >> 3) & 0x70))
#define TC_IDESC ((1u<<4)|(2u<<7)|(2u<<10)|(16u<<17)|(8u<<24))
#endif  // TC_OK

__device__ __forceinline__ void mma_tf32(float& c0, float& c1, float& c2, float& c3,
                                         unsigned a0, unsigned a1, unsigned a2, unsigned a3,
                                         unsigned b0, unsigned b1) {
    asm volatile(
        "mma.sync.aligned.m16n8k8.row.col.f32.tf32.tf32.f32 "
        "{%0,%1,%2,%3}, {%4,%5,%6,%7}, {%8,%9}, {%0,%1,%2,%3};"
        : "+f"(c0), "+f"(c1), "+f"(c2), "+f"(c3)
        : "r"(a0), "r"(a1), "r"(a2), "r"(a3), "r"(b0), "r"(b1));
}
__device__ __forceinline__ void mma_f16(float& c0, float& c1, float& c2, float& c3,
                                        unsigned a0, unsigned a1, unsigned a2, unsigned a3,
                                        unsigned b0, unsigned b1) {
    asm volatile(
        "mma.sync.aligned.m16n8k16.row.col.f32.f16.f16.f32 "
        "{%0,%1,%2,%3}, {%4,%5,%6,%7}, {%8,%9}, {%0,%1,%2,%3};"
        : "+f"(c0), "+f"(c1), "+f"(c2), "+f"(c3)
        : "r"(a0), "r"(a1), "r"(a2), "r"(a3), "r"(b0), "r"(b1));
}

// ---------------- one-shot tf32 rounding of all six weights (fused) ----------
__global__ __launch_bounds__(256)
void cvt_all_kernel(const float4* wq, const float4* wk, const float4* wv,
                    const float4* wo, const float4* w1, const float4* w2,
                    float4* dst) {
    const int DD4 = CW_DD/4, FD4 = CW_FD/4;
    const int total = 4*DD4 + 2*FD4;
    int i = blockIdx.x * blockDim.x + threadIdx.x;
    if (i >= total) return;
    const float4* src;
    int off;
    if (i < 4*DD4) {
        int w = i / DD4; off = i - w*DD4;
        src = (w == 0) ? wq : (w == 1) ? wk : (w == 2) ? wv : wo;
    } else {
        int j = i - 4*DD4;
        if (j < FD4) { src = w1; off = j; }
        else         { src = w2; off = j - FD4; }
    }
    float4 v = src[off];
    uint4 o;
    o.x = f2tf32(v.x); o.y = f2tf32(v.y); o.z = f2tf32(v.z); o.w = f2tf32(v.w);
    ((uint4*)dst)[i] = o;
}

// ---------------- LayerNorm (tf32-rounded output) ----------------------------
__global__ __launch_bounds__(256)
void ln_kernel(const float* __restrict__ x, const float* __restrict__ w,
               const float* __restrict__ b, float* __restrict__ out) {
    const int row = blockIdx.x;
    const int tid = threadIdx.x;
    const float* xr = x + (size_t)row * D_;
    float v[3];
    float s = 0.f;
    #pragma unroll
    for (int i = 0; i < 3; i++) { v[i] = xr[tid + i*256]; s += v[i]; }

    __shared__ float red[8];
    __shared__ float bc[2];
    #pragma unroll
    for (int o = 16; o; o >>= 1) s += __shfl_xor_sync(0xffffffffu, s, o);
    if ((tid & 31) == 0) red[tid >> 5] = s;
    __syncthreads();
    if (tid == 0) {
        float t = 0.f;
        #pragma unroll
        for (int i = 0; i < 8; i++) t += red[i];
        bc[0] = t * (1.0f / D_);
    }
    __syncthreads();
    const float mu = bc[0];

    float s2 = 0.f;
    #pragma unroll
    for (int i = 0; i < 3; i++) { float d = v[i] - mu; s2 += d * d; }
    #pragma unroll
    for (int o = 16; o; o >>= 1) s2 += __shfl_xor_sync(0xffffffffu, s2, o);
    if ((tid & 31) == 0) red[tid >> 5] = s2;
    __syncthreads();
    if (tid == 0) {
        float t = 0.f;
        #pragma unroll
        for (int i = 0; i < 8; i++) t += red[i];
        bc[1] = rsqrtf(t * (1.0f / D_) + EPS_);
    }
    __syncthreads();
    const float rstd = bc[1];

    float* orow = out + (size_t)row * D_;
    #pragma unroll
    for (int i = 0; i < 3; i++) {
        int c = tid + i*256;
        orow[c] = tf32r((v[i] - mu) * rstd * w[c] + b[c]);
    }
}

// ---------------- GEMM cores (shared by gemm_u and gemm_qkv) ------------------
#define NSTAGE 3
#define SLOT_BYTES 32768
#define GEMM_DYN_SMEM (NSTAGE*SLOT_BYTES + 1024)

#if TC_OK
__device__ __forceinline__ void tc_core(const float* __restrict__ A,
                                        const float* __restrict__ W,
                                        int K, int m0, int n0, char* dsm,
                                        uint32_t* dr) {
    __shared__ uint32_t tmem_ptr_s[1];
    __shared__ __align__(8) uint64_t mbar_s[NSTAGE];

    const int tid  = threadIdx.x;
    const int warp = tid >> 5;

    uint32_t rawb = smem_u32(dsm);
    uint32_t ab   = (rawb + 1023u) & ~1023u;
    uint32_t cbar[NSTAGE];
    #pragma unroll
    for (int j = 0; j < NSTAGE; j++) cbar[j] = smem_u32(&mbar_s[j]);

    if (warp == 0) {
        TC_ALLOC(smem_u32(tmem_ptr_s), 128);
        TC_RELINQ();
    }
    if (tid == 0) {
        #pragma unroll
        for (int j = 0; j < NSTAGE; j++) MBAR_INIT(cbar[j], 1);
    }
    __syncthreads();
    uint32_t tmem;
    asm volatile("ld.shared.b32 %0, [%1];" : "=r"(tmem) : "r"(smem_u32(tmem_ptr_s)));

    const int prow = tid >> 3;
    const int psub = tid & 7;

    const float* Ap[4];
    const float* Wp[4];
    uint32_t soff[4];
    #pragma unroll
    for (int p = 0; p < 4; p++) {
        const int r = prow + (p << 5);
        Ap[p] = A + (size_t)(m0 + r) * K + (psub << 2);
        Wp[p] = W + (size_t)(n0 + r) * K + (psub << 2);
        soff[p] = SWZ128((r << 7) | (psub << 4));
    }

    const int nst = K >> 5;

    #define ISSUE_STAGE(s)                                                   \
        do {                                                                 \
            const int _j = (s) % NSTAGE;                                     \
            const uint32_t _ab = ab + _j * SLOT_BYTES;                       \
            const uint32_t _bb = _ab + 16384;                                \
            const int _ko = (s) << 5;                                        \
            _Pragma("unroll")                                                \
            for (int p = 0; p < 4; p++) {                                    \
                cp16(_ab + soff[p], Ap[p] + _ko);                            \
                cp16(_bb + soff[p], Wp[p] + _ko);                            \
            }                                                                \
            CP_COMMIT();                                                     \
        } while (0)

    ISSUE_STAGE(0);
    ISSUE_STAGE(1);

    for (int i = 0; i < nst; i++) {
        const int pf = i + NSTAGE - 1;
        if (pf < nst) {
            if (i >= 1) MBAR_WAIT(cbar[(i - 1) % NSTAGE], ((i - 1) / NSTAGE) & 1);
            ISSUE_STAGE(pf);
            asm volatile("cp.async.wait_group 2;" ::: "memory");
        } else if (pf == nst) {
            asm volatile("cp.async.wait_group 1;" ::: "memory");
        } else {
            asm volatile("cp.async.wait_group 0;" ::: "memory");
        }
        FENCE_ASYNC_SH();
        __syncthreads();

        if (warp == 0 && elect_one()) {
            const int j = i % NSTAGE;
            const uint64_t ad = mk_desc(ab + j * SLOT_BYTES);
            const uint64_t bd = mk_desc(ab + j * SLOT_BYTES + 16384);
            #pragma unroll
            for (int kk = 0; kk < 4; kk++)
                tc_mma_tf32_ss(tmem, ad + kk*2, bd + kk*2, TC_IDESC, (i > 0) || (kk > 0));
            TC_COMMIT(cbar[j]);
        }
    }
    #undef ISSUE_STAGE

    MBAR_WAIT(cbar[(nst - 1) % NSTAGE], ((nst - 1) / NSTAGE) & 1);
    TC_FENCE_AFTER();

    const int cb = (warp >> 2) << 6;
    TC_LD_X32(dr,      tmem + cb);
    TC_LD_X32(dr + 32, tmem + cb + 32);
    TC_WAIT_LD();
    __syncthreads();
    if (warp == 0) TC_DEALLOC(tmem, 128);
}
#else
__device__ __forceinline__ void fb_core(const float* __restrict__ A,
                                        const float* __restrict__ W,
                                        int K, int m0, int n0, char* dsm,
                                        float (*acc)[4][4]) {
    typedef unsigned SmemBuf[128][16];
    SmemBuf* As = reinterpret_cast<SmemBuf*>(dsm);
    SmemBuf* Ws = reinterpret_cast<SmemBuf*>(dsm + 2 * sizeof(SmemBuf));

    const int tid  = threadIdx.x;
    const int lane = tid & 31;
    const int warp = tid >> 5;
    const int wm = (warp >> 2) * 64;
    const int wn = (warp & 3) * 32;
    const int grp = lane >> 2;
    const int qk  = lane & 3;

    const int ldr = tid >> 2;
    const int sub = tid & 3;
    const float* Ap0 = A + (size_t)(m0 + ldr) * K + (sub << 2);
    const float* Ap1 = A + (size_t)(m0 + ldr + 64) * K + (sub << 2);
    const float* Wp0 = W + (size_t)(n0 + ldr) * K + (sub << 2);
    const float* Wp1 = W + (size_t)(n0 + ldr + 64) * K + (sub << 2);
    const int sw0 = ((ldr >> 1) & 3);
    const int sw1 = (((ldr + 64) >> 1) & 3);

    const int ntiles = K >> 4;

    #define STORE_TILE(buf, a0v, a1v, w0v, w1v)                                              \
        do {                                                                                  \
            As[buf][ldr   ][((0^sw0)<<2)+sub]=__float_as_uint(a0v.x); As[buf][ldr   ][((1^sw0)<<2)+sub]=__float_as_uint(a0v.y); \
            As[buf][ldr   ][((2^sw0)<<2)+sub]=__float_as_uint(a0v.z); As[buf][ldr   ][((3^sw0)<<2)+sub]=__float_as_uint(a0v.w); \
            As[buf][ldr+64][((0^sw1)<<2)+sub]=__float_as_uint(a1v.x); As[buf][ldr+64][((1^sw1)<<2)+sub]=__float_as_uint(a1v.y); \
            As[buf][ldr+64][((2^sw1)<<2)+sub]=__float_as_uint(a1v.z); As[buf][ldr+64][((3^sw1)<<2)+sub]=__float_as_uint(a1v.w); \
            Ws[buf][ldr   ][((0^sw0)<<2)+sub]=__float_as_uint(w0v.x); Ws[buf][ldr   ][((1^sw0)<<2)+sub]=__float_as_uint(w0v.y); \
            Ws[buf][ldr   ][((2^sw0)<<2)+sub]=__float_as_uint(w0v.z); Ws[buf][ldr   ][((3^sw0)<<2)+sub]=__float_as_uint(w0v.w); \
            Ws[buf][ldr+64][((0^sw1)<<2)+sub]=__float_as_uint(w1v.x); Ws[buf][ldr+64][((1^sw1)<<2)+sub]=__float_as_uint(w1v.y); \
            Ws[buf][ldr+64][((2^sw1)<<2)+sub]=__float_as_uint(w1v.z); Ws[buf][ldr+64][((3^sw1)<<2)+sub]=__float_as_uint(w1v.w); \
        } while (0)

    {
        float4 a0 = *(const float4*)(Ap0);
        float4 a1 = *(const float4*)(Ap1);
        float4 w0 = *(const float4*)(Wp0);
        float4 w1 = *(const float4*)(Wp1);
        STORE_TILE(0, a0, a1, w0, w1);
    }
    __syncthreads();

    for (int it = 0; it < ntiles; it++) {
        const int cur = it & 1, nxt = cur ^ 1;
        float4 a0, a1, w0, w1;
        const bool have_next = (it + 1) < ntiles;
        if (have_next) {
            const int ko = (it + 1) << 4;
            a0 = *(const float4*)(Ap0 + ko);
            a1 = *(const float4*)(Ap1 + ko);
            w0 = *(const float4*)(Wp0 + ko);
            w1 = *(const float4*)(Wp1 + ko);
        }

        uint4 Bv[4];
        #pragma unroll
        for (int ni = 0; ni < 4; ni++) {
            const int rn = wn + (ni << 3) + grp;
            Bv[ni] = *(const uint4*)&Ws[cur][rn][((qk ^ ((rn >> 1) & 3)) << 2)];
        }
        #pragma unroll
        for (int mi = 0; mi < 4; mi++) {
            const int rl = wm + (mi << 4) + grp;
            const int rh = rl + 8;
            const uint4 Alo = *(const uint4*)&As[cur][rl][((qk ^ ((rl >> 1) & 3)) << 2)];
            const uint4 Ahi = *(const uint4*)&As[cur][rh][((qk ^ ((rh >> 1) & 3)) << 2)];
            #pragma unroll
            for (int ni = 0; ni < 4; ni++) {
                mma_tf32(acc[mi][ni][0], acc[mi][ni][1], acc[mi][ni][2], acc[mi][ni][3],
                         Alo.x, Ahi.x, Alo.y, Ahi.y, Bv[ni].x, Bv[ni].y);
                mma_tf32(acc[mi][ni][0], acc[mi][ni][1], acc[mi][ni][2], acc[mi][ni][3],
                         Alo.z, Ahi.z, Alo.w, Ahi.w, Bv[ni].z, Bv[ni].w);
            }
        }

        if (have_next) {
            STORE_TILE(nxt, a0, a1, w0, w1);
        }
        __syncthreads();
    }
    #undef STORE_TILE
}
#endif

// ---------------- generic GEMM: EP 0 plain / 2 GELU / 3 +res; RND tf32 -------
template<int EP, int RND>
__global__ __launch_bounds__(256, 2)
void gemm_u(const float* __restrict__ A, const float* __restrict__ W,
            const float* __restrict__ bias, const float* __restrict__ res,
            float* __restrict__ C, int M, int N, int K) {
    extern __shared__ char dsm[];
    const int tid  = threadIdx.x;
    const int warp = tid >> 5;
    const int lane = tid & 31;
    const int m0 = blockIdx.y << 7, n0 = blockIdx.x << 7;

#if TC_OK
    uint32_t dr[64];
    tc_core(A, W, K, m0, n0, dsm, dr);

    const int r  = m0 + ((warp & 3) << 5) + lane;
    const int cg = n0 + ((warp >> 2) << 6);
    float* crow = C + (size_t)r * N + cg;
    const float* rrow = (EP == 3) ? (res + (size_t)r * N + cg) : nullptr;
    #pragma unroll
    for (int j4 = 0; j4 < 16; j4++) {
        float4 bv = *(const float4*)(bias + cg + (j4 << 2));
        float4 o;
        o.x = __uint_as_float(dr[j4*4+0]) + bv.x;
        o.y = __uint_as_float(dr[j4*4+1]) + bv.y;
        o.z = __uint_as_float(dr[j4*4+2]) + bv.z;
        o.w = __uint_as_float(dr[j4*4+3]) + bv.w;
        if (EP == 2) {
            o.x = 0.5f * o.x * (1.0f + erff(o.x * 0.70710678118654752f));
            o.y = 0.5f * o.y * (1.0f + erff(o.y * 0.70710678118654752f));
            o.z = 0.5f * o.z * (1.0f + erff(o.z * 0.70710678118654752f));
            o.w = 0.5f * o.w * (1.0f + erff(o.w * 0.70710678118654752f));
        }
        if (EP == 3) {
            float4 rv = *(const float4*)(rrow + (j4 << 2));
            o.x += rv.x; o.y += rv.y; o.z += rv.z; o.w += rv.w;
        }
        if (RND) { o.x = tf32r(o.x); o.y = tf32r(o.y); o.z = tf32r(o.z); o.w = tf32r(o.w); }
        *(float4*)(crow + (j4 << 2)) = o;
    }
#else
    float acc[4][4][4];
    #pragma unroll
    for (int i = 0; i < 4; i++)
        #pragma unroll
        for (int j = 0; j < 4; j++)
            #pragma unroll
            for (int f = 0; f < 4; f++) acc[i][j][f] = 0.f;
    fb_core(A, W, K, m0, n0, dsm, acc);

    const int wm = (warp >> 2) * 64;
    const int wn = (warp & 3) * 32;
    const int grp = lane >> 2;
    const int qk  = lane & 3;
    #pragma unroll
    for (int mi = 0; mi < 4; mi++) {
        #pragma unroll
        for (int ni = 0; ni < 4; ni++) {
            #pragma unroll
            for (int f = 0; f < 4; f++) {
                const int r = m0 + wm + (mi << 4) + grp + ((f >> 1) << 3);
                const int c = n0 + wn + (ni << 3) + (qk << 1) + (f & 1);
                float val = acc[mi][ni][f] + bias[c];
                if (EP == 2) val = 0.5f * val * (1.0f + erff(val * 0.70710678118654752f));
                if (EP == 3) val += res[(size_t)r * N + c];
                if (RND) val = tf32r(val);
                C[(size_t)r * N + c] = val;
            }
        }
    }
#endif
}

// ---------------- fused QKV GEMM + RoPE epilogue ------------------------------
__global__ __launch_bounds__(256, 2)
void gemm_qkv(const float* __restrict__ A, const float* __restrict__ cw,
              const float* __restrict__ bq, const float* __restrict__ bk,
              const float* __restrict__ bv, const float* __restrict__ freqs,
              float* __restrict__ q, float* __restrict__ k, float* __restrict__ v) {
    extern __shared__ char dsm[];
    const int tid  = threadIdx.x;
    const int warp = tid >> 5;
    const int lane = tid & 31;
    const int m0 = blockIdx.y << 7, n0 = blockIdx.x << 7;
    const int z  = blockIdx.z;
    const float* W    = cw + (size_t)z * CW_DD;
    const float* bias = (z == 0) ? bq : (z == 1) ? bk : bv;
    float* C          = (z == 0) ? q  : (z == 1) ? k  : v;

#if TC_OK
    uint32_t dr[64];
    tc_core(A, W, D_, m0, n0, dsm, dr);

    const int r  = m0 + ((warp & 3) << 5) + lane;
    const int cg = n0 + ((warp >> 2) << 6);
    const float n_pos = (float)(r & (N_ - 1));
    float* crow = C + (size_t)r * D_ + cg;
    #pragma unroll
    for (int j4 = 0; j4 < 16; j4++) {
        const int c4 = cg + (j4 << 2);
        float4 bvv = *(const float4*)(bias + c4);
        float4 o;
        o.x = __uint_as_float(dr[j4*4+0]) + bvv.x;
        o.y = __uint_as_float(dr[j4*4+1]) + bvv.y;
        o.z = __uint_as_float(dr[j4*4+2]) + bvv.z;
        o.w = __uint_as_float(dr[j4*4+3]) + bvv.w;
        if (z == 0) { o.x *= SCALING_; o.y *= SCALING_; o.z *= SCALING_; o.w *= SCALING_; }
        if (z < 2) {
            const int i0 = (c4 & 63) >> 1;
            float s0, c0, s1, c1;
            __sincosf(n_pos * freqs[i0],     &s0, &c0);
            __sincosf(n_pos * freqs[i0 + 1], &s1, &c1);
            float4 t = o;
            o.x = t.x * c0 - t.y * s0;
            o.y = t.y * c0 + t.x * s0;
            o.z = t.z * c1 - t.w * s1;
            o.w = t.w * c1 + t.z * s1;
        }
        o.x = tf32r(o.x); o.y = tf32r(o.y); o.z = tf32r(o.z); o.w = tf32r(o.w);
        *(float4*)(crow + (j4 << 2)) = o;
    }
#else
    float acc[4][4][4];
    #pragma unroll
    for (int i = 0; i < 4; i++)
        #pragma unroll
        for (int j = 0; j < 4; j++)
            #pragma unroll
            for (int f = 0; f < 4; f++) acc[i][j][f] = 0.f;
    fb_core(A, W, D_, m0, n0, dsm, acc);

    const int wm = (warp >> 2) * 64;
    const int wn = (warp & 3) * 32;
    const int grp = lane >> 2;
    const int qk  = lane & 3;
    #pragma unroll
    for (int mi = 0; mi < 4; mi++) {
        #pragma unroll
        for (int ni = 0; ni < 4; ni++) {
            #pragma unroll
            for (int fp = 0; fp < 2; fp++) {
                const int r = m0 + wm + (mi << 4) + grp + (fp << 3);
                const int c0 = n0 + wn + (ni << 3) + (qk << 1);
                float v0 = acc[mi][ni][fp*2+0] + bias[c0];
                float v1 = acc[mi][ni][fp*2+1] + bias[c0+1];
                if (z == 0) { v0 *= SCALING_; v1 *= SCALING_; }
                if (z < 2) {
                    const int i0 = (c0 & 63) >> 1;
                    float s0, cc0;
                    __sincosf((float)(r & (N_-1)) * freqs[i0], &s0, &cc0);
                    float t0 = v0, t1 = v1;
                    v0 = t0 * cc0 - t1 * s0;
                    v1 = t1 * cc0 + t0 * s0;
                }
                C[(size_t)r * D_ + c0]     = tf32r(v0);
                C[(size_t)r * D_ + c0 + 1] = tf32r(v1);
            }
        }
    }
#endif
}

// ---------------- flash attention, fp16 mma m16n8k16, BQ=128 BK=32 -----------
// K/V/Q/P in fp16, accumulate fp32. P conversion is register-local (the
// m16n8k8 C-layout equals the m16n8k16 A-layout when packed to half2): no
// shuffles, no Ps smem. Smem: Ks 32x32 words (4KB) + Vt 64x16 words (4KB).
// Ks word(p) = (p&3)*8 + ((p>>2) ^ ((key&1)<<2)); Vt word(p) = (p&3)*4 + (p>>2).
#define ATTN_SMEM (4096 + 4096 + 64)
__global__ __launch_bounds__(256, 2)
void attn_tc(const float* __restrict__ q, const float* __restrict__ k,
             const float* __restrict__ v, const unsigned char* __restrict__ pm,
             float* __restrict__ out) {
    extern __shared__ char asmem[];
    unsigned* Ks = (unsigned*)asmem;               // [32 keys][32 half2 words]
    unsigned* Vt = (unsigned*)(asmem + 4096);      // [64 dims][16 half2 words]
    unsigned char* Ms = (unsigned char*)(asmem + 8192);

    const int tid = threadIdx.x, warp = tid >> 5, lane = tid & 31;
    const int grp = lane >> 2, qk = lane & 3;
    const int qt = blockIdx.x, bh = blockIdx.y;
    const int b = bh / H_, h = bh - b * H_;
    const int row0 = b * N_ + qt * 128;
    const int colh = h * HD_;
    const int rl0 = (warp << 4) + grp;
    const int r0 = row0 + rl0;

    // Q A-frags fp16: chunk c: a0=(rl0, 16c+2qk,+1) a1=(rl1,..) a2=(rl0, +8) a3=(rl1, +8)
    unsigned aq[4][4];
    {
        const float* q0 = q + (size_t)r0 * D_ + colh;
        const float* q1 = q0 + (size_t)8 * D_;
        #pragma unroll
        for (int c = 0; c < 4; c++) {
            const int d0 = 16*c + 2*qk;
            float2 f;
            f = *(const float2*)(q0 + d0);     aq[c][0] = h2pack(f.x, f.y);
            f = *(const float2*)(q1 + d0);     aq[c][1] = h2pack(f.x, f.y);
            f = *(const float2*)(q0 + d0 + 8); aq[c][2] = h2pack(f.x, f.y);
            f = *(const float2*)(q1 + d0 + 8); aq[c][3] = h2pack(f.x, f.y);
        }
    }

    float o_[8][4];
    #pragma unroll
    for (int nt = 0; nt < 8; nt++) { o_[nt][0]=0.f; o_[nt][1]=0.f; o_[nt][2]=0.f; o_[nt][3]=0.f; }
    float m0 = -3.0e38f, m1 = -3.0e38f, l0 = 0.f, l1 = 0.f;

    // K producer: key = tid>>3, lq8 = tid&7 -> pairs p = lq8 + 8c
    const int lkey = tid >> 3, lq8 = tid & 7;
    const int kpar = (lkey & 1) << 2;
    // V producer: pair pidx = tid&15 (keys 2p,2p+1), dims 4*(tid>>4)..+3
    const int vp = tid & 15, vdc = tid >> 4;
    const int vw = ((vp & 3) << 2) + (vp >> 2);

    for (int kt = 0; kt < N_; kt += 32) {
        __syncthreads();
        {
            // K: 4 float2 -> half2 -> 4 STS.32
            const float* krow = k + (size_t)(b * N_ + kt + lkey) * D_ + colh;
            #pragma unroll
            for (int c = 0; c < 4; c++) {
                const float2 k2 = *(const float2*)(krow + 2*lq8 + 16*c);
                const int m = (lq8 >> 2) + 2*c;
                Ks[(lkey << 5) + ((lq8 & 3) << 3) + (m ^ kpar)] = h2pack(k2.x, k2.y);
            }
            // V: 2 float4 (keys 2vp, 2vp+1) -> 4 half2 -> 4 STS.32
            {
                const float4 v0 = *(const float4*)(v + (size_t)(b * N_ + kt + 2*vp)     * D_ + colh + 4*vdc);
                const float4 v1 = *(const float4*)(v + (size_t)(b * N_ + kt + 2*vp + 1) * D_ + colh + 4*vdc);
                Vt[((4*vdc + 0) << 4) + vw] = h2pack(v0.x, v1.x);
                Vt[((4*vdc + 1) << 4) + vw] = h2pack(v0.y, v1.y);
                Vt[((4*vdc + 2) << 4) + vw] = h2pack(v0.z, v1.z);
                Vt[((4*vdc + 3) << 4) + vw] = h2pack(v0.w, v1.w);
            }
            if (tid < 32) Ms[tid] = pm[b * N_ + kt + tid];
        }
        __syncthreads();

        // S = Q K^T : 4 nt-tiles x 4 k16-chunks, 16 m16n8k16 MMAs
        float s_[4][4];
        #pragma unroll
        for (int nt = 0; nt < 4; nt++) { s_[nt][0]=0.f; s_[nt][1]=0.f; s_[nt][2]=0.f; s_[nt][3]=0.f; }
        #pragma unroll
        for (int nt = 0; nt < 4; nt++) {
            const int rn = (nt << 3) + grp;
            const int rpar = (rn & 1) << 2;
            const uint4 B01 = *(const uint4*)(Ks + (rn << 5) + (qk << 3) + rpar);
            const uint4 B23 = *(const uint4*)(Ks + (rn << 5) + (qk << 3) + (4 ^ rpar));
            mma_f16(s_[nt][0], s_[nt][1], s_[nt][2], s_[nt][3],
                    aq[0][0], aq[0][1], aq[0][2], aq[0][3], B01.x, B01.y);
            mma_f16(s_[nt][0], s_[nt][1], s_[nt][2], s_[nt][3],
                    aq[1][0], aq[1][1], aq[1][2], aq[1][3], B01.z, B01.w);
            mma_f16(s_[nt][0], s_[nt][1], s_[nt][2], s_[nt][3],
                    aq[2][0], aq[2][1], aq[2][2], aq[2][3], B23.x, B23.y);
            mma_f16(s_[nt][0], s_[nt][1], s_[nt][2], s_[nt][3],
                    aq[3][0], aq[3][1], aq[3][2], aq[3][3], B23.z, B23.w);
        }

        float mx0 = -3.0e38f, mx1 = -3.0e38f;
        #pragma unroll
        for (int nt = 0; nt < 4; nt++) {
            const int c0 = (nt << 3) + (qk << 1);
            const bool k0m = Ms[c0] != 0, k1m = Ms[c0 + 1] != 0;
            s_[nt][0] = k0m ? -3.0e38f : s_[nt][0] * 0.125f;
            s_[nt][1] = k1m ? -3.0e38f : s_[nt][1] * 0.125f;
            s_[nt][2] = k0m ? -3.0e38f : s_[nt][2] * 0.125f;
            s_[nt][3] = k1m ? -3.0e38f : s_[nt][3] * 0.125f;
            mx0 = fmaxf(mx0, fmaxf(s_[nt][0], s_[nt][1]));
            mx1 = fmaxf(mx1, fmaxf(s_[nt][2], s_[nt][3]));
        }
        mx0 = fmaxf(mx0, __shfl_xor_sync(0xffffffffu, mx0, 1));
        mx0 = fmaxf(mx0, __shfl_xor_sync(0xffffffffu, mx0, 2));
        mx1 = fmaxf(mx1, __shfl_xor_sync(0xffffffffu, mx1, 1));
        mx1 = fmaxf(mx1, __shfl_xor_sync(0xffffffffu, mx1, 2));

        const float mn0 = fmaxf(m0, mx0), mn1 = fmaxf(m1, mx1);
        const float al0 = __expf(m0 - mn0), al1 = __expf(m1 - mn1);
        m0 = mn0; m1 = mn1;
        float rs0 = 0.f, rs1 = 0.f;
        #pragma unroll
        for (int nt = 0; nt < 4; nt++) {
            s_[nt][0] = __expf(s_[nt][0] - mn0);
            s_[nt][1] = __expf(s_[nt][1] - mn0);
            s_[nt][2] = __expf(s_[nt][2] - mn1);
            s_[nt][3] = __expf(s_[nt][3] - mn1);
            rs0 += s_[nt][0] + s_[nt][1];
            rs1 += s_[nt][2] + s_[nt][3];
        }
        #pragma unroll
        for (int nt = 0; nt < 8; nt++) {
            o_[nt][0] *= al0; o_[nt][1] *= al0;
            o_[nt][2] *= al1; o_[nt][3] *= al1;
        }
        rs0 += __shfl_xor_sync(0xffffffffu, rs0, 1);
        rs0 += __shfl_xor_sync(0xffffffffu, rs0, 2);
        rs1 += __shfl_xor_sync(0xffffffffu, rs1, 1);
        rs1 += __shfl_xor_sync(0xffffffffu, rs1, 2);
        l0 = l0 * al0 + rs0;
        l1 = l1 * al1 + rs1;

        // P A-frags: register-local pack (C-layout == fp16 A-layout)
        // chunk c: a0 = (rl0, keys 16c+2qk,+1) = s_[2c][0..1], a1 = rl1 = s_[2c][2..3],
        //          a2 = s_[2c+1][0..1], a3 = s_[2c+1][2..3]
        unsigned Af[2][4];
        #pragma unroll
        for (int c = 0; c < 2; c++) {
            Af[c][0] = h2pack(s_[2*c][0],   s_[2*c][1]);
            Af[c][1] = h2pack(s_[2*c][2],   s_[2*c][3]);
            Af[c][2] = h2pack(s_[2*c+1][0], s_[2*c+1][1]);
            Af[c][3] = h2pack(s_[2*c+1][2], s_[2*c+1][3]);
        }

        // O += P V : 8 nt-tiles x 2 k16-chunks, one LDS.128 covers both chunks
        #pragma unroll
        for (int nt = 0; nt < 8; nt++) {
            const int rn = (nt << 3) + grp;
            const uint4 Bv = *(const uint4*)(Vt + (rn << 4) + (qk << 2));
            mma_f16(o_[nt][0], o_[nt][1], o_[nt][2], o_[nt][3],
                    Af[0][0], Af[0][1], Af[0][2], Af[0][3], Bv.x, Bv.y);
            mma_f16(o_[nt][0], o_[nt][1], o_[nt][2], o_[nt][3],
                    Af[1][0], Af[1][1], Af[1][2], Af[1][3], Bv.z, Bv.w);
        }
    }

    const float inv0 = 1.0f / l0, inv1 = 1.0f / l1;
    float* out0 = out + (size_t)r0 * D_ + colh;
    float* out1 = out0 + (size_t)8 * D_;
    #pragma unroll
    for (int nt = 0; nt < 8; nt++) {
        const int c0 = (nt << 3) + (qk << 1);
        out0[c0]     = tf32r(o_[nt][0] * inv0);
        out0[c0 + 1] = tf32r(o_[nt][1] * inv0);
        out1[c0]     = tf32r(o_[nt][2] * inv1);
        out1[c0 + 1] = tf32r(o_[nt][3] * inv1);
    }
}

// ---------------- launch ------------------------------------------------------
extern "C" void kernel_launch(void* const* d_in, const int* in_sizes, int n_in,
                              void* d_out, int out_size) {
    const float* x     = (const float*)d_in[0];
    const unsigned char* pmask = (const unsigned char*)d_in[1];
    const float* wq = (const float*)d_in[2];
    const float* bq = (const float*)d_in[3];
    const float* wk = (const float*)d_in[4];
    const float* bk = (const float*)d_in[5];
    const float* wv = (const float*)d_in[6];
    const float* bv = (const float*)d_in[7];
    const float* wo = (const float*)d_in[8];
    const float* bo = (const float*)d_in[9];
    const float* w1 = (const float*)d_in[10];
    const float* b1 = (const float*)d_in[11];
    const float* w2 = (const float*)d_in[12];
    const float* b2 = (const float*)d_in[13];
    const float* ln1w = (const float*)d_in[14];
    const float* ln1b = (const float*)d_in[15];
    const float* ln2w = (const float*)d_in[16];
    const float* ln2b = (const float*)d_in[17];
    const float* freqs = (const float*)d_in[18];
    float* out = (float*)d_out;

    float *ph, *pq, *pk, *pv, *patt, *pff, *pcw;
    cudaGetSymbolAddress((void**)&ph,   g_h);
    cudaGetSymbolAddress((void**)&pq,   g_q);
    cudaGetSymbolAddress((void**)&pk,   g_k);
    cudaGetSymbolAddress((void**)&pv,   g_v);
    cudaGetSymbolAddress((void**)&patt, g_att);
    cudaGetSymbolAddress((void**)&pff,  g_ff);
    cudaGetSymbolAddress((void**)&pcw,  g_cw);

    float* cwo = pcw + 3*CW_DD;
    float* cw1 = pcw + 4*CW_DD;
    float* cw2 = pcw + 4*CW_DD + CW_FD;

    cudaFuncSetAttribute(gemm_u<0,0>, cudaFuncAttributeMaxDynamicSharedMemorySize, GEMM_DYN_SMEM);
    cudaFuncSetAttribute(gemm_u<2,1>, cudaFuncAttributeMaxDynamicSharedMemorySize, GEMM_DYN_SMEM);
    cudaFuncSetAttribute(gemm_u<3,0>, cudaFuncAttributeMaxDynamicSharedMemorySize, GEMM_DYN_SMEM);
    cudaFuncSetAttribute(gemm_qkv,    cudaFuncAttributeMaxDynamicSharedMemorySize, GEMM_DYN_SMEM);
    cudaFuncSetAttribute(attn_tc,     cudaFuncAttributeMaxDynamicSharedMemorySize, ATTN_SMEM);

    const dim3 gD(D_ / 128, M_ / 128);        // (6, 64)
    const dim3 gQKV(D_ / 128, M_ / 128, 3);   // (6, 64, 3)
    const dim3 gF(FF_ / 128, M_ / 128);       // (24, 64)
    const int ntotal4 = (4*CW_DD + 2*CW_FD) / 4;

    // tf32-round all six weight matrices in ONE launch
    cvt_all_kernel<<<(ntotal4 + 255)/256, 256>>>(
        (const float4*)wq, (const float4*)wk, (const float4*)wv,
        (const float4*)wo, (const float4*)w1, (const float4*)w2, (float4*)pcw);

    // LN1 (tf32-rounded output)
    ln_kernel<<<M_, 256>>>(x, ln1w, ln1b, ph);
    // fused QKV projections + RoPE (one launch)
    gemm_qkv<<<gQKV, 256, GEMM_DYN_SMEM>>>(ph, pcw, bq, bk, bv, freqs, pq, pk, pv);
    // attention (fp16 MMA)
    attn_tc<<<dim3(N_ / 128, B_ * H_), 256, ATTN_SMEM>>>(pq, pk, pv, pmask, patt);
    // O projection + residual (x) -> d_out
    gemm_u<3,0><<<gD, 256, GEMM_DYN_SMEM>>>(patt, cwo, bo, x, out, M_, D_, D_);
    // LN2 (reuse g_h)
    ln_kernel<<<M_, 256>>>(out, ln2w, ln2b, ph);
    // FFN1 with exact GELU (rounded output feeds FFN2)
    gemm_u<2,1><<<gF, 256, GEMM_DYN_SMEM>>>(ph, cw1, b1, nullptr, pff, M_, FF_, D_);
    // FFN2 + residual (d_out) -> d_out
    gemm_u<3,0><<<gD, 256, GEMM_DYN_SMEM>>>(pff, cw2, b2, out, out, M_, D_, FF_);
}

// round 17
// speedup vs baseline: 2.2607x; 1.2821x over previous
#include <cuda_runtime.h>
#include <cuda_fp16.h>
#include <math.h>
#include <stdint.h>

#define D_  768
#define H_  12
#define HD_ 64
#define FF_ 3072
#define B_  8
#define N_  1024
#define M_  (B_*N_)          // 8192 rows
#define SCALING_ 0.125f      // HD^-0.5
#define EPS_ 1e-5f

#if defined(__CUDA_ARCH_FEAT_SM103_ALL) || defined(__CUDA_ARCH_FEAT_SM100_ALL) || \
    defined(__CUDA_ARCH_SPECIFIC__) || defined(__CUDA_ARCH_FAMILY_SPECIFIC__)
#define TC_OK 1
#else
#define TC_OK 0
#endif

// ---------------- scratch (static device globals; no allocation) -------------
__device__ __half g_h  [M_*D_];
__device__ __half g_q  [M_*D_];
__device__ __half g_k  [M_*D_];
__device__ __half g_v  [M_*D_];
__device__ __half g_att[M_*D_];
__device__ __half g_ff [M_*FF_];
#define CW_DD (D_*D_)
#define CW_FD (FF_*D_)
__device__ __half g_cw [4*CW_DD + 2*CW_FD];

// ---------------- common helpers ---------------------------------------------
__device__ __forceinline__ unsigned h2pack(float lo, float hi) {
    __half2 h = __floats2half2_rn(lo, hi);
    return *reinterpret_cast<unsigned*>(&h);
}

#if TC_OK
__device__ __forceinline__ uint32_t smem_u32(const void* p) {
    uint32_t a;
    asm("{ .reg .u64 t; cvta.to.shared.u64 t, %1; cvt.u32.u64 %0, t; }" : "=r"(a) : "l"(p));
    return a;
}
__device__ __forceinline__ uint32_t elect_one() {
    uint32_t p;
    asm volatile("{ .reg .pred p; elect.sync _|p, 0xFFFFFFFF; selp.b32 %0, 1, 0, p; }" : "=r"(p));
    return p;
}
__device__ __forceinline__ void cp16(uint32_t smaddr, const void* g) {
    asm volatile("cp.async.cg.shared.global [%0], [%1], 16;" :: "r"(smaddr), "l"(g) : "memory");
}
#define CP_COMMIT() asm volatile("cp.async.commit_group;" ::: "memory")
#define TC_ALLOC(smem_addr, n) \
    asm volatile("tcgen05.alloc.cta_group::1.sync.aligned.shared::cta.b32 [%0], %1;" \
                 :: "r"(smem_addr), "r"((uint32_t)(n)) : "memory")
#define TC_RELINQ() \
    asm volatile("tcgen05.relinquish_alloc_permit.cta_group::1.sync.aligned;")
#define TC_DEALLOC(tmem, n) \
    asm volatile("tcgen05.dealloc.cta_group::1.sync.aligned.b32 %0, %1;" :: "r"(tmem), "r"((uint32_t)(n)))
#define TC_COMMIT(mbar) \
    asm volatile("tcgen05.commit.cta_group::1.mbarrier::arrive::one.shared::cluster.b64 [%0];" \
                 :: "r"(mbar) : "memory")
#define TC_FENCE_AFTER()  asm volatile("tcgen05.fence::after_thread_sync;" ::: "memory")
#define FENCE_ASYNC_SH()  asm volatile("fence.proxy.async.shared::cta;" ::: "memory")
#define MBAR_INIT(mbar, cnt) \
    asm volatile("mbarrier.init.shared.b64 [%0], %1;" :: "r"(mbar), "r"((uint32_t)(cnt)) : "memory")
#define MBAR_WAIT(mbar, ph) do {                                                  \
    asm volatile("{\n\t.reg .pred P1;\n\t"                                        \
        "WL_%=:\n\t"                                                              \
        "mbarrier.try_wait.parity.acquire.cta.shared::cta.b64 P1, [%0], %1, 0x989680;\n\t" \
        "@P1 bra.uni WD_%=;\n\t"                                                  \
        "bra.uni WL_%=;\n\t"                                                      \
        "WD_%=:\n\t}"                                                             \
        :: "r"(mbar), "r"((uint32_t)(ph)) : "memory");                            \
} while (0)
#define TC_LD_X32(r, tmem) \
    asm volatile( \
        "tcgen05.ld.sync.aligned.32x32b.x32.b32 " \
        "{%0, %1, %2, %3, %4, %5, %6, %7, " \
        " %8, %9, %10, %11, %12, %13, %14, %15, " \
        " %16, %17, %18, %19, %20, %21, %22, %23, " \
        " %24, %25, %26, %27, %28, %29, %30, %31}, [%32];" \
        : "=r"((r)[0]),  "=r"((r)[1]),  "=r"((r)[2]),  "=r"((r)[3]), \
          "=r"((r)[4]),  "=r"((r)[5]),  "=r"((r)[6]),  "=r"((r)[7]), \
          "=r"((r)[8]),  "=r"((r)[9]),  "=r"((r)[10]), "=r"((r)[11]), \
          "=r"((r)[12]), "=r"((r)[13]), "=r"((r)[14]), "=r"((r)[15]), \
          "=r"((r)[16]), "=r"((r)[17]), "=r"((r)[18]), "=r"((r)[19]), \
          "=r"((r)[20]), "=r"((r)[21]), "=r"((r)[22]), "=r"((r)[23]), \
          "=r"((r)[24]), "=r"((r)[25]), "=r"((r)[26]), "=r"((r)[27]), \
          "=r"((r)[28]), "=r"((r)[29]), "=r"((r)[30]), "=r"((r)[31]) \
        : "r"(tmem))
#define TC_WAIT_LD() asm volatile("tcgen05.wait::ld.sync.aligned;" ::: "memory")

__device__ __forceinline__ void tc_mma_f16_ss(uint32_t d, uint64_t ad, uint64_t bd,
                                              uint32_t idesc, bool acc) {
    uint32_t e = acc ? 1u : 0u;
    asm volatile(
        "{\n\t.reg .pred p;\n\tsetp.ne.u32 p, %4, 0;\n\t"
        "tcgen05.mma.cta_group::1.kind::f16 [%0], %1, %2, %3, {%5,%5,%5,%5}, p;\n\t}"
        :: "r"(d), "l"(ad), "l"(bd), "r"(idesc), "r"(e), "r"(0u) : "memory");
}
__device__ __forceinline__ uint64_t mk_desc(uint32_t addr) {
    const uint64_t base = (uint64_t(2) << 61) | (uint64_t(1) << 46)
                        | (uint64_t(64) << 32) | (uint64_t(1) << 16);
    return base | ((uint64_t)(addr >> 4) & 0x3FFF);
}
#define SWZ128(b) ((b) ^ (((b) >> 3) & 0x70))
// kind::f16 idesc: dtype F32=1<<4, atype=btype=F16=0, N=128 ->16<<17, M=128 ->8<<24
#define TC_IDESC_F16 ((1u<<4)|(16u<<17)|(8u<<24))
#endif  // TC_OK

__device__ __forceinline__ void mma_f16(float& c0, float& c1, float& c2, float& c3,
                                        unsigned a0, unsigned a1, unsigned a2, unsigned a3,
                                        unsigned b0, unsigned b1) {
    asm volatile(
        "mma.sync.aligned.m16n8k16.row.col.f32.f16.f16.f32 "
        "{%0,%1,%2,%3}, {%4,%5,%6,%7}, {%8,%9}, {%0,%1,%2,%3};"
        : "+f"(c0), "+f"(c1), "+f"(c2), "+f"(c3)
        : "r"(a0), "r"(a1), "r"(a2), "r"(a3), "r"(b0), "r"(b1));
}

// ---------------- one-shot fp16 conversion of all six weights (fused) --------
__global__ __launch_bounds__(256)
void cvt_all_kernel(const float4* wq, const float4* wk, const float4* wv,
                    const float4* wo, const float4* w1, const float4* w2,
                    uint2* dst) {
    const int DD4 = CW_DD/4, FD4 = CW_FD/4;
    const int total = 4*DD4 + 2*FD4;
    int i = blockIdx.x * blockDim.x + threadIdx.x;
    if (i >= total) return;
    const float4* src;
    int off;
    if (i < 4*DD4) {
        int w = i / DD4; off = i - w*DD4;
        src = (w == 0) ? wq : (w == 1) ? wk : (w == 2) ? wv : wo;
    } else {
        int j = i - 4*DD4;
        if (j < FD4) { src = w1; off = j; }
        else         { src = w2; off = j - FD4; }
    }
    float4 v = src[off];
    uint2 o;
    o.x = h2pack(v.x, v.y);
    o.y = h2pack(v.z, v.w);
    dst[i] = o;
}

// ---------------- LayerNorm (fp16 output) ------------------------------------
__global__ __launch_bounds__(256)
void ln_kernel(const float* __restrict__ x, const float* __restrict__ w,
               const float* __restrict__ b, __half* __restrict__ out) {
    const int row = blockIdx.x;
    const int tid = threadIdx.x;
    const float* xr = x + (size_t)row * D_;
    float v[3];
    float s = 0.f;
    #pragma unroll
    for (int i = 0; i < 3; i++) { v[i] = xr[tid + i*256]; s += v[i]; }

    __shared__ float red[8];
    __shared__ float bc[2];
    #pragma unroll
    for (int o = 16; o; o >>= 1) s += __shfl_xor_sync(0xffffffffu, s, o);
    if ((tid & 31) == 0) red[tid >> 5] = s;
    __syncthreads();
    if (tid == 0) {
        float t = 0.f;
        #pragma unroll
        for (int i = 0; i < 8; i++) t += red[i];
        bc[0] = t * (1.0f / D_);
    }
    __syncthreads();
    const float mu = bc[0];

    float s2 = 0.f;
    #pragma unroll
    for (int i = 0; i < 3; i++) { float d = v[i] - mu; s2 += d * d; }
    #pragma unroll
    for (int o = 16; o; o >>= 1) s2 += __shfl_xor_sync(0xffffffffu, s2, o);
    if ((tid & 31) == 0) red[tid >> 5] = s2;
    __syncthreads();
    if (tid == 0) {
        float t = 0.f;
        #pragma unroll
        for (int i = 0; i < 8; i++) t += red[i];
        bc[1] = rsqrtf(t * (1.0f / D_) + EPS_);
    }
    __syncthreads();
    const float rstd = bc[1];

    __half* orow = out + (size_t)row * D_;
    #pragma unroll
    for (int i = 0; i < 3; i++) {
        int c = tid + i*256;
        orow[c] = __float2half_rn((v[i] - mu) * rstd * w[c] + b[c]);
    }
}

// ---------------- fp16 GEMM core ---------------------------------------------
// C = A[M,K]h @ W[N,K]h^T, 128x128 tile, K staged 64 halves (128B SW128 rows),
// 3-deep cp.async ring, tcgen05 kind::f16, fp32 accum in TMEM.
#define NSTAGE 3
#define SLOT_BYTES 32768
#define GEMM_DYN_SMEM (NSTAGE*SLOT_BYTES + 1024)

#if TC_OK
__device__ __forceinline__ void tc_core(const __half* __restrict__ A,
                                        const __half* __restrict__ W,
                                        int K, int m0, int n0, char* dsm,
                                        uint32_t* dr) {
    __shared__ uint32_t tmem_ptr_s[1];
    __shared__ __align__(8) uint64_t mbar_s[NSTAGE];

    const int tid  = threadIdx.x;
    const int warp = tid >> 5;

    uint32_t rawb = smem_u32(dsm);
    uint32_t ab   = (rawb + 1023u) & ~1023u;
    uint32_t cbar[NSTAGE];
    #pragma unroll
    for (int j = 0; j < NSTAGE; j++) cbar[j] = smem_u32(&mbar_s[j]);

    if (warp == 0) {
        TC_ALLOC(smem_u32(tmem_ptr_s), 128);
        TC_RELINQ();
    }
    if (tid == 0) {
        #pragma unroll
        for (int j = 0; j < NSTAGE; j++) MBAR_INIT(cbar[j], 1);
    }
    __syncthreads();
    uint32_t tmem;
    asm volatile("ld.shared.b32 %0, [%1];" : "=r"(tmem) : "r"(smem_u32(tmem_ptr_s)));

    const int prow = tid >> 3;    // 0..31 (+32p)
    const int psub = tid & 7;     // 16B chunk (8 halves)

    const __half* Ap[4];
    const __half* Wp[4];
    uint32_t soff[4];
    #pragma unroll
    for (int p = 0; p < 4; p++) {
        const int r = prow + (p << 5);
        Ap[p] = A + (size_t)(m0 + r) * K + (psub << 3);
        Wp[p] = W + (size_t)(n0 + r) * K + (psub << 3);
        soff[p] = SWZ128((r << 7) | (psub << 4));
    }

    const int nst = K >> 6;   // 64 halves per stage

    #define ISSUE_STAGE(s)                                                   \
        do {                                                                 \
            const int _j = (s) % NSTAGE;                                     \
            const uint32_t _ab = ab + _j * SLOT_BYTES;                       \
            const uint32_t _bb = _ab + 16384;                                \
            const int _ko = (s) << 6;                                        \
            _Pragma("unroll")                                                \
            for (int p = 0; p < 4; p++) {                                    \
                cp16(_ab + soff[p], Ap[p] + _ko);                            \
                cp16(_bb + soff[p], Wp[p] + _ko);                            \
            }                                                                \
            CP_COMMIT();                                                     \
        } while (0)

    ISSUE_STAGE(0);
    ISSUE_STAGE(1);

    for (int i = 0; i < nst; i++) {
        const int pf = i + NSTAGE - 1;
        if (pf < nst) {
            if (i >= 1) MBAR_WAIT(cbar[(i - 1) % NSTAGE], ((i - 1) / NSTAGE) & 1);
            ISSUE_STAGE(pf);
            asm volatile("cp.async.wait_group 2;" ::: "memory");
        } else if (pf == nst) {
            asm volatile("cp.async.wait_group 1;" ::: "memory");
        } else {
            asm volatile("cp.async.wait_group 0;" ::: "memory");
        }
        FENCE_ASYNC_SH();
        __syncthreads();

        if (warp == 0 && elect_one()) {
            const int j = i % NSTAGE;
            const uint64_t ad = mk_desc(ab + j * SLOT_BYTES);
            const uint64_t bd = mk_desc(ab + j * SLOT_BYTES + 16384);
            #pragma unroll
            for (int kk = 0; kk < 4; kk++)   // 4 x K=16 halves (32B = 2 units)
                tc_mma_f16_ss(tmem, ad + kk*2, bd + kk*2, TC_IDESC_F16, (i > 0) || (kk > 0));
            TC_COMMIT(cbar[j]);
        }
    }
    #undef ISSUE_STAGE

    MBAR_WAIT(cbar[(nst - 1) % NSTAGE], ((nst - 1) / NSTAGE) & 1);
    TC_FENCE_AFTER();

    const int cb = (warp >> 2) << 6;
    TC_LD_X32(dr,      tmem + cb);
    TC_LD_X32(dr + 32, tmem + cb + 32);
    TC_WAIT_LD();
    __syncthreads();
    if (warp == 0) TC_DEALLOC(tmem, 128);
}
#endif

// ---------------- generic GEMM: EP 2 = GELU, 3 = +res; OUTH = fp16 out -------
template<int EP, int OUTH>
__global__ __launch_bounds__(256, 2)
void gemm_u(const __half* __restrict__ A, const __half* __restrict__ W,
            const float* __restrict__ bias, const float* __restrict__ res,
            void* __restrict__ Cv, int M, int N, int K) {
    extern __shared__ char dsm[];
    const int tid  = threadIdx.x;
    const int m0 = blockIdx.y << 7, n0 = blockIdx.x << 7;

#if TC_OK
    const int warp = tid >> 5;
    const int lane = tid & 31;
    uint32_t dr[64];
    tc_core(A, W, K, m0, n0, dsm, dr);

    const int r  = m0 + ((warp & 3) << 5) + lane;
    const int cg = n0 + ((warp >> 2) << 6);
    #pragma unroll
    for (int j4 = 0; j4 < 16; j4++) {
        float4 bv = *(const float4*)(bias + cg + (j4 << 2));
        float4 o;
        o.x = __uint_as_float(dr[j4*4+0]) + bv.x;
        o.y = __uint_as_float(dr[j4*4+1]) + bv.y;
        o.z = __uint_as_float(dr[j4*4+2]) + bv.z;
        o.w = __uint_as_float(dr[j4*4+3]) + bv.w;
        if (EP == 2) {
            o.x = 0.5f * o.x * (1.0f + erff(o.x * 0.70710678118654752f));
            o.y = 0.5f * o.y * (1.0f + erff(o.y * 0.70710678118654752f));
            o.z = 0.5f * o.z * (1.0f + erff(o.z * 0.70710678118654752f));
            o.w = 0.5f * o.w * (1.0f + erff(o.w * 0.70710678118654752f));
        }
        if (EP == 3) {
            float4 rv = *(const float4*)(res + (size_t)r * N + cg + (j4 << 2));
            o.x += rv.x; o.y += rv.y; o.z += rv.z; o.w += rv.w;
        }
        if (OUTH) {
            uint2 hp;
            hp.x = h2pack(o.x, o.y);
            hp.y = h2pack(o.z, o.w);
            *(uint2*)((__half*)Cv + (size_t)r * N + cg + (j4 << 2)) = hp;
        } else {
            *(float4*)((float*)Cv + (size_t)r * N + cg + (j4 << 2)) = o;
        }
    }
#else
    // naive fallback (never selected on sm_103a; correctness only)
    for (int idx = tid; idx < 128 * 128; idx += 256) {
        const int r = m0 + (idx >> 7), c = n0 + (idx & 127);
        float s = 0.f;
        for (int kk = 0; kk < K; kk++)
            s += __half2float(A[(size_t)r * K + kk]) * __half2float(W[(size_t)c * K + kk]);
        s += bias[c];
        if (EP == 2) s = 0.5f * s * (1.0f + erff(s * 0.70710678118654752f));
        if (EP == 3) s += res[(size_t)r * N + c];
        if (OUTH) ((__half*)Cv)[(size_t)r * N + c] = __float2half_rn(s);
        else      ((float*)Cv)[(size_t)r * N + c] = s;
    }
#endif
}

// ---------------- fused QKV GEMM + RoPE epilogue (fp16 in/out) ----------------
__global__ __launch_bounds__(256, 2)
void gemm_qkv(const __half* __restrict__ A, const __half* __restrict__ cw,
              const float* __restrict__ bq, const float* __restrict__ bk,
              const float* __restrict__ bv, const float* __restrict__ freqs,
              __half* __restrict__ q, __half* __restrict__ k, __half* __restrict__ v) {
    extern __shared__ char dsm[];
    const int tid  = threadIdx.x;
    const int m0 = blockIdx.y << 7, n0 = blockIdx.x << 7;
    const int z  = blockIdx.z;
    const __half* W   = cw + (size_t)z * CW_DD;
    const float* bias = (z == 0) ? bq : (z == 1) ? bk : bv;
    __half* C         = (z == 0) ? q  : (z == 1) ? k  : v;

#if TC_OK
    const int warp = tid >> 5;
    const int lane = tid & 31;
    uint32_t dr[64];
    tc_core(A, W, D_, m0, n0, dsm, dr);

    const int r  = m0 + ((warp & 3) << 5) + lane;
    const int cg = n0 + ((warp >> 2) << 6);
    const float n_pos = (float)(r & (N_ - 1));
    #pragma unroll
    for (int j4 = 0; j4 < 16; j4++) {
        const int c4 = cg + (j4 << 2);
        float4 bvv = *(const float4*)(bias + c4);
        float4 o;
        o.x = __uint_as_float(dr[j4*4+0]) + bvv.x;
        o.y = __uint_as_float(dr[j4*4+1]) + bvv.y;
        o.z = __uint_as_float(dr[j4*4+2]) + bvv.z;
        o.w = __uint_as_float(dr[j4*4+3]) + bvv.w;
        if (z == 0) { o.x *= SCALING_; o.y *= SCALING_; o.z *= SCALING_; o.w *= SCALING_; }
        if (z < 2) {
            const int i0 = (c4 & 63) >> 1;
            float s0, c0, s1, c1;
            __sincosf(n_pos * freqs[i0],     &s0, &c0);
            __sincosf(n_pos * freqs[i0 + 1], &s1, &c1);
            float4 t = o;
            o.x = t.x * c0 - t.y * s0;
            o.y = t.y * c0 + t.x * s0;
            o.z = t.z * c1 - t.w * s1;
            o.w = t.w * c1 + t.z * s1;
        }
        uint2 hp;
        hp.x = h2pack(o.x, o.y);
        hp.y = h2pack(o.z, o.w);
        *(uint2*)(C + (size_t)r * D_ + c4) = hp;
    }
#else
    for (int idx = tid; idx < 128 * 128; idx += 256) {
        const int r = m0 + (idx >> 7), c = n0 + (idx & 127);
        float s = 0.f;
        for (int kk = 0; kk < D_; kk++)
            s += __half2float(A[(size_t)r * D_ + kk]) * __half2float(W[(size_t)c * D_ + kk]);
        s += bias[c];
        if (z == 0) s *= SCALING_;
        if (z < 2) {
            const int i0 = (c & 63) >> 1;
            float sn, cs;
            __sincosf((float)(r & (N_-1)) * freqs[i0], &sn, &cs);
            // pairwise rope: need partner value; recompute partner dot product
            const int cp = c ^ 1;
            float sp = 0.f;
            for (int kk = 0; kk < D_; kk++)
                sp += __half2float(A[(size_t)r * D_ + kk]) * __half2float(W[(size_t)cp * D_ + kk]);
            sp += bias[cp];
            if (z == 0) sp *= SCALING_;
            s = (c & 1) ? (s * cs + sp * sn) : (s * cs - sp * sn);
        }
        C[(size_t)r * D_ + c] = __float2half_rn(s);
    }
#endif
}

// ---------------- flash attention, fp16 mma m16n8k16, BQ=128 BK=32 -----------
// q/k/v/att fp16 in gmem; raw half2 moves, fp32 softmax/accum.
#define ATTN_SMEM (4096 + 4096 + 64)
__global__ __launch_bounds__(256, 2)
void attn_tc(const __half* __restrict__ q, const __half* __restrict__ k,
             const __half* __restrict__ v, const unsigned char* __restrict__ pm,
             __half* __restrict__ out) {
    extern __shared__ char asmem[];
    unsigned* Ks = (unsigned*)asmem;               // [32 keys][32 half2 words]
    unsigned* Vt = (unsigned*)(asmem + 4096);      // [64 dims][16 half2 words]
    unsigned char* Ms = (unsigned char*)(asmem + 8192);

    const int tid = threadIdx.x, warp = tid >> 5, lane = tid & 31;
    const int grp = lane >> 2, qk = lane & 3;
    const int qt = blockIdx.x, bh = blockIdx.y;
    const int b = bh / H_, h = bh - b * H_;
    const int row0 = b * N_ + qt * 128;
    const int colh = h * HD_;
    const int rl0 = (warp << 4) + grp;
    const int r0 = row0 + rl0;

    // Q A-frags: raw half2 loads
    unsigned aq[4][4];
    {
        const __half* q0 = q + (size_t)r0 * D_ + colh;
        const __half* q1 = q0 + (size_t)8 * D_;
        #pragma unroll
        for (int c = 0; c < 4; c++) {
            const int d0 = 16*c + 2*qk;
            aq[c][0] = *(const unsigned*)(q0 + d0);
            aq[c][1] = *(const unsigned*)(q1 + d0);
            aq[c][2] = *(const unsigned*)(q0 + d0 + 8);
            aq[c][3] = *(const unsigned*)(q1 + d0 + 8);
        }
    }

    float o_[8][4];
    #pragma unroll
    for (int nt = 0; nt < 8; nt++) { o_[nt][0]=0.f; o_[nt][1]=0.f; o_[nt][2]=0.f; o_[nt][3]=0.f; }
    float m0 = -3.0e38f, m1 = -3.0e38f, l0 = 0.f, l1 = 0.f;

    const int lkey = tid >> 3, lq8 = tid & 7;
    const int kpar = (lkey & 1) << 2;
    const int vp = tid & 15, vdc = tid >> 4;
    const int vw = ((vp & 3) << 2) + (vp >> 2);

    for (int kt = 0; kt < N_; kt += 32) {
        __syncthreads();
        {
            // K: 4 raw half2 loads -> 4 STS.32
            const __half* krow = k + (size_t)(b * N_ + kt + lkey) * D_ + colh;
            #pragma unroll
            for (int c = 0; c < 4; c++) {
                const unsigned kw = *(const unsigned*)(krow + 2*lq8 + 16*c);
                const int m = (lq8 >> 2) + 2*c;
                Ks[(lkey << 5) + ((lq8 & 3) << 3) + (m ^ kpar)] = kw;
            }
            // V: interleave keys 2vp/2vp+1 per dim via PRMT
            {
                const __half* va = v + (size_t)(b * N_ + kt + 2*vp)     * D_ + colh + 4*vdc;
                const __half* vb = v + (size_t)(b * N_ + kt + 2*vp + 1) * D_ + colh + 4*vdc;
                const uint2 wa = *(const uint2*)va;
                const uint2 wb = *(const uint2*)vb;
                Vt[((4*vdc + 0) << 4) + vw] = __byte_perm(wa.x, wb.x, 0x5410);
                Vt[((4*vdc + 1) << 4) + vw] = __byte_perm(wa.x, wb.x, 0x7632);
                Vt[((4*vdc + 2) << 4) + vw] = __byte_perm(wa.y, wb.y, 0x5410);
                Vt[((4*vdc + 3) << 4) + vw] = __byte_perm(wa.y, wb.y, 0x7632);
            }
            if (tid < 32) Ms[tid] = pm[b * N_ + kt + tid];
        }
        __syncthreads();

        float s_[4][4];
        #pragma unroll
        for (int nt = 0; nt < 4; nt++) { s_[nt][0]=0.f; s_[nt][1]=0.f; s_[nt][2]=0.f; s_[nt][3]=0.f; }
        #pragma unroll
        for (int nt = 0; nt < 4; nt++) {
            const int rn = (nt << 3) + grp;
            const int rpar = (rn & 1) << 2;
            const uint4 B01 = *(const uint4*)(Ks + (rn << 5) + (qk << 3) + rpar);
            const uint4 B23 = *(const uint4*)(Ks + (rn << 5) + (qk << 3) + (4 ^ rpar));
            mma_f16(s_[nt][0], s_[nt][1], s_[nt][2], s_[nt][3],
                    aq[0][0], aq[0][1], aq[0][2], aq[0][3], B01.x, B01.y);
            mma_f16(s_[nt][0], s_[nt][1], s_[nt][2], s_[nt][3],
                    aq[1][0], aq[1][1], aq[1][2], aq[1][3], B01.z, B01.w);
            mma_f16(s_[nt][0], s_[nt][1], s_[nt][2], s_[nt][3],
                    aq[2][0], aq[2][1], aq[2][2], aq[2][3], B23.x, B23.y);
            mma_f16(s_[nt][0], s_[nt][1], s_[nt][2], s_[nt][3],
                    aq[3][0], aq[3][1], aq[3][2], aq[3][3], B23.z, B23.w);
        }

        float mx0 = -3.0e38f, mx1 = -3.0e38f;
        #pragma unroll
        for (int nt = 0; nt < 4; nt++) {
            const int c0 = (nt << 3) + (qk << 1);
            const bool k0m = Ms[c0] != 0, k1m = Ms[c0 + 1] != 0;
            s_[nt][0] = k0m ? -3.0e38f : s_[nt][0] * 0.125f;
            s_[nt][1] = k1m ? -3.0e38f : s_[nt][1] * 0.125f;
            s_[nt][2] = k0m ? -3.0e38f : s_[nt][2] * 0.125f;
            s_[nt][3] = k1m ? -3.0e38f : s_[nt][3] * 0.125f;
            mx0 = fmaxf(mx0, fmaxf(s_[nt][0], s_[nt][1]));
            mx1 = fmaxf(mx1, fmaxf(s_[nt][2], s_[nt][3]));
        }
        mx0 = fmaxf(mx0, __shfl_xor_sync(0xffffffffu, mx0, 1));
        mx0 = fmaxf(mx0, __shfl_xor_sync(0xffffffffu, mx0, 2));
        mx1 = fmaxf(mx1, __shfl_xor_sync(0xffffffffu, mx1, 1));
        mx1 = fmaxf(mx1, __shfl_xor_sync(0xffffffffu, mx1, 2));

        const float mn0 = fmaxf(m0, mx0), mn1 = fmaxf(m1, mx1);
        const float al0 = __expf(m0 - mn0), al1 = __expf(m1 - mn1);
        m0 = mn0; m1 = mn1;
        float rs0 = 0.f, rs1 = 0.f;
        #pragma unroll
        for (int nt = 0; nt < 4; nt++) {
            s_[nt][0] = __expf(s_[nt][0] - mn0);
            s_[nt][1] = __expf(s_[nt][1] - mn0);
            s_[nt][2] = __expf(s_[nt][2] - mn1);
            s_[nt][3] = __expf(s_[nt][3] - mn1);
            rs0 += s_[nt][0] + s_[nt][1];
            rs1 += s_[nt][2] + s_[nt][3];
        }
        #pragma unroll
        for (int nt = 0; nt < 8; nt++) {
            o_[nt][0] *= al0; o_[nt][1] *= al0;
            o_[nt][2] *= al1; o_[nt][3] *= al1;
        }
        rs0 += __shfl_xor_sync(0xffffffffu, rs0, 1);
        rs0 += __shfl_xor_sync(0xffffffffu, rs0, 2);
        rs1 += __shfl_xor_sync(0xffffffffu, rs1, 1);
        rs1 += __shfl_xor_sync(0xffffffffu, rs1, 2);
        l0 = l0 * al0 + rs0;
        l1 = l1 * al1 + rs1;

        // P A-frags: register-local pack (C-layout == fp16 A-layout)
        unsigned Af[2][4];
        #pragma unroll
        for (int c = 0; c < 2; c++) {
            Af[c][0] = h2pack(s_[2*c][0],   s_[2*c][1]);
            Af[c][1] = h2pack(s_[2*c][2],   s_[2*c][3]);
            Af[c][2] = h2pack(s_[2*c+1][0], s_[2*c+1][1]);
            Af[c][3] = h2pack(s_[2*c+1][2], s_[2*c+1][3]);
        }

        #pragma unroll
        for (int nt = 0; nt < 8; nt++) {
            const int rn = (nt << 3) + grp;
            const uint4 Bv = *(const uint4*)(Vt + (rn << 4) + (qk << 2));
            mma_f16(o_[nt][0], o_[nt][1], o_[nt][2], o_[nt][3],
                    Af[0][0], Af[0][1], Af[0][2], Af[0][3], Bv.x, Bv.y);
            mma_f16(o_[nt][0], o_[nt][1], o_[nt][2], o_[nt][3],
                    Af[1][0], Af[1][1], Af[1][2], Af[1][3], Bv.z, Bv.w);
        }
    }

    const float inv0 = 1.0f / l0, inv1 = 1.0f / l1;
    __half* out0 = out + (size_t)r0 * D_ + colh;
    __half* out1 = out0 + (size_t)8 * D_;
    #pragma unroll
    for (int nt = 0; nt < 8; nt++) {
        const int c0 = (nt << 3) + (qk << 1);
        *(unsigned*)(out0 + c0) = h2pack(o_[nt][0] * inv0, o_[nt][1] * inv0);
        *(unsigned*)(out1 + c0) = h2pack(o_[nt][2] * inv1, o_[nt][3] * inv1);
    }
}

// ---------------- launch ------------------------------------------------------
extern "C" void kernel_launch(void* const* d_in, const int* in_sizes, int n_in,
                              void* d_out, int out_size) {
    const float* x     = (const float*)d_in[0];
    const unsigned char* pmask = (const unsigned char*)d_in[1];
    const float* wq = (const float*)d_in[2];
    const float* bq = (const float*)d_in[3];
    const float* wk = (const float*)d_in[4];
    const float* bk = (const float*)d_in[5];
    const float* wv = (const float*)d_in[6];
    const float* bv = (const float*)d_in[7];
    const float* wo = (const float*)d_in[8];
    const float* bo = (const float*)d_in[9];
    const float* w1 = (const float*)d_in[10];
    const float* b1 = (const float*)d_in[11];
    const float* w2 = (const float*)d_in[12];
    const float* b2 = (const float*)d_in[13];
    const float* ln1w = (const float*)d_in[14];
    const float* ln1b = (const float*)d_in[15];
    const float* ln2w = (const float*)d_in[16];
    const float* ln2b = (const float*)d_in[17];
    const float* freqs = (const float*)d_in[18];
    float* out = (float*)d_out;

    __half *ph, *pq, *pk, *pv, *patt, *pff, *pcw;
    cudaGetSymbolAddress((void**)&ph,   g_h);
    cudaGetSymbolAddress((void**)&pq,   g_q);
    cudaGetSymbolAddress((void**)&pk,   g_k);
    cudaGetSymbolAddress((void**)&pv,   g_v);
    cudaGetSymbolAddress((void**)&patt, g_att);
    cudaGetSymbolAddress((void**)&pff,  g_ff);
    cudaGetSymbolAddress((void**)&pcw,  g_cw);

    __half* cwo = pcw + 3*CW_DD;
    __half* cw1 = pcw + 4*CW_DD;
    __half* cw2 = pcw + 4*CW_DD + CW_FD;

    cudaFuncSetAttribute(gemm_u<2,1>, cudaFuncAttributeMaxDynamicSharedMemorySize, GEMM_DYN_SMEM);
    cudaFuncSetAttribute(gemm_u<3,0>, cudaFuncAttributeMaxDynamicSharedMemorySize, GEMM_DYN_SMEM);
    cudaFuncSetAttribute(gemm_qkv,    cudaFuncAttributeMaxDynamicSharedMemorySize, GEMM_DYN_SMEM);
    cudaFuncSetAttribute(attn_tc,     cudaFuncAttributeMaxDynamicSharedMemorySize, ATTN_SMEM);

    const dim3 gD(D_ / 128, M_ / 128);        // (6, 64)
    const dim3 gQKV(D_ / 128, M_ / 128, 3);   // (6, 64, 3)
    const dim3 gF(FF_ / 128, M_ / 128);       // (24, 64)
    const int ntotal4 = (4*CW_DD + 2*CW_FD) / 4;

    // fp16-convert all six weight matrices in ONE launch
    cvt_all_kernel<<<(ntotal4 + 255)/256, 256>>>(
        (const float4*)wq, (const float4*)wk, (const float4*)wv,
        (const float4*)wo, (const float4*)w1, (const float4*)w2, (uint2*)pcw);

    // LN1 (fp16 output)
    ln_kernel<<<M_, 256>>>(x, ln1w, ln1b, ph);
    // fused QKV projections + RoPE
    gemm_qkv<<<gQKV, 256, GEMM_DYN_SMEM>>>(ph, pcw, bq, bk, bv, freqs, pq, pk, pv);
    // attention (fp16 end-to-end)
    attn_tc<<<dim3(N_ / 128, B_ * H_), 256, ATTN_SMEM>>>(pq, pk, pv, pmask, patt);
    // O projection + residual (x) -> d_out (fp32)
    gemm_u<3,0><<<gD, 256, GEMM_DYN_SMEM>>>(patt, cwo, bo, x, out, M_, D_, D_);
    // LN2 (fp16 output)
    ln_kernel<<<M_, 256>>>(out, ln2w, ln2b, ph);
    // FFN1 with exact GELU (fp16 output)
    gemm_u<2,1><<<gF, 256, GEMM_DYN_SMEM>>>(ph, cw1, b1, nullptr, pff, M_, FF_, D_);
    // FFN2 + residual (d_out) -> d_out (fp32)
    gemm_u<3,0><<<gD, 256, GEMM_DYN_SMEM>>>(pff, cw2, b2, out, out, M_, D_, FF_);
}